// round 5
// baseline (speedup 1.0000x reference)
#include <cuda_runtime.h>
#include <math.h>

#define Bn 4096
#define Tn 64
#define Hn 64

#define STR 68   // padded stride for transposed smem tiles (multiple of 4)
#define XS  68

typedef unsigned long long ull;

// ---------------- device scratch (allocation-free rule: __device__ globals) ----
__device__ float g_x2[(size_t)Tn * Bn * 64];   // trunk output, [T][B][64]
__device__ float g_xs[(size_t)2 * Bn * Tn];    // [2B][T]
__device__ float g_ps[(size_t)2 * Bn * Tn];    // [2B][T]

__device__ __forceinline__ float sigf(float x) {
    return __fdividef(1.f, 1.f + __expf(-x));
}
__device__ __forceinline__ float tanh_fast(float x) {
    float e = __expf(-2.f * fabsf(x));
    float t = __fdividef(1.f - e, 1.f + e);
    return copysignf(t, x);
}

// ---- packed fp32x2 helpers (Blackwell FFMA2 path, PTX-only) ----
__device__ __forceinline__ void ffma2(ull& d, ull a, ull b) {
    asm("fma.rn.f32x2 %0, %1, %2, %0;" : "+l"(d) : "l"(a), "l"(b));
}
__device__ __forceinline__ ull pack2(float x, float y) {
    ull r; asm("mov.b64 %0, {%1, %2};" : "=l"(r) : "f"(x), "f"(y)); return r;
}
__device__ __forceinline__ ull bcast2(float x) { return pack2(x, x); }
__device__ __forceinline__ float2 unpack2(ull v) {
    float2 f; asm("mov.b64 {%0, %1}, %2;" : "=f"(f.x), "=f"(f.y) : "l"(v)); return f;
}

// =====================================================================
// Kernel 1: MLP trunk.  x1 = relu(LN(obs@W1+b1)); x2 = relu(LN([x1,act]@W2+b2))
// Writes x2 to g_x2 in [T][B][64] layout (row i of obs: b = i/T, t = i%T).
// 256 threads, 64 rows/block. Accumulators packed f32x2 over row-pairs.
// =====================================================================
__global__ void __launch_bounds__(256, 2) trunk_kernel(
    const float* __restrict__ obs, const float* __restrict__ act,
    const float* __restrict__ W1, const float* __restrict__ b1,
    const float* __restrict__ g1, const float* __restrict__ be1,
    const float* __restrict__ W2, const float* __restrict__ b2,
    const float* __restrict__ g2, const float* __restrict__ be2)
{
    extern __shared__ float sm[];
    float* sW1 = sm;                 // 128*64
    float* sW2 = sW1 + 128 * 64;     // 96*64
    float* sX  = sW2 + 96 * 64;      // 64 x STR (k-chunk of obs, transposed)
    float* sA  = sX + 64 * STR;      // 96 x STR (x1 | action, transposed)
    float* sP  = sA + 96 * STR;      // 6*64 params

    const int tid  = threadIdx.x;
    const int row0 = blockIdx.x * 64;

    for (int i = tid; i < 2048; i += 256) ((float4*)sW1)[i] = ((const float4*)W1)[i];
    for (int i = tid; i < 1536; i += 256) ((float4*)sW2)[i] = ((const float4*)W2)[i];
    if (tid < 64) {
        sP[tid]       = b1[tid];  sP[64 + tid]  = g1[tid];  sP[128 + tid] = be1[tid];
        sP[192 + tid] = b2[tid];  sP[256 + tid] = g2[tid];  sP[320 + tid] = be2[tid];
    }

    const int cg = tid & 15, rg = tid >> 4;
    const int c0 = cg * 4, r0 = rg * 4;
    const int lr = tid >> 2, kq = tid & 3;   // cooperative loader mapping

    // packed accumulators: acc2[rp][c] holds rows (r0+2rp, r0+2rp+1), col c0+c
    ull acc2[2][4];
#pragma unroll
    for (int rp = 0; rp < 2; ++rp)
#pragma unroll
        for (int c = 0; c < 4; ++c) acc2[rp][c] = 0ull;

    // GEMM1: K=128 in two chunks of 64
    for (int kc = 0; kc < 2; ++kc) {
        __syncthreads();
        {
            const float* src = obs + (size_t)(row0 + lr) * 128 + kc * 64 + kq * 16;
#pragma unroll
            for (int j = 0; j < 4; ++j) {
                float4 v = *(const float4*)(src + j * 4);
                int k = kq * 16 + j * 4;
                sX[(k + 0) * STR + lr] = v.x;
                sX[(k + 1) * STR + lr] = v.y;
                sX[(k + 2) * STR + lr] = v.z;
                sX[(k + 3) * STR + lr] = v.w;
            }
        }
        __syncthreads();
#pragma unroll 4
        for (int k = 0; k < 64; ++k) {
            ulonglong2 xp = *(const ulonglong2*)(sX + k * STR + r0);   // rows r0..r0+3 packed
            float4 wv = *(const float4*)(sW1 + (kc * 64 + k) * 64 + c0);
            ull wb0 = bcast2(wv.x), wb1 = bcast2(wv.y), wb2 = bcast2(wv.z), wb3 = bcast2(wv.w);
            ffma2(acc2[0][0], xp.x, wb0); ffma2(acc2[0][1], xp.x, wb1);
            ffma2(acc2[0][2], xp.x, wb2); ffma2(acc2[0][3], xp.x, wb3);
            ffma2(acc2[1][0], xp.y, wb0); ffma2(acc2[1][1], xp.y, wb1);
            ffma2(acc2[1][2], xp.y, wb2); ffma2(acc2[1][3], xp.y, wb3);
        }
    }

    // LN1 + relu -> sA (transposed), cols 0..63
#pragma unroll
    for (int r = 0; r < 4; ++r) {
        float y[4]; float s = 0.f, q = 0.f;
#pragma unroll
        for (int c = 0; c < 4; ++c) {
            float2 v = unpack2(acc2[r >> 1][c]);
            y[c] = ((r & 1) ? v.y : v.x) + sP[c0 + c];
            s += y[c]; q += y[c] * y[c];
        }
#pragma unroll
        for (int o = 8; o; o >>= 1) {
            s += __shfl_xor_sync(0xffffffffu, s, o);
            q += __shfl_xor_sync(0xffffffffu, q, o);
        }
        float m = s * 0.015625f;
        float var = q * 0.015625f - m * m;
        float rs = rsqrtf(var + 1e-12f);
#pragma unroll
        for (int c = 0; c < 4; ++c) {
            float z = (y[c] - m) * rs * sP[64 + c0 + c] + sP[128 + c0 + c];
            sA[(c0 + c) * STR + r0 + r] = fmaxf(z, 0.f);
        }
    }

    // append action -> sA cols 64..95 (transposed)
    {
        const float* asrc = act + (size_t)(row0 + lr) * 32 + kq * 8;
        float4 a0 = *(const float4*)asrc;
        float4 a1 = *(const float4*)(asrc + 4);
        int cb = 64 + kq * 8;
        sA[(cb + 0) * STR + lr] = a0.x; sA[(cb + 1) * STR + lr] = a0.y;
        sA[(cb + 2) * STR + lr] = a0.z; sA[(cb + 3) * STR + lr] = a0.w;
        sA[(cb + 4) * STR + lr] = a1.x; sA[(cb + 5) * STR + lr] = a1.y;
        sA[(cb + 6) * STR + lr] = a1.z; sA[(cb + 7) * STR + lr] = a1.w;
    }
    __syncthreads();

    // GEMM2: K=96, packed accumulators, init with bias (same for both rows)
    ull a22[2][4];
#pragma unroll
    for (int rp = 0; rp < 2; ++rp)
#pragma unroll
        for (int c = 0; c < 4; ++c) a22[rp][c] = bcast2(sP[192 + c0 + c]);
#pragma unroll 4
    for (int k = 0; k < 96; ++k) {
        ulonglong2 xp = *(const ulonglong2*)(sA + k * STR + r0);
        float4 wv = *(const float4*)(sW2 + k * 64 + c0);
        ull wb0 = bcast2(wv.x), wb1 = bcast2(wv.y), wb2 = bcast2(wv.z), wb3 = bcast2(wv.w);
        ffma2(a22[0][0], xp.x, wb0); ffma2(a22[0][1], xp.x, wb1);
        ffma2(a22[0][2], xp.x, wb2); ffma2(a22[0][3], xp.x, wb3);
        ffma2(a22[1][0], xp.y, wb0); ffma2(a22[1][1], xp.y, wb1);
        ffma2(a22[1][2], xp.y, wb2); ffma2(a22[1][3], xp.y, wb3);
    }

    // LN2 + relu -> global, layout [t][b][64]
#pragma unroll
    for (int r = 0; r < 4; ++r) {
        float y[4]; float s = 0.f, q = 0.f;
#pragma unroll
        for (int c = 0; c < 4; ++c) {
            float2 v = unpack2(a22[r >> 1][c]);
            y[c] = (r & 1) ? v.y : v.x;
            s += y[c]; q += y[c] * y[c];
        }
#pragma unroll
        for (int o = 8; o; o >>= 1) {
            s += __shfl_xor_sync(0xffffffffu, s, o);
            q += __shfl_xor_sync(0xffffffffu, q, o);
        }
        float m = s * 0.015625f;
        float var = q * 0.015625f - m * m;
        float rs = rsqrtf(var + 1e-12f);
        int grow = row0 + r0 + r;
        int bb = grow >> 6, tt = grow & 63;   // T == 64
        float4 o4;
        o4.x = fmaxf((y[0] - m) * rs * sP[256 + c0 + 0] + sP[320 + c0 + 0], 0.f);
        o4.y = fmaxf((y[1] - m) * rs * sP[256 + c0 + 1] + sP[320 + c0 + 1], 0.f);
        o4.z = fmaxf((y[2] - m) * rs * sP[256 + c0 + 2] + sP[320 + c0 + 2], 0.f);
        o4.w = fmaxf((y[3] - m) * rs * sP[256 + c0 + 3] + sP[320 + c0 + 3], 0.f);
        *(float4*)(g_x2 + ((size_t)tt * Bn + bb) * 64 + c0) = o4;
    }
}

// =====================================================================
// Kernel 2: bidirectional LSTM scan. grid = (64, 2): 64 seq-chunks x dir.
// 256 threads. Thread = (seq-group sg = tid>>5) x (unit-pair up = tid&31).
// Gate accumulators packed f32x2 over the unit pair (u, u+1): the scalar
// x[k][s] multiplies the contiguous weight pair -> one FFMA2 per 2 FMAs.
// =====================================================================
__global__ void __launch_bounds__(256, 1) lstm_kernel(
    const float* __restrict__ Wf, const float* __restrict__ bfv,
    const float* __restrict__ Wb, const float* __restrict__ bbv,
    const float* __restrict__ wx, const float* __restrict__ bx,
    const float* __restrict__ wp, const float* __restrict__ bp)
{
    extern __shared__ float sm[];
    float* Ws = sm;                 // 128*256
    float* xT = Ws + 128 * 256;     // 64 x XS
    float* hT = xT + 64 * XS;       // 64 x XS

    const int dir = blockIdx.y;
    const int b0  = blockIdx.x * 64;
    const float* W    = dir ? Wb  : Wf;
    const float* bias = dir ? bbv : bfv;
    const int tid = threadIdx.x;

    for (int i = tid; i < 8192; i += 256) ((float4*)Ws)[i] = ((const float4*)W)[i];
    for (int i = tid; i < 64 * XS; i += 256) hT[i] = 0.f;

    const int up = tid & 31, sg = tid >> 5;
    const int u = up * 2, s0 = sg * 8;

    const ull bi2 = pack2(bias[u],       bias[u + 1]);
    const ull bj2 = pack2(bias[64 + u],  bias[65 + u]);
    const ull bF2 = pack2(bias[128 + u], bias[129 + u]);
    const ull bo2 = pack2(bias[192 + u], bias[193 + u]);
    const float wx0 = wx[u], wx1 = wx[u + 1];
    const float wp0 = wp[u], wp1 = wp[u + 1];
    const float bxs = bx[0], bps = bp[0];

    float c0r[8], c1r[8];
#pragma unroll
    for (int s = 0; s < 8; ++s) { c0r[s] = 0.f; c1r[s] = 0.f; }

    const int lr = tid >> 2, kq = tid & 3;

    for (int st = 0; st < Tn; ++st) {
        const int t = dir ? (Tn - 1 - st) : st;
        __syncthreads();   // prev hT writes visible; xT free
        {
            const float* src = g_x2 + ((size_t)t * Bn + b0 + lr) * 64 + kq * 16;
#pragma unroll
            for (int j = 0; j < 4; ++j) {
                float4 v = *(const float4*)(src + j * 4);
                int k = kq * 16 + j * 4;
                xT[(k + 0) * XS + lr] = v.x;
                xT[(k + 1) * XS + lr] = v.y;
                xT[(k + 2) * XS + lr] = v.z;
                xT[(k + 3) * XS + lr] = v.w;
            }
        }
        __syncthreads();

        // packed gate accumulators: [s] -> (unit u, unit u+1)
        ull ai[8], aj[8], aF[8], ao[8];
#pragma unroll
        for (int s = 0; s < 8; ++s) { ai[s] = bi2; aj[s] = bj2; aF[s] = bF2; ao[s] = bo2; }

        const float* xb = xT + s0;
        const float* hb = hT + s0;

#pragma unroll 2
        for (int k = 0; k < 64; ++k) {
            float xv[8];
            *(float4*)(xv)     = *(const float4*)(xb + k * XS);
            *(float4*)(xv + 4) = *(const float4*)(xb + k * XS + 4);
            const float* wr = Ws + k * 256 + u;
            ull wi = *(const ull*)(wr);
            ull wj = *(const ull*)(wr + 64);
            ull wf2 = *(const ull*)(wr + 128);
            ull wo = *(const ull*)(wr + 192);
#pragma unroll
            for (int s = 0; s < 8; ++s) {
                ull xp = bcast2(xv[s]);
                ffma2(ai[s], xp, wi);
                ffma2(aj[s], xp, wj);
                ffma2(aF[s], xp, wf2);
                ffma2(ao[s], xp, wo);
            }
        }
#pragma unroll 2
        for (int k = 0; k < 64; ++k) {
            float hv[8];
            *(float4*)(hv)     = *(const float4*)(hb + k * XS);
            *(float4*)(hv + 4) = *(const float4*)(hb + k * XS + 4);
            const float* wr = Ws + (64 + k) * 256 + u;
            ull wi = *(const ull*)(wr);
            ull wj = *(const ull*)(wr + 64);
            ull wf2 = *(const ull*)(wr + 128);
            ull wo = *(const ull*)(wr + 192);
#pragma unroll
            for (int s = 0; s < 8; ++s) {
                ull xp = bcast2(hv[s]);
                ffma2(ai[s], xp, wi);
                ffma2(aj[s], xp, wj);
                ffma2(aF[s], xp, wf2);
                ffma2(ao[s], xp, wo);
            }
        }
        __syncthreads();   // all hT/xT reads done before hT overwrite

        float px[8], pq[8];
#pragma unroll
        for (int s = 0; s < 8; ++s) {
            float2 vi = unpack2(ai[s]);
            float2 vj = unpack2(aj[s]);
            float2 vf = unpack2(aF[s]);
            float2 vo = unpack2(ao[s]);

            float ig = sigf(vi.x);
            float jg = tanh_fast(vj.x);
            float fg = sigf(vf.x + 1.f);
            float og = sigf(vo.x);
            float cn = c0r[s] * fg + ig * jg;
            c0r[s] = cn;
            float h0 = tanh_fast(cn) * og;

            ig = sigf(vi.y);
            jg = tanh_fast(vj.y);
            fg = sigf(vf.y + 1.f);
            og = sigf(vo.y);
            cn = c1r[s] * fg + ig * jg;
            c1r[s] = cn;
            float h1 = tanh_fast(cn) * og;

            hT[u * XS + s0 + s]       = h0;
            hT[(u + 1) * XS + s0 + s] = h1;
            px[s] = h0 * wx0 + h1 * wx1;
            pq[s] = h0 * wp0 + h1 * wp1;
        }
#pragma unroll
        for (int o = 16; o; o >>= 1) {
#pragma unroll
            for (int s = 0; s < 8; ++s) {
                px[s] += __shfl_xor_sync(0xffffffffu, px[s], o);
                pq[s] += __shfl_xor_sync(0xffffffffu, pq[s], o);
            }
        }
        if (up < 8) {
            size_t row = (size_t)dir * Bn + b0 + s0 + up;
            g_xs[row * Tn + t] = px[up] + bxs;
            g_ps[row * Tn + t] = pq[up] + bps;
        }
    }
}

// =====================================================================
// Kernel 3: attention head. warp per sequence; 8 seqs / block.
// p = softmax(relu(LN(ps)) @ W3 + b3); out = sum(p * xs)
// =====================================================================
__global__ void __launch_bounds__(256) attn_kernel(
    const float* __restrict__ gp, const float* __restrict__ bep,
    const float* __restrict__ W3, const float* __restrict__ b3,
    float* __restrict__ out)
{
    __shared__ float sW3[4096];
    __shared__ float sb3[64];
    const int tid = threadIdx.x;
    for (int i = tid; i < 1024; i += 256) ((float4*)sW3)[i] = ((const float4*)W3)[i];
    if (tid < 64) sb3[tid] = b3[tid];
    __syncthreads();

    const int lane = tid & 31, w = tid >> 5;
    const int seq = blockIdx.x * 8 + w;

    const float* psr = g_ps + (size_t)seq * Tn;
    float v0 = psr[lane], v1 = psr[lane + 32];
    float s = v0 + v1, q = v0 * v0 + v1 * v1;
#pragma unroll
    for (int o = 16; o; o >>= 1) {
        s += __shfl_xor_sync(0xffffffffu, s, o);
        q += __shfl_xor_sync(0xffffffffu, q, o);
    }
    float m = s * 0.015625f;
    float var = q * 0.015625f - m * m;
    float rs = rsqrtf(var + 1e-12f);
    float p0 = fmaxf((v0 - m) * rs * gp[lane]      + bep[lane],      0.f);
    float p1 = fmaxf((v1 - m) * rs * gp[lane + 32] + bep[lane + 32], 0.f);

    float l0 = sb3[lane], l1 = sb3[lane + 32];
#pragma unroll 8
    for (int tt = 0; tt < 32; ++tt) {
        float pv = __shfl_sync(0xffffffffu, p0, tt);
        l0 += pv * sW3[tt * 64 + lane];
        l1 += pv * sW3[tt * 64 + lane + 32];
    }
#pragma unroll 8
    for (int tt = 0; tt < 32; ++tt) {
        float pv = __shfl_sync(0xffffffffu, p1, tt);
        l0 += pv * sW3[(32 + tt) * 64 + lane];
        l1 += pv * sW3[(32 + tt) * 64 + lane + 32];
    }

    float mx = fmaxf(l0, l1);
#pragma unroll
    for (int o = 16; o; o >>= 1) mx = fmaxf(mx, __shfl_xor_sync(0xffffffffu, mx, o));
    float e0 = __expf(l0 - mx), e1 = __expf(l1 - mx);
    float se = e0 + e1;
    const float* xsr = g_xs + (size_t)seq * Tn;
    float rsum = e0 * xsr[lane] + e1 * xsr[lane + 32];
#pragma unroll
    for (int o = 16; o; o >>= 1) {
        se   += __shfl_xor_sync(0xffffffffu, se, o);
        rsum += __shfl_xor_sync(0xffffffffu, rsum, o);
    }
    if (lane == 0) out[seq] = rsum / se;
}

// =====================================================================
extern "C" void kernel_launch(void* const* d_in, const int* in_sizes, int n_in,
                              void* d_out, int out_size)
{
    const float* obs = (const float*)d_in[0];
    const float* act = (const float*)d_in[1];
    const float* W1  = (const float*)d_in[2];
    const float* b1  = (const float*)d_in[3];
    const float* g1  = (const float*)d_in[4];
    const float* be1 = (const float*)d_in[5];
    const float* W2  = (const float*)d_in[6];
    const float* b2  = (const float*)d_in[7];
    const float* g2  = (const float*)d_in[8];
    const float* be2 = (const float*)d_in[9];
    const float* Wf  = (const float*)d_in[10];
    const float* bf  = (const float*)d_in[11];
    const float* Wb  = (const float*)d_in[12];
    const float* bb  = (const float*)d_in[13];
    const float* wx  = (const float*)d_in[14];
    const float* bx  = (const float*)d_in[15];
    const float* wp  = (const float*)d_in[16];
    const float* bp  = (const float*)d_in[17];
    const float* gp  = (const float*)d_in[18];
    const float* bep = (const float*)d_in[19];
    const float* W3  = (const float*)d_in[20];
    const float* b3  = (const float*)d_in[21];
    float* out = (float*)d_out;

    const int trunk_smem = (128 * 64 + 96 * 64 + 64 * STR + 96 * STR + 6 * 64) * 4;
    const int lstm_smem  = (128 * 256 + 2 * 64 * XS) * 4;
    cudaFuncSetAttribute(trunk_kernel, cudaFuncAttributeMaxDynamicSharedMemorySize, trunk_smem);
    cudaFuncSetAttribute(lstm_kernel,  cudaFuncAttributeMaxDynamicSharedMemorySize, lstm_smem);

    trunk_kernel<<<4096, 256, trunk_smem>>>(obs, act, W1, b1, g1, be1, W2, b2, g2, be2);

    dim3 lg(64, 2);
    lstm_kernel<<<lg, 256, lstm_smem>>>(Wf, bf, Wb, bb, wx, bx, wp, bp);

    attn_kernel<<<1024, 256>>>(gp, bep, W3, b3, out);
}

// round 6
// speedup vs baseline: 2.1649x; 2.1649x over previous
#include <cuda_runtime.h>
#include <math.h>

#define Bn 4096
#define Tn 64
#define Hn 64

#define STR 68   // padded stride for transposed smem tiles

typedef unsigned long long ull;

// ---------------- device scratch (allocation-free rule: __device__ globals) ----
// g_x2 layout: per (t, blk) a 4096-float block in mma A-fragment layout:
//   idx = ((mt*8 + ktx)*32 + lane)*4 + reg, mt=seq/16, ktx=col/8,
//   lane=(seq%8)*4 + col%4... (values pre-rounded to tf32)
__device__ float g_x2[(size_t)Tn * Bn * 64];
__device__ float g_xs[(size_t)2 * Bn * Tn];    // [2B][T]
__device__ float g_ps[(size_t)2 * Bn * Tn];    // [2B][T]

__device__ __forceinline__ float sigf(float x) {
    return __fdividef(1.f, 1.f + __expf(-x));
}
__device__ __forceinline__ float tanh_fast(float x) {
    float e = __expf(-2.f * fabsf(x));
    float t = __fdividef(1.f - e, 1.f + e);
    return copysignf(t, x);
}
__device__ __forceinline__ unsigned cvt_tf32(float x) {
    unsigned r; asm("cvt.rna.tf32.f32 %0, %1;" : "=r"(r) : "f"(x)); return r;
}
__device__ __forceinline__ void mma_tf32(float* c, uint4 a, uint2 b) {
    asm volatile(
        "mma.sync.aligned.m16n8k8.row.col.f32.tf32.tf32.f32 "
        "{%0,%1,%2,%3}, {%4,%5,%6,%7}, {%8,%9}, {%0,%1,%2,%3};"
        : "+f"(c[0]), "+f"(c[1]), "+f"(c[2]), "+f"(c[3])
        : "r"(a.x), "r"(a.y), "r"(a.z), "r"(a.w), "r"(b.x), "r"(b.y));
}

// =====================================================================
// Kernel 1: MLP trunk (scalar FFMA — known L1-bound, round-1 version).
// Output: x2 tf32-rounded, written directly in mma A-fragment layout.
// =====================================================================
__global__ void __launch_bounds__(256, 2) trunk_kernel(
    const float* __restrict__ obs, const float* __restrict__ act,
    const float* __restrict__ W1, const float* __restrict__ b1,
    const float* __restrict__ g1, const float* __restrict__ be1,
    const float* __restrict__ W2, const float* __restrict__ b2,
    const float* __restrict__ g2, const float* __restrict__ be2)
{
    extern __shared__ float sm[];
    float* sW1 = sm;                 // 128*64
    float* sW2 = sW1 + 128 * 64;     // 96*64
    float* sX  = sW2 + 96 * 64;      // 64 x STR
    float* sA  = sX + 64 * STR;      // 96 x STR
    float* sP  = sA + 96 * STR;      // 6*64 params

    const int tid  = threadIdx.x;
    const int row0 = blockIdx.x * 64;

    for (int i = tid; i < 2048; i += 256) ((float4*)sW1)[i] = ((const float4*)W1)[i];
    for (int i = tid; i < 1536; i += 256) ((float4*)sW2)[i] = ((const float4*)W2)[i];
    if (tid < 64) {
        sP[tid]       = b1[tid];  sP[64 + tid]  = g1[tid];  sP[128 + tid] = be1[tid];
        sP[192 + tid] = b2[tid];  sP[256 + tid] = g2[tid];  sP[320 + tid] = be2[tid];
    }

    const int cg = tid & 15, rg = tid >> 4;
    const int c0 = cg * 4, r0 = rg * 4;
    const int lr = tid >> 2, kq = tid & 3;

    float acc[4][4];
#pragma unroll
    for (int r = 0; r < 4; ++r) { acc[r][0]=0.f; acc[r][1]=0.f; acc[r][2]=0.f; acc[r][3]=0.f; }

    for (int kc = 0; kc < 2; ++kc) {
        __syncthreads();
        {
            const float* src = obs + (size_t)(row0 + lr) * 128 + kc * 64 + kq * 16;
#pragma unroll
            for (int j = 0; j < 4; ++j) {
                float4 v = *(const float4*)(src + j * 4);
                int k = kq * 16 + j * 4;
                sX[(k + 0) * STR + lr] = v.x;
                sX[(k + 1) * STR + lr] = v.y;
                sX[(k + 2) * STR + lr] = v.z;
                sX[(k + 3) * STR + lr] = v.w;
            }
        }
        __syncthreads();
#pragma unroll 4
        for (int k = 0; k < 64; ++k) {
            float4 xv = *(const float4*)(sX + k * STR + r0);
            float4 wv = *(const float4*)(sW1 + (kc * 64 + k) * 64 + c0);
            acc[0][0] += xv.x * wv.x; acc[0][1] += xv.x * wv.y; acc[0][2] += xv.x * wv.z; acc[0][3] += xv.x * wv.w;
            acc[1][0] += xv.y * wv.x; acc[1][1] += xv.y * wv.y; acc[1][2] += xv.y * wv.z; acc[1][3] += xv.y * wv.w;
            acc[2][0] += xv.z * wv.x; acc[2][1] += xv.z * wv.y; acc[2][2] += xv.z * wv.z; acc[2][3] += xv.z * wv.w;
            acc[3][0] += xv.w * wv.x; acc[3][1] += xv.w * wv.y; acc[3][2] += xv.w * wv.z; acc[3][3] += xv.w * wv.w;
        }
    }

    // LN1 + relu -> sA
#pragma unroll
    for (int r = 0; r < 4; ++r) {
        float y[4]; float s = 0.f, q = 0.f;
#pragma unroll
        for (int c = 0; c < 4; ++c) { y[c] = acc[r][c] + sP[c0 + c]; s += y[c]; q += y[c]*y[c]; }
#pragma unroll
        for (int o = 8; o; o >>= 1) {
            s += __shfl_xor_sync(0xffffffffu, s, o);
            q += __shfl_xor_sync(0xffffffffu, q, o);
        }
        float m = s * 0.015625f;
        float var = q * 0.015625f - m * m;
        float rs = rsqrtf(var + 1e-12f);
#pragma unroll
        for (int c = 0; c < 4; ++c) {
            float z = (y[c] - m) * rs * sP[64 + c0 + c] + sP[128 + c0 + c];
            sA[(c0 + c) * STR + r0 + r] = fmaxf(z, 0.f);
        }
    }

    {
        const float* asrc = act + (size_t)(row0 + lr) * 32 + kq * 8;
        float4 a0 = *(const float4*)asrc;
        float4 a1 = *(const float4*)(asrc + 4);
        int cb = 64 + kq * 8;
        sA[(cb + 0) * STR + lr] = a0.x; sA[(cb + 1) * STR + lr] = a0.y;
        sA[(cb + 2) * STR + lr] = a0.z; sA[(cb + 3) * STR + lr] = a0.w;
        sA[(cb + 4) * STR + lr] = a1.x; sA[(cb + 5) * STR + lr] = a1.y;
        sA[(cb + 6) * STR + lr] = a1.z; sA[(cb + 7) * STR + lr] = a1.w;
    }
    __syncthreads();

    float a2[4][4];
#pragma unroll
    for (int r = 0; r < 4; ++r) {
        a2[r][0] = sP[192 + c0 + 0]; a2[r][1] = sP[192 + c0 + 1];
        a2[r][2] = sP[192 + c0 + 2]; a2[r][3] = sP[192 + c0 + 3];
    }
#pragma unroll 4
    for (int k = 0; k < 96; ++k) {
        float4 xv = *(const float4*)(sA + k * STR + r0);
        float4 wv = *(const float4*)(sW2 + k * 64 + c0);
        a2[0][0] += xv.x * wv.x; a2[0][1] += xv.x * wv.y; a2[0][2] += xv.x * wv.z; a2[0][3] += xv.x * wv.w;
        a2[1][0] += xv.y * wv.x; a2[1][1] += xv.y * wv.y; a2[1][2] += xv.y * wv.z; a2[1][3] += xv.y * wv.w;
        a2[2][0] += xv.z * wv.x; a2[2][1] += xv.z * wv.y; a2[2][2] += xv.z * wv.z; a2[2][3] += xv.z * wv.w;
        a2[3][0] += xv.w * wv.x; a2[3][1] += xv.w * wv.y; a2[3][2] += xv.w * wv.z; a2[3][3] += xv.w * wv.w;
    }

    // LN2 + relu -> global in A-fragment layout (tf32-rounded)
    const int ktx = c0 >> 3;
    const int c4  = (c0 & 7) >> 2;
#pragma unroll
    for (int r = 0; r < 4; ++r) {
        float y[4]; float s = 0.f, q = 0.f;
#pragma unroll
        for (int c = 0; c < 4; ++c) { y[c] = a2[r][c]; s += y[c]; q += y[c]*y[c]; }
#pragma unroll
        for (int o = 8; o; o >>= 1) {
            s += __shfl_xor_sync(0xffffffffu, s, o);
            q += __shfl_xor_sync(0xffffffffu, q, o);
        }
        float m = s * 0.015625f;
        float var = q * 0.015625f - m * m;
        float rs = rsqrtf(var + 1e-12f);

        int grow = row0 + r0 + r;
        int b = grow >> 6, t = grow & 63;
        int blkx = b >> 6, sq = b & 63;
        int mt = sq >> 4, rr = sq & 15;
        int rhi = rr >> 3, rlo = rr & 7;
        size_t base = ((size_t)t * 64 + blkx) * 4096;
        int reg = rhi + 2 * c4;
#pragma unroll
        for (int c = 0; c < 4; ++c) {
            float z = fmaxf((y[c] - m) * rs * sP[256 + c0 + c] + sP[320 + c0 + c], 0.f);
            int lane = rlo * 4 + c;
            g_x2[base + (size_t)(((mt * 8 + ktx) * 32 + lane) * 4 + reg)] =
                __uint_as_float(cvt_tf32(z));
        }
    }
}

// =====================================================================
// Kernel 2: bidirectional LSTM via tf32 mma.sync. grid (64, 2).
// Per CTA: 64 seqs. Per step: Z[64][256] = [x_t | h] @ W via m16n8k8.
// W pre-staged in B-fragment layout with gate-unit permutation so warp w
// owns units 8w..8w+7 x all 4 gates; h written back into A-frag kt=8+w.
// =====================================================================
__global__ void __launch_bounds__(256, 1) lstm_kernel(
    const float* __restrict__ Wf, const float* __restrict__ bfv,
    const float* __restrict__ Wb, const float* __restrict__ bbv,
    const float* __restrict__ wx, const float* __restrict__ bx,
    const float* __restrict__ wp, const float* __restrict__ bp)
{
    extern __shared__ float sm[];
    float* wFrag = sm;              // 32768 floats (128KB): [w][g][kt][lane][2]
    float* aFrag = wFrag + 32768;   // 8192 floats (32KB):   [mt][kt][lane][4]
    float* red   = aFrag + 8192;    // 1024 floats: [2][8 warps][64 seqs]

    const int dir  = blockIdx.y;
    const int blkx = blockIdx.x;
    const int b0   = blkx * 64;
    const float* W    = dir ? Wb  : Wf;
    const float* bias = dir ? bbv : bfv;
    const int tid = threadIdx.x;
    const int l = tid & 31, w = tid >> 5;

    // ---- stage W into B-fragment layout (once) ----
    for (int q = 0; q < 64; ++q) {
        int s = tid + q * 256;
        int lane = s & 31, kt = (s >> 5) & 15, g = (s >> 9) & 3, ww = s >> 11;
        int k0 = kt * 8 + (lane & 3);
        int n  = g * 64 + 8 * ww + (lane >> 2);
        wFrag[s * 2]     = __uint_as_float(cvt_tf32(W[k0 * 256 + n]));
        wFrag[s * 2 + 1] = __uint_as_float(cvt_tf32(W[(k0 + 4) * 256 + n]));
    }
    // ---- zero h-frags, load x(t0) (already fragment layout + tf32) ----
    {
        int t0 = dir ? 63 : 0;
        const float4* src = (const float4*)(g_x2 + ((size_t)t0 * 64 + blkx) * 4096);
        float4* dstA = (float4*)aFrag;
#pragma unroll
        for (int q = 0; q < 4; ++q) {
            int f = tid + q * 256;
            int d = f + (f >> 8) * 256;
            dstA[d] = src[f];
            dstA[d + 256] = make_float4(0.f, 0.f, 0.f, 0.f);
        }
    }

    // ---- per-thread constants ----
    const int u0 = 8 * w + 2 * (l & 3);
    float bia[4][2];
#pragma unroll
    for (int g = 0; g < 4; ++g) {
        bia[g][0] = bias[g * 64 + u0];
        bia[g][1] = bias[g * 64 + u0 + 1];
    }
    const float wxu0 = wx[u0], wxu1 = wx[u0 + 1];
    const float wpu0 = wp[u0], wpu1 = wp[u0 + 1];
    const float bxs = bx[0], bps = bp[0];

    float cst[4][4];
#pragma unroll
    for (int mt = 0; mt < 4; ++mt)
#pragma unroll
        for (int s = 0; s < 4; ++s) cst[mt][s] = 0.f;

    const int kth   = 8 + w;
    const int c0v   = 2 * (l & 3);
    const int laneh = (l >> 2) * 4 + (c0v & 3);
    const int regLo = 2 * (c0v >> 2);
    const ull* wB = (const ull*)wFrag;

    for (int st = 0; st < 64; ++st) {
        const int t = dir ? (63 - st) : st;
        __syncthreads();   // aFrag (x_t + h_{t-1}) ready

        float acc[4][4][4];
#pragma unroll
        for (int mt = 0; mt < 4; ++mt)
#pragma unroll
            for (int g = 0; g < 4; ++g) {
                acc[mt][g][0] = bia[g][0]; acc[mt][g][1] = bia[g][1];
                acc[mt][g][2] = bia[g][0]; acc[mt][g][3] = bia[g][1];
            }

#pragma unroll
        for (int kt = 0; kt < 16; ++kt) {
            uint2 b[4];
#pragma unroll
            for (int g = 0; g < 4; ++g) {
                ull v = wB[(size_t)(((w * 4 + g) * 16 + kt) * 32 + l)];
                b[g].x = (unsigned)(v & 0xffffffffu);
                b[g].y = (unsigned)(v >> 32);
            }
#pragma unroll
            for (int mt = 0; mt < 4; ++mt) {
                uint4 a = *(const uint4*)(aFrag + ((mt * 16 + kt) * 32 + l) * 4);
#pragma unroll
                for (int g = 0; g < 4; ++g) mma_tf32(acc[mt][g], a, b[g]);
            }
        }
        __syncthreads();   // aFrag reads done; safe to overwrite

        // ---- epilogue: gates, c/h update, h -> aFrag (kt = 8+w) ----
        float px[4][2], pq[4][2];
#pragma unroll
        for (int mt = 0; mt < 4; ++mt) {
            float h[4];
#pragma unroll
            for (int s = 0; s < 4; ++s) {
                float iv = acc[mt][0][s], jv = acc[mt][1][s];
                float fv = acc[mt][2][s], ov = acc[mt][3][s];
                float cn = cst[mt][s] * sigf(fv + 1.f) + sigf(iv) * tanh_fast(jv);
                cst[mt][s] = cn;
                h[s] = tanh_fast(cn) * sigf(ov);
            }
            px[mt][0] = h[0] * wxu0 + h[1] * wxu1;
            px[mt][1] = h[2] * wxu0 + h[3] * wxu1;
            pq[mt][0] = h[0] * wpu0 + h[1] * wpu1;
            pq[mt][1] = h[2] * wpu0 + h[3] * wpu1;

            float* dst = aFrag + ((mt * 16 + kth) * 32 + laneh) * 4 + regLo;
            dst[0] = __uint_as_float(cvt_tf32(h[0]));  // (rowLo, u0)
            dst[1] = __uint_as_float(cvt_tf32(h[2]));  // (rowHi, u0)
            dst[4] = __uint_as_float(cvt_tf32(h[1]));  // (rowLo, u0+1)
            dst[5] = __uint_as_float(cvt_tf32(h[3]));  // (rowHi, u0+1)
        }

        // ---- prefetch x for next step into aFrag (kts 0..7) ----
        if (st < 63) {
            int t2 = dir ? (63 - (st + 1)) : (st + 1);
            const float4* src = (const float4*)(g_x2 + ((size_t)t2 * 64 + blkx) * 4096);
            float4* dstA = (float4*)aFrag;
#pragma unroll
            for (int q = 0; q < 4; ++q) {
                int f = tid + q * 256;
                dstA[f + (f >> 8) * 256] = src[f];
            }
        }

        // ---- xs/ps: reduce over the warp's 8 units, then cross-warp ----
#pragma unroll
        for (int o = 1; o <= 2; o <<= 1) {
#pragma unroll
            for (int mt = 0; mt < 4; ++mt) {
                px[mt][0] += __shfl_xor_sync(0xffffffffu, px[mt][0], o);
                px[mt][1] += __shfl_xor_sync(0xffffffffu, px[mt][1], o);
                pq[mt][0] += __shfl_xor_sync(0xffffffffu, pq[mt][0], o);
                pq[mt][1] += __shfl_xor_sync(0xffffffffu, pq[mt][1], o);
            }
        }
        if ((l & 3) == 0) {
#pragma unroll
            for (int mt = 0; mt < 4; ++mt) {
                int seqlo = mt * 16 + (l >> 2);
                red[w * 64 + seqlo]           = px[mt][0];
                red[w * 64 + seqlo + 8]       = px[mt][1];
                red[512 + w * 64 + seqlo]     = pq[mt][0];
                red[512 + w * 64 + seqlo + 8] = pq[mt][1];
            }
        }
        __syncthreads();
        if (tid < 128) {
            int which = tid >> 6, seq = tid & 63;
            const float* rb = red + which * 512 + seq;
            float v = rb[0] + rb[64] + rb[128] + rb[192]
                    + rb[256] + rb[320] + rb[384] + rb[448];
            v += which ? bps : bxs;
            float* gdst = which ? g_ps : g_xs;
            gdst[((size_t)dir * Bn + b0 + seq) * Tn + t] = v;
        }
    }
}

// =====================================================================
// Kernel 3: attention head. warp per sequence; 8 seqs / block.
// =====================================================================
__global__ void __launch_bounds__(256) attn_kernel(
    const float* __restrict__ gp, const float* __restrict__ bep,
    const float* __restrict__ W3, const float* __restrict__ b3,
    float* __restrict__ out)
{
    __shared__ float sW3[4096];
    __shared__ float sb3[64];
    const int tid = threadIdx.x;
    for (int i = tid; i < 1024; i += 256) ((float4*)sW3)[i] = ((const float4*)W3)[i];
    if (tid < 64) sb3[tid] = b3[tid];
    __syncthreads();

    const int lane = tid & 31, w = tid >> 5;
    const int seq = blockIdx.x * 8 + w;

    const float* psr = g_ps + (size_t)seq * Tn;
    float v0 = psr[lane], v1 = psr[lane + 32];
    float s = v0 + v1, q = v0 * v0 + v1 * v1;
#pragma unroll
    for (int o = 16; o; o >>= 1) {
        s += __shfl_xor_sync(0xffffffffu, s, o);
        q += __shfl_xor_sync(0xffffffffu, q, o);
    }
    float m = s * 0.015625f;
    float var = q * 0.015625f - m * m;
    float rs = rsqrtf(var + 1e-12f);
    float p0 = fmaxf((v0 - m) * rs * gp[lane]      + bep[lane],      0.f);
    float p1 = fmaxf((v1 - m) * rs * gp[lane + 32] + bep[lane + 32], 0.f);

    float l0 = sb3[lane], l1 = sb3[lane + 32];
#pragma unroll 8
    for (int tt = 0; tt < 32; ++tt) {
        float pv = __shfl_sync(0xffffffffu, p0, tt);
        l0 += pv * sW3[tt * 64 + lane];
        l1 += pv * sW3[tt * 64 + lane + 32];
    }
#pragma unroll 8
    for (int tt = 0; tt < 32; ++tt) {
        float pv = __shfl_sync(0xffffffffu, p1, tt);
        l0 += pv * sW3[(32 + tt) * 64 + lane];
        l1 += pv * sW3[(32 + tt) * 64 + lane + 32];
    }

    float mx = fmaxf(l0, l1);
#pragma unroll
    for (int o = 16; o; o >>= 1) mx = fmaxf(mx, __shfl_xor_sync(0xffffffffu, mx, o));
    float e0 = __expf(l0 - mx), e1 = __expf(l1 - mx);
    float se = e0 + e1;
    const float* xsr = g_xs + (size_t)seq * Tn;
    float rsum = e0 * xsr[lane] + e1 * xsr[lane + 32];
#pragma unroll
    for (int o = 16; o; o >>= 1) {
        se   += __shfl_xor_sync(0xffffffffu, se, o);
        rsum += __shfl_xor_sync(0xffffffffu, rsum, o);
    }
    if (lane == 0) out[seq] = rsum / se;
}

// =====================================================================
extern "C" void kernel_launch(void* const* d_in, const int* in_sizes, int n_in,
                              void* d_out, int out_size)
{
    const float* obs = (const float*)d_in[0];
    const float* act = (const float*)d_in[1];
    const float* W1  = (const float*)d_in[2];
    const float* b1  = (const float*)d_in[3];
    const float* g1  = (const float*)d_in[4];
    const float* be1 = (const float*)d_in[5];
    const float* W2  = (const float*)d_in[6];
    const float* b2  = (const float*)d_in[7];
    const float* g2  = (const float*)d_in[8];
    const float* be2 = (const float*)d_in[9];
    const float* Wf  = (const float*)d_in[10];
    const float* bf  = (const float*)d_in[11];
    const float* Wb  = (const float*)d_in[12];
    const float* bb  = (const float*)d_in[13];
    const float* wx  = (const float*)d_in[14];
    const float* bx  = (const float*)d_in[15];
    const float* wp  = (const float*)d_in[16];
    const float* bp  = (const float*)d_in[17];
    const float* gp  = (const float*)d_in[18];
    const float* bep = (const float*)d_in[19];
    const float* W3  = (const float*)d_in[20];
    const float* b3  = (const float*)d_in[21];
    float* out = (float*)d_out;

    const int trunk_smem = (128 * 64 + 96 * 64 + 64 * STR + 96 * STR + 6 * 64) * 4;
    const int lstm_smem  = (32768 + 8192 + 1024) * 4;   // 167936 B
    cudaFuncSetAttribute(trunk_kernel, cudaFuncAttributeMaxDynamicSharedMemorySize, trunk_smem);
    cudaFuncSetAttribute(lstm_kernel,  cudaFuncAttributeMaxDynamicSharedMemorySize, lstm_smem);

    trunk_kernel<<<4096, 256, trunk_smem>>>(obs, act, W1, b1, g1, be1, W2, b2, g2, be2);

    dim3 lg(64, 2);
    lstm_kernel<<<lg, 256, lstm_smem>>>(Wf, bf, Wb, bb, wx, bx, wp, bp);

    attn_kernel<<<1024, 256>>>(gp, bep, W3, b3, out);
}

// round 7
// speedup vs baseline: 3.0957x; 1.4299x over previous
#include <cuda_runtime.h>
#include <math.h>

#define Bn 4096
#define Tn 64

typedef unsigned long long ull;

// ---------------- device scratch (allocation-free rule: __device__ globals) ----
__device__ float g_x2[(size_t)Tn * Bn * 64];   // [t][b][64], tf32-rounded
__device__ float g_xs[(size_t)2 * Bn * Tn];    // [2B][T]
__device__ float g_ps[(size_t)2 * Bn * Tn];    // [2B][T]

__device__ __forceinline__ float sigf(float x) {
    return __fdividef(1.f, 1.f + __expf(-x));
}
__device__ __forceinline__ float tanh_fast(float x) {
    float e = __expf(-2.f * fabsf(x));
    float t = __fdividef(1.f - e, 1.f + e);
    return copysignf(t, x);
}
__device__ __forceinline__ unsigned cvt_tf32(float x) {
    unsigned r; asm("cvt.rna.tf32.f32 %0, %1;" : "=r"(r) : "f"(x)); return r;
}
__device__ __forceinline__ void split_tf32(float f, unsigned& hi, unsigned& lo) {
    hi = cvt_tf32(f);
    lo = cvt_tf32(f - __uint_as_float(hi));
}
__device__ __forceinline__ void mma_tf32(float* c, uint4 a, uint2 b) {
    asm volatile(
        "mma.sync.aligned.m16n8k8.row.col.f32.tf32.tf32.f32 "
        "{%0,%1,%2,%3}, {%4,%5,%6,%7}, {%8,%9}, {%0,%1,%2,%3};"
        : "+f"(c[0]), "+f"(c[1]), "+f"(c[2]), "+f"(c[3])
        : "r"(a.x), "r"(a.y), "r"(a.z), "r"(a.w), "r"(b.x), "r"(b.y));
}

// =====================================================================
// Kernel 1: MLP trunk via tf32 mma, A-split for precision.
// M=128 rows/CTA (grid 2048), 8 warps, warp w owns m-tile rows 16w..16w+15.
// x2 written coalesced to g_x2 in plain [t][b][64] (tf32-rounded values).
// =====================================================================
__global__ void __launch_bounds__(256, 1) trunk_kernel(
    const float* __restrict__ obs, const float* __restrict__ act,
    const float* __restrict__ W1, const float* __restrict__ b1,
    const float* __restrict__ g1, const float* __restrict__ be1,
    const float* __restrict__ W2, const float* __restrict__ b2,
    const float* __restrict__ g2, const float* __restrict__ be2)
{
    extern __shared__ float sm[];
    ull*   B1  = (ull*)sm;                    // 4096 ull  (32 KB) W1 frags [nt][kt][lane]
    ull*   B2  = (ull*)(sm + 8192);           // 3072 ull  (24 KB) W2 frags
    float* sX  = sm + 8192 + 6144;            // 128 x 132 (obs tile; later out stage)
    float* sA2 = sX + 128 * 132;              // 128 x 100 (x1 | action)
    float* sP  = sA2 + 128 * 100;             // 384 params

    const int tid = threadIdx.x;
    const int l = tid & 31, w = tid >> 5;
    const int row0 = blockIdx.x * 128;

    // ---- stage W1/W2 into B-fragment layout (tf32) ----
#pragma unroll
    for (int q = 0; q < 16; ++q) {
        int s = tid + q * 256;
        int lane = s & 31, kt = (s >> 5) & 15, nt = s >> 9;
        int k0 = kt * 8 + (lane & 3), n = nt * 8 + (lane >> 2);
        ull lo = cvt_tf32(W1[k0 * 64 + n]);
        ull hi = cvt_tf32(W1[(k0 + 4) * 64 + n]);
        B1[s] = (hi << 32) | lo;
    }
#pragma unroll
    for (int q = 0; q < 12; ++q) {
        int s = tid + q * 256;
        int lane = s & 31, r = s >> 5;
        int kt = r % 12, nt = r / 12;
        int k0 = kt * 8 + (lane & 3), n = nt * 8 + (lane >> 2);
        ull lo = cvt_tf32(W2[k0 * 64 + n]);
        ull hi = cvt_tf32(W2[(k0 + 4) * 64 + n]);
        B2[s] = (hi << 32) | lo;
    }
    if (tid < 64) {
        sP[tid]       = b1[tid];  sP[64 + tid]  = g1[tid];  sP[128 + tid] = be1[tid];
        sP[192 + tid] = b2[tid];  sP[256 + tid] = g2[tid];  sP[320 + tid] = be2[tid];
    }
    // ---- load obs tile [128 x 128] coalesced ----
#pragma unroll
    for (int q = 0; q < 16; ++q) {
        int f = tid + q * 256;
        int row = f >> 5, c4 = f & 31;
        float4 v = *(const float4*)(obs + (size_t)(row0 + row) * 128 + c4 * 4);
        *(float4*)(sX + row * 132 + c4 * 4) = v;
    }
    __syncthreads();

    const int q4 = l & 3, rlq = l >> 2;
    const int ar = w * 16 + rlq;

    // ---- GEMM1: acc[nt][4], init with b1 ----
    float acc[8][4];
#pragma unroll
    for (int nt = 0; nt < 8; ++nt) {
        int c0 = nt * 8 + 2 * q4;
        acc[nt][0] = sP[c0]; acc[nt][1] = sP[c0 + 1];
        acc[nt][2] = sP[c0]; acc[nt][3] = sP[c0 + 1];
    }
#pragma unroll
    for (int kt = 0; kt < 16; ++kt) {
        int c = kt * 8 + q4;
        float f0 = sX[ar * 132 + c];
        float f1 = sX[(ar + 8) * 132 + c];
        float f2 = sX[ar * 132 + c + 4];
        float f3 = sX[(ar + 8) * 132 + c + 4];
        uint4 ahi, alo;
        split_tf32(f0, ahi.x, alo.x);
        split_tf32(f1, ahi.y, alo.y);
        split_tf32(f2, ahi.z, alo.z);
        split_tf32(f3, ahi.w, alo.w);
#pragma unroll
        for (int nt = 0; nt < 8; ++nt) {
            ull v = B1[(nt * 16 + kt) * 32 + l];
            uint2 b; b.x = (unsigned)v; b.y = (unsigned)(v >> 32);
            mma_tf32(acc[nt], ahi, b);
            mma_tf32(acc[nt], alo, b);
        }
    }

    // ---- LN1 + relu -> sA2 cols 0..63 ----
    {
        float sl = 0.f, ql = 0.f, sh = 0.f, qh = 0.f;
#pragma unroll
        for (int nt = 0; nt < 8; ++nt) {
            sl += acc[nt][0] + acc[nt][1];
            ql += acc[nt][0] * acc[nt][0] + acc[nt][1] * acc[nt][1];
            sh += acc[nt][2] + acc[nt][3];
            qh += acc[nt][2] * acc[nt][2] + acc[nt][3] * acc[nt][3];
        }
#pragma unroll
        for (int o = 1; o <= 2; o <<= 1) {
            sl += __shfl_xor_sync(0xffffffffu, sl, o);
            ql += __shfl_xor_sync(0xffffffffu, ql, o);
            sh += __shfl_xor_sync(0xffffffffu, sh, o);
            qh += __shfl_xor_sync(0xffffffffu, qh, o);
        }
        float ml = sl * 0.015625f, vl = ql * 0.015625f - ml * ml;
        float mh = sh * 0.015625f, vh = qh * 0.015625f - mh * mh;
        float il = rsqrtf(vl + 1e-12f), ih = rsqrtf(vh + 1e-12f);
#pragma unroll
        for (int nt = 0; nt < 8; ++nt) {
            int c0 = nt * 8 + 2 * q4;
            float g0 = sP[64 + c0], g1v = sP[64 + c0 + 1];
            float e0 = sP[128 + c0], e1v = sP[128 + c0 + 1];
            float2 zl, zh;
            zl.x = fmaxf((acc[nt][0] - ml) * il * g0  + e0,  0.f);
            zl.y = fmaxf((acc[nt][1] - ml) * il * g1v + e1v, 0.f);
            zh.x = fmaxf((acc[nt][2] - mh) * ih * g0  + e0,  0.f);
            zh.y = fmaxf((acc[nt][3] - mh) * ih * g1v + e1v, 0.f);
            *(float2*)(sA2 + ar * 100 + c0)       = zl;
            *(float2*)(sA2 + (ar + 8) * 100 + c0) = zh;
        }
    }
    // ---- append action cols 64..95 ----
#pragma unroll
    for (int q = 0; q < 4; ++q) {
        int f = tid + q * 256;
        int row = f >> 3, c8 = f & 7;
        float4 v = *(const float4*)(act + (size_t)(row0 + row) * 32 + c8 * 4);
        *(float4*)(sA2 + row * 100 + 64 + c8 * 4) = v;
    }
    __syncthreads();

    // ---- GEMM2: K=96 ----
    float a2[8][4];
#pragma unroll
    for (int nt = 0; nt < 8; ++nt) {
        int c0 = nt * 8 + 2 * q4;
        a2[nt][0] = sP[192 + c0]; a2[nt][1] = sP[192 + c0 + 1];
        a2[nt][2] = sP[192 + c0]; a2[nt][3] = sP[192 + c0 + 1];
    }
#pragma unroll
    for (int kt = 0; kt < 12; ++kt) {
        int c = kt * 8 + q4;
        float f0 = sA2[ar * 100 + c];
        float f1 = sA2[(ar + 8) * 100 + c];
        float f2 = sA2[ar * 100 + c + 4];
        float f3 = sA2[(ar + 8) * 100 + c + 4];
        uint4 ahi, alo;
        split_tf32(f0, ahi.x, alo.x);
        split_tf32(f1, ahi.y, alo.y);
        split_tf32(f2, ahi.z, alo.z);
        split_tf32(f3, ahi.w, alo.w);
#pragma unroll
        for (int nt = 0; nt < 8; ++nt) {
            ull v = B2[(nt * 12 + kt) * 32 + l];
            uint2 b; b.x = (unsigned)v; b.y = (unsigned)(v >> 32);
            mma_tf32(a2[nt], ahi, b);
            mma_tf32(a2[nt], alo, b);
        }
    }

    // ---- LN2 + relu + tf32-round -> stage in sX -> coalesced STG ----
    {
        float sl = 0.f, ql = 0.f, sh = 0.f, qh = 0.f;
#pragma unroll
        for (int nt = 0; nt < 8; ++nt) {
            sl += a2[nt][0] + a2[nt][1];
            ql += a2[nt][0] * a2[nt][0] + a2[nt][1] * a2[nt][1];
            sh += a2[nt][2] + a2[nt][3];
            qh += a2[nt][2] * a2[nt][2] + a2[nt][3] * a2[nt][3];
        }
#pragma unroll
        for (int o = 1; o <= 2; o <<= 1) {
            sl += __shfl_xor_sync(0xffffffffu, sl, o);
            ql += __shfl_xor_sync(0xffffffffu, ql, o);
            sh += __shfl_xor_sync(0xffffffffu, sh, o);
            qh += __shfl_xor_sync(0xffffffffu, qh, o);
        }
        float ml = sl * 0.015625f, vl = ql * 0.015625f - ml * ml;
        float mh = sh * 0.015625f, vh = qh * 0.015625f - mh * mh;
        float il = rsqrtf(vl + 1e-12f), ih = rsqrtf(vh + 1e-12f);
#pragma unroll
        for (int nt = 0; nt < 8; ++nt) {
            int c0 = nt * 8 + 2 * q4;
            float g0 = sP[256 + c0], g1v = sP[256 + c0 + 1];
            float e0 = sP[320 + c0], e1v = sP[320 + c0 + 1];
            float2 zl, zh;
            zl.x = __uint_as_float(cvt_tf32(fmaxf((a2[nt][0] - ml) * il * g0  + e0,  0.f)));
            zl.y = __uint_as_float(cvt_tf32(fmaxf((a2[nt][1] - ml) * il * g1v + e1v, 0.f)));
            zh.x = __uint_as_float(cvt_tf32(fmaxf((a2[nt][2] - mh) * ih * g0  + e0,  0.f)));
            zh.y = __uint_as_float(cvt_tf32(fmaxf((a2[nt][3] - mh) * ih * g1v + e1v, 0.f)));
            *(float2*)(sX + ar * 132 + c0)       = zl;
            *(float2*)(sX + (ar + 8) * 132 + c0) = zh;
        }
    }
    __syncwarp();
#pragma unroll
    for (int j = 0; j < 8; ++j) {
        int row = w * 16 + 2 * j + (l >> 4);      // warp-local rows
        int c = (l & 15) * 4;
        float4 v = *(const float4*)(sX + row * 132 + c);
        int t = row & 63;
        int b = (blockIdx.x << 1) + (row >> 6);
        *(float4*)(g_x2 + ((size_t)t * Bn + b) * 64 + c) = v;
    }
}

// =====================================================================
// Kernel 2: bidirectional LSTM via tf32 mma. grid (64, 2).
// Plain padded smem buffer sXH [seq 64][k 128] (x cols 0..63, h cols 64..127);
// A-fragments gathered by 4 conflict-free LDS.32; h written back in place.
// =====================================================================
__global__ void __launch_bounds__(256, 1) lstm_kernel(
    const float* __restrict__ Wf, const float* __restrict__ bfv,
    const float* __restrict__ Wb, const float* __restrict__ bbv,
    const float* __restrict__ wx, const float* __restrict__ bx,
    const float* __restrict__ wp, const float* __restrict__ bp)
{
    extern __shared__ float sm[];
    float* wFrag = sm;              // 32768 floats (128KB): [w][g][kt][lane] x ull
    float* sXH   = wFrag + 32768;   // 64 x 132
    float* red   = sXH + 64 * 132;  // 1024: [2][8 warps][64 seqs]

    const int dir  = blockIdx.y;
    const int b0   = blockIdx.x * 64;
    const float* W    = dir ? Wb  : Wf;
    const float* bias = dir ? bbv : bfv;
    const int tid = threadIdx.x;
    const int l = tid & 31, w = tid >> 5;

    // ---- stage W into B-fragment layout with gate-unit permutation ----
    for (int q = 0; q < 64; ++q) {
        int s = tid + q * 256;
        int lane = s & 31, kt = (s >> 5) & 15, g = (s >> 9) & 3, ww = s >> 11;
        int k0 = kt * 8 + (lane & 3);
        int n  = g * 64 + 8 * ww + (lane >> 2);
        wFrag[s * 2]     = __uint_as_float(cvt_tf32(W[k0 * 256 + n]));
        wFrag[s * 2 + 1] = __uint_as_float(cvt_tf32(W[(k0 + 4) * 256 + n]));
    }
    // ---- zero h region; load x(t0) (coalesced, already tf32) ----
    {
        int t0 = dir ? 63 : 0;
        const float4* src = (const float4*)(g_x2 + ((size_t)t0 * Bn + b0) * 64);
#pragma unroll
        for (int q = 0; q < 4; ++q) {
            int f = tid + q * 256;
            int sq = f >> 4, c4 = f & 15;
            *(float4*)(sXH + sq * 132 + c4 * 4) = src[f];
            *(float4*)(sXH + sq * 132 + 64 + c4 * 4) = make_float4(0.f, 0.f, 0.f, 0.f);
        }
    }

    // ---- per-thread constants ----
    const int u0 = 8 * w + 2 * (l & 3);
    float bia[4][2];
#pragma unroll
    for (int g = 0; g < 4; ++g) {
        bia[g][0] = bias[g * 64 + u0];
        bia[g][1] = bias[g * 64 + u0 + 1];
    }
    const float wxu0 = wx[u0], wxu1 = wx[u0 + 1];
    const float wpu0 = wp[u0], wpu1 = wp[u0 + 1];
    const float bxs = bx[0], bps = bp[0];

    float cst[4][4];
#pragma unroll
    for (int mt = 0; mt < 4; ++mt)
#pragma unroll
        for (int s = 0; s < 4; ++s) cst[mt][s] = 0.f;

    const ull* wB = (const ull*)wFrag;
    const int q4 = l & 3, rlq = l >> 2;

    for (int st = 0; st < 64; ++st) {
        const int t = dir ? (63 - st) : st;
        __syncthreads();   // sXH (x_t + h_{t-1}) ready

        float acc[4][4][4];
#pragma unroll
        for (int mt = 0; mt < 4; ++mt)
#pragma unroll
            for (int g = 0; g < 4; ++g) {
                acc[mt][g][0] = bia[g][0]; acc[mt][g][1] = bia[g][1];
                acc[mt][g][2] = bia[g][0]; acc[mt][g][3] = bia[g][1];
            }

#pragma unroll
        for (int kt = 0; kt < 16; ++kt) {
            uint2 b[4];
#pragma unroll
            for (int g = 0; g < 4; ++g) {
                ull v = wB[(size_t)(((w * 4 + g) * 16 + kt) * 32 + l)];
                b[g].x = (unsigned)(v & 0xffffffffu);
                b[g].y = (unsigned)(v >> 32);
            }
            int c = kt * 8 + q4;
#pragma unroll
            for (int mt = 0; mt < 4; ++mt) {
                int r = mt * 16 + rlq;
                uint4 a;
                a.x = __float_as_uint(sXH[r * 132 + c]);
                a.y = __float_as_uint(sXH[(r + 8) * 132 + c]);
                a.z = __float_as_uint(sXH[r * 132 + c + 4]);
                a.w = __float_as_uint(sXH[(r + 8) * 132 + c + 4]);
#pragma unroll
                for (int g = 0; g < 4; ++g) mma_tf32(acc[mt][g], a, b[g]);
            }
        }
        __syncthreads();   // sXH reads done; safe to overwrite

        // ---- epilogue: gates, c/h update, h -> sXH cols 64..127 ----
        float px[4][2], pq[4][2];
#pragma unroll
        for (int mt = 0; mt < 4; ++mt) {
            float h[4];
#pragma unroll
            for (int s = 0; s < 4; ++s) {
                float iv = acc[mt][0][s], jv = acc[mt][1][s];
                float fv = acc[mt][2][s], ov = acc[mt][3][s];
                float cn = cst[mt][s] * sigf(fv + 1.f) + sigf(iv) * tanh_fast(jv);
                cst[mt][s] = cn;
                h[s] = tanh_fast(cn) * sigf(ov);
            }
            // h[0]=(r_lo,u0) h[1]=(r_lo,u0+1) h[2]=(r_hi,u0) h[3]=(r_hi,u0+1)
            px[mt][0] = h[0] * wxu0 + h[1] * wxu1;
            px[mt][1] = h[2] * wxu0 + h[3] * wxu1;
            pq[mt][0] = h[0] * wpu0 + h[1] * wpu1;
            pq[mt][1] = h[2] * wpu0 + h[3] * wpu1;

            int rlo = mt * 16 + rlq, rhi = rlo + 8;
            float2 vlo, vhi;
            vlo.x = __uint_as_float(cvt_tf32(h[0]));
            vlo.y = __uint_as_float(cvt_tf32(h[1]));
            vhi.x = __uint_as_float(cvt_tf32(h[2]));
            vhi.y = __uint_as_float(cvt_tf32(h[3]));
            *(float2*)(sXH + rlo * 132 + 64 + u0) = vlo;
            *(float2*)(sXH + rhi * 132 + 64 + u0) = vhi;
        }

        // ---- prefetch x for next step (coalesced) ----
        if (st < 63) {
            int t2 = dir ? (63 - (st + 1)) : (st + 1);
            const float4* src = (const float4*)(g_x2 + ((size_t)t2 * Bn + b0) * 64);
#pragma unroll
            for (int q = 0; q < 4; ++q) {
                int f = tid + q * 256;
                int sq = f >> 4, c4 = f & 15;
                *(float4*)(sXH + sq * 132 + c4 * 4) = src[f];
            }
        }

        // ---- xs/ps reductions ----
#pragma unroll
        for (int o = 1; o <= 2; o <<= 1) {
#pragma unroll
            for (int mt = 0; mt < 4; ++mt) {
                px[mt][0] += __shfl_xor_sync(0xffffffffu, px[mt][0], o);
                px[mt][1] += __shfl_xor_sync(0xffffffffu, px[mt][1], o);
                pq[mt][0] += __shfl_xor_sync(0xffffffffu, pq[mt][0], o);
                pq[mt][1] += __shfl_xor_sync(0xffffffffu, pq[mt][1], o);
            }
        }
        if ((l & 3) == 0) {
#pragma unroll
            for (int mt = 0; mt < 4; ++mt) {
                int seqlo = mt * 16 + (l >> 2);
                red[w * 64 + seqlo]           = px[mt][0];
                red[w * 64 + seqlo + 8]       = px[mt][1];
                red[512 + w * 64 + seqlo]     = pq[mt][0];
                red[512 + w * 64 + seqlo + 8] = pq[mt][1];
            }
        }
        __syncthreads();
        if (tid < 128) {
            int which = tid >> 6, seq = tid & 63;
            const float* rb = red + which * 512 + seq;
            float v = rb[0] + rb[64] + rb[128] + rb[192]
                    + rb[256] + rb[320] + rb[384] + rb[448];
            v += which ? bps : bxs;
            float* gdst = which ? g_ps : g_xs;
            gdst[((size_t)dir * Bn + b0 + seq) * Tn + t] = v;
        }
    }
}

// =====================================================================
// Kernel 3: attention head. warp per sequence; 8 seqs / block.
// =====================================================================
__global__ void __launch_bounds__(256) attn_kernel(
    const float* __restrict__ gp, const float* __restrict__ bep,
    const float* __restrict__ W3, const float* __restrict__ b3,
    float* __restrict__ out)
{
    __shared__ float sW3[4096];
    __shared__ float sb3[64];
    const int tid = threadIdx.x;
    for (int i = tid; i < 1024; i += 256) ((float4*)sW3)[i] = ((const float4*)W3)[i];
    if (tid < 64) sb3[tid] = b3[tid];
    __syncthreads();

    const int lane = tid & 31, w = tid >> 5;
    const int seq = blockIdx.x * 8 + w;

    const float* psr = g_ps + (size_t)seq * Tn;
    float v0 = psr[lane], v1 = psr[lane + 32];
    float s = v0 + v1, q = v0 * v0 + v1 * v1;
#pragma unroll
    for (int o = 16; o; o >>= 1) {
        s += __shfl_xor_sync(0xffffffffu, s, o);
        q += __shfl_xor_sync(0xffffffffu, q, o);
    }
    float m = s * 0.015625f;
    float var = q * 0.015625f - m * m;
    float rs = rsqrtf(var + 1e-12f);
    float p0 = fmaxf((v0 - m) * rs * gp[lane]      + bep[lane],      0.f);
    float p1 = fmaxf((v1 - m) * rs * gp[lane + 32] + bep[lane + 32], 0.f);

    float l0 = sb3[lane], l1 = sb3[lane + 32];
#pragma unroll 8
    for (int tt = 0; tt < 32; ++tt) {
        float pv = __shfl_sync(0xffffffffu, p0, tt);
        l0 += pv * sW3[tt * 64 + lane];
        l1 += pv * sW3[tt * 64 + lane + 32];
    }
#pragma unroll 8
    for (int tt = 0; tt < 32; ++tt) {
        float pv = __shfl_sync(0xffffffffu, p1, tt);
        l0 += pv * sW3[(32 + tt) * 64 + lane];
        l1 += pv * sW3[(32 + tt) * 64 + lane + 32];
    }

    float mx = fmaxf(l0, l1);
#pragma unroll
    for (int o = 16; o; o >>= 1) mx = fmaxf(mx, __shfl_xor_sync(0xffffffffu, mx, o));
    float e0 = __expf(l0 - mx), e1 = __expf(l1 - mx);
    float se = e0 + e1;
    const float* xsr = g_xs + (size_t)seq * Tn;
    float rsum = e0 * xsr[lane] + e1 * xsr[lane + 32];
#pragma unroll
    for (int o = 16; o; o >>= 1) {
        se   += __shfl_xor_sync(0xffffffffu, se, o);
        rsum += __shfl_xor_sync(0xffffffffu, rsum, o);
    }
    if (lane == 0) out[seq] = rsum / se;
}

// =====================================================================
extern "C" void kernel_launch(void* const* d_in, const int* in_sizes, int n_in,
                              void* d_out, int out_size)
{
    const float* obs = (const float*)d_in[0];
    const float* act = (const float*)d_in[1];
    const float* W1  = (const float*)d_in[2];
    const float* b1  = (const float*)d_in[3];
    const float* g1  = (const float*)d_in[4];
    const float* be1 = (const float*)d_in[5];
    const float* W2  = (const float*)d_in[6];
    const float* b2  = (const float*)d_in[7];
    const float* g2  = (const float*)d_in[8];
    const float* be2 = (const float*)d_in[9];
    const float* Wf  = (const float*)d_in[10];
    const float* bf  = (const float*)d_in[11];
    const float* Wb  = (const float*)d_in[12];
    const float* bb  = (const float*)d_in[13];
    const float* wx  = (const float*)d_in[14];
    const float* bx  = (const float*)d_in[15];
    const float* wp  = (const float*)d_in[16];
    const float* bp  = (const float*)d_in[17];
    const float* gp  = (const float*)d_in[18];
    const float* bep = (const float*)d_in[19];
    const float* W3  = (const float*)d_in[20];
    const float* b3  = (const float*)d_in[21];
    float* out = (float*)d_out;

    const int trunk_smem = (8192 + 6144 + 128 * 132 + 128 * 100 + 384) * 4;   // 177664 B
    const int lstm_smem  = (32768 + 64 * 132 + 1024) * 4;                      // 168960 B
    cudaFuncSetAttribute(trunk_kernel, cudaFuncAttributeMaxDynamicSharedMemorySize, trunk_smem);
    cudaFuncSetAttribute(lstm_kernel,  cudaFuncAttributeMaxDynamicSharedMemorySize, lstm_smem);

    trunk_kernel<<<2048, 256, trunk_smem>>>(obs, act, W1, b1, g1, be1, W2, b2, g2, be2);

    dim3 lg(64, 2);
    lstm_kernel<<<lg, 256, lstm_smem>>>(Wf, bf, Wb, bb, wx, bx, wp, bp);

    attn_kernel<<<1024, 256>>>(gp, bep, W3, b3, out);
}

// round 8
// speedup vs baseline: 3.2945x; 1.0642x over previous
#include <cuda_runtime.h>
#include <math.h>

#define Bn 4096
#define Tn 64

typedef unsigned long long ull;

// ---------------- device scratch (allocation-free rule: __device__ globals) ----
__device__ float g_x2[(size_t)Tn * Bn * 64];   // [t][b][64], tf32-rounded
__device__ float g_xs[(size_t)2 * Bn * Tn];    // [2B][T]
__device__ float g_ps[(size_t)2 * Bn * Tn];    // [2B][T]

__device__ __forceinline__ float tanha(float x) {
    float r; asm("tanh.approx.f32 %0, %1;" : "=f"(r) : "f"(x)); return r;
}
__device__ __forceinline__ float sigt(float x) {
    return fmaf(tanha(0.5f * x), 0.5f, 0.5f);
}
__device__ __forceinline__ unsigned cvt_tf32(float x) {
    unsigned r; asm("cvt.rna.tf32.f32 %0, %1;" : "=r"(r) : "f"(x)); return r;
}
__device__ __forceinline__ void split_tf32(float f, unsigned& hi, unsigned& lo) {
    hi = cvt_tf32(f);
    lo = cvt_tf32(f - __uint_as_float(hi));
}
__device__ __forceinline__ void mma_tf32(float* c, uint4 a, uint2 b) {
    asm volatile(
        "mma.sync.aligned.m16n8k8.row.col.f32.tf32.tf32.f32 "
        "{%0,%1,%2,%3}, {%4,%5,%6,%7}, {%8,%9}, {%0,%1,%2,%3};"
        : "+f"(c[0]), "+f"(c[1]), "+f"(c[2]), "+f"(c[3])
        : "r"(a.x), "r"(a.y), "r"(a.z), "r"(a.w), "r"(b.x), "r"(b.y));
}

// =====================================================================
// Kernel 1: MLP trunk via tf32 mma, A-split for precision. 512 threads.
// 16 warps: warp w -> rows 16*(w>>1)..+15, nt half (w&1)*4..+3.
// LN row sums combined across the warp pair through psum.
// =====================================================================
__global__ void __launch_bounds__(512, 1) trunk_kernel(
    const float* __restrict__ obs, const float* __restrict__ act,
    const float* __restrict__ W1, const float* __restrict__ b1,
    const float* __restrict__ g1, const float* __restrict__ be1,
    const float* __restrict__ W2, const float* __restrict__ b2,
    const float* __restrict__ g2, const float* __restrict__ be2)
{
    extern __shared__ float sm[];
    ull*   B1   = (ull*)sm;                    // 4096 ull (32 KB)
    ull*   B2   = (ull*)(sm + 8192);           // 3072 ull (24 KB)
    float* sX   = sm + 8192 + 6144;            // 128 x 132 (obs; later out stage)
    float* sA2  = sX + 128 * 132;              // 128 x 100 (x1 | action)
    float* psum = sA2 + 128 * 100;             // 128 x 4
    float* sP   = psum + 512;                  // 384 params

    const int tid = threadIdx.x;
    const int l = tid & 31, w = tid >> 5;
    const int wr = w >> 1, wn = w & 1;
    const int row0 = blockIdx.x * 128;

#pragma unroll
    for (int q = 0; q < 8; ++q) {
        int s = tid + q * 512;
        int lane = s & 31, kt = (s >> 5) & 15, nt = s >> 9;
        int k0 = kt * 8 + (lane & 3), n = nt * 8 + (lane >> 2);
        ull lo = cvt_tf32(W1[k0 * 64 + n]);
        ull hi = cvt_tf32(W1[(k0 + 4) * 64 + n]);
        B1[s] = (hi << 32) | lo;
    }
#pragma unroll
    for (int q = 0; q < 6; ++q) {
        int s = tid + q * 512;
        int lane = s & 31, r = s >> 5;
        int kt = r % 12, nt = r / 12;
        int k0 = kt * 8 + (lane & 3), n = nt * 8 + (lane >> 2);
        ull lo = cvt_tf32(W2[k0 * 64 + n]);
        ull hi = cvt_tf32(W2[(k0 + 4) * 64 + n]);
        B2[s] = (hi << 32) | lo;
    }
    if (tid < 64) {
        sP[tid]       = b1[tid];  sP[64 + tid]  = g1[tid];  sP[128 + tid] = be1[tid];
        sP[192 + tid] = b2[tid];  sP[256 + tid] = g2[tid];  sP[320 + tid] = be2[tid];
    }
#pragma unroll
    for (int q = 0; q < 8; ++q) {
        int f = tid + q * 512;
        int row = f >> 5, c4 = f & 31;
        *(float4*)(sX + row * 132 + c4 * 4) =
            *(const float4*)(obs + (size_t)(row0 + row) * 128 + c4 * 4);
    }
#pragma unroll
    for (int q = 0; q < 2; ++q) {
        int f = tid + q * 512;
        int row = f >> 3, c8 = f & 7;
        *(float4*)(sA2 + row * 100 + 64 + c8 * 4) =
            *(const float4*)(act + (size_t)(row0 + row) * 32 + c8 * 4);
    }
    __syncthreads();

    const int q4 = l & 3, rlq = l >> 2;
    const int ar = wr * 16 + rlq;

    // ---- GEMM1 ----
    float acc[4][4];
#pragma unroll
    for (int ntb = 0; ntb < 4; ++ntb) {
        int c0 = (wn * 4 + ntb) * 8 + 2 * q4;
        acc[ntb][0] = sP[c0]; acc[ntb][1] = sP[c0 + 1];
        acc[ntb][2] = sP[c0]; acc[ntb][3] = sP[c0 + 1];
    }
#pragma unroll
    for (int kt = 0; kt < 16; ++kt) {
        int c = kt * 8 + q4;
        uint4 ahi, alo;
        split_tf32(sX[ar * 132 + c],           ahi.x, alo.x);
        split_tf32(sX[(ar + 8) * 132 + c],     ahi.y, alo.y);
        split_tf32(sX[ar * 132 + c + 4],       ahi.z, alo.z);
        split_tf32(sX[(ar + 8) * 132 + c + 4], ahi.w, alo.w);
#pragma unroll
        for (int ntb = 0; ntb < 4; ++ntb) {
            ull v = B1[((wn * 4 + ntb) * 16 + kt) * 32 + l];
            uint2 b; b.x = (unsigned)v; b.y = (unsigned)(v >> 32);
            mma_tf32(acc[ntb], ahi, b);
            mma_tf32(acc[ntb], alo, b);
        }
    }

    // ---- LN1 (cross-pair sums via psum) + relu -> sA2 ----
    {
        float sl = 0.f, ql = 0.f, sh = 0.f, qh = 0.f;
#pragma unroll
        for (int ntb = 0; ntb < 4; ++ntb) {
            sl += acc[ntb][0] + acc[ntb][1];
            ql += acc[ntb][0] * acc[ntb][0] + acc[ntb][1] * acc[ntb][1];
            sh += acc[ntb][2] + acc[ntb][3];
            qh += acc[ntb][2] * acc[ntb][2] + acc[ntb][3] * acc[ntb][3];
        }
#pragma unroll
        for (int o = 1; o <= 2; o <<= 1) {
            sl += __shfl_xor_sync(0xffffffffu, sl, o);
            ql += __shfl_xor_sync(0xffffffffu, ql, o);
            sh += __shfl_xor_sync(0xffffffffu, sh, o);
            qh += __shfl_xor_sync(0xffffffffu, qh, o);
        }
        if (q4 == 0) {
            psum[ar * 4 + wn * 2]           = sl;
            psum[ar * 4 + wn * 2 + 1]       = ql;
            psum[(ar + 8) * 4 + wn * 2]     = sh;
            psum[(ar + 8) * 4 + wn * 2 + 1] = qh;
        }
        __syncthreads();
        float2 ol = *(float2*)(psum + ar * 4 + (wn ^ 1) * 2);
        float2 oh = *(float2*)(psum + (ar + 8) * 4 + (wn ^ 1) * 2);
        float ml = (sl + ol.x) * 0.015625f;
        float vl = (ql + ol.y) * 0.015625f - ml * ml;
        float mh = (sh + oh.x) * 0.015625f;
        float vh = (qh + oh.y) * 0.015625f - mh * mh;
        float il = rsqrtf(vl + 1e-12f), ih = rsqrtf(vh + 1e-12f);
#pragma unroll
        for (int ntb = 0; ntb < 4; ++ntb) {
            int c0 = (wn * 4 + ntb) * 8 + 2 * q4;
            float g0 = sP[64 + c0], g1v = sP[64 + c0 + 1];
            float e0 = sP[128 + c0], e1v = sP[128 + c0 + 1];
            float2 zl, zh;
            zl.x = fmaxf((acc[ntb][0] - ml) * il * g0  + e0,  0.f);
            zl.y = fmaxf((acc[ntb][1] - ml) * il * g1v + e1v, 0.f);
            zh.x = fmaxf((acc[ntb][2] - mh) * ih * g0  + e0,  0.f);
            zh.y = fmaxf((acc[ntb][3] - mh) * ih * g1v + e1v, 0.f);
            *(float2*)(sA2 + ar * 100 + c0)       = zl;
            *(float2*)(sA2 + (ar + 8) * 100 + c0) = zh;
        }
    }
    __syncthreads();   // pair's LN1 cols visible for GEMM2

    // ---- GEMM2: K=96 ----
    float a2[4][4];
#pragma unroll
    for (int ntb = 0; ntb < 4; ++ntb) {
        int c0 = (wn * 4 + ntb) * 8 + 2 * q4;
        a2[ntb][0] = sP[192 + c0]; a2[ntb][1] = sP[192 + c0 + 1];
        a2[ntb][2] = sP[192 + c0]; a2[ntb][3] = sP[192 + c0 + 1];
    }
#pragma unroll
    for (int kt = 0; kt < 12; ++kt) {
        int c = kt * 8 + q4;
        uint4 ahi, alo;
        split_tf32(sA2[ar * 100 + c],           ahi.x, alo.x);
        split_tf32(sA2[(ar + 8) * 100 + c],     ahi.y, alo.y);
        split_tf32(sA2[ar * 100 + c + 4],       ahi.z, alo.z);
        split_tf32(sA2[(ar + 8) * 100 + c + 4], ahi.w, alo.w);
#pragma unroll
        for (int ntb = 0; ntb < 4; ++ntb) {
            ull v = B2[((wn * 4 + ntb) * 12 + kt) * 32 + l];
            uint2 b; b.x = (unsigned)v; b.y = (unsigned)(v >> 32);
            mma_tf32(a2[ntb], ahi, b);
            mma_tf32(a2[ntb], alo, b);
        }
    }

    // ---- LN2 + relu + tf32 -> stage sX -> coalesced STG ----
    {
        float sl = 0.f, ql = 0.f, sh = 0.f, qh = 0.f;
#pragma unroll
        for (int ntb = 0; ntb < 4; ++ntb) {
            sl += a2[ntb][0] + a2[ntb][1];
            ql += a2[ntb][0] * a2[ntb][0] + a2[ntb][1] * a2[ntb][1];
            sh += a2[ntb][2] + a2[ntb][3];
            qh += a2[ntb][2] * a2[ntb][2] + a2[ntb][3] * a2[ntb][3];
        }
#pragma unroll
        for (int o = 1; o <= 2; o <<= 1) {
            sl += __shfl_xor_sync(0xffffffffu, sl, o);
            ql += __shfl_xor_sync(0xffffffffu, ql, o);
            sh += __shfl_xor_sync(0xffffffffu, sh, o);
            qh += __shfl_xor_sync(0xffffffffu, qh, o);
        }
        if (q4 == 0) {
            psum[ar * 4 + wn * 2]           = sl;
            psum[ar * 4 + wn * 2 + 1]       = ql;
            psum[(ar + 8) * 4 + wn * 2]     = sh;
            psum[(ar + 8) * 4 + wn * 2 + 1] = qh;
        }
        __syncthreads();
        float2 ol = *(float2*)(psum + ar * 4 + (wn ^ 1) * 2);
        float2 oh = *(float2*)(psum + (ar + 8) * 4 + (wn ^ 1) * 2);
        float ml = (sl + ol.x) * 0.015625f;
        float vl = (ql + ol.y) * 0.015625f - ml * ml;
        float mh = (sh + oh.x) * 0.015625f;
        float vh = (qh + oh.y) * 0.015625f - mh * mh;
        float il = rsqrtf(vl + 1e-12f), ih = rsqrtf(vh + 1e-12f);
#pragma unroll
        for (int ntb = 0; ntb < 4; ++ntb) {
            int c0 = (wn * 4 + ntb) * 8 + 2 * q4;
            float g0 = sP[256 + c0], g1v = sP[256 + c0 + 1];
            float e0 = sP[320 + c0], e1v = sP[320 + c0 + 1];
            float2 zl, zh;
            zl.x = __uint_as_float(cvt_tf32(fmaxf((a2[ntb][0] - ml) * il * g0  + e0,  0.f)));
            zl.y = __uint_as_float(cvt_tf32(fmaxf((a2[ntb][1] - ml) * il * g1v + e1v, 0.f)));
            zh.x = __uint_as_float(cvt_tf32(fmaxf((a2[ntb][2] - mh) * ih * g0  + e0,  0.f)));
            zh.y = __uint_as_float(cvt_tf32(fmaxf((a2[ntb][3] - mh) * ih * g1v + e1v, 0.f)));
            *(float2*)(sX + ar * 132 + c0)       = zl;
            *(float2*)(sX + (ar + 8) * 132 + c0) = zh;
        }
    }
    __syncthreads();
#pragma unroll
    for (int q = 0; q < 4; ++q) {
        int f = tid + q * 512;
        int row = f >> 4, c = (f & 15) * 4;
        float4 v = *(const float4*)(sX + row * 132 + c);
        int t = row & 63;
        int b = (blockIdx.x << 1) + (row >> 6);
        *(float4*)(g_x2 + ((size_t)t * Bn + b) * 64 + c) = v;
    }
}

// =====================================================================
// Kernel 2: bidirectional LSTM via tf32 mma. grid (64, 2). 2 syncs/step.
// tanh.approx gates; early LDG prefetch; h held in regs across sync2.
// =====================================================================
__global__ void __launch_bounds__(256, 1) lstm_kernel(
    const float* __restrict__ Wf, const float* __restrict__ bfv,
    const float* __restrict__ Wb, const float* __restrict__ bbv,
    const float* __restrict__ wx, const float* __restrict__ bx,
    const float* __restrict__ wp, const float* __restrict__ bp)
{
    extern __shared__ float sm[];
    float* wFrag = sm;                // 32768 floats (128KB)
    float* xb    = wFrag + 32768;     // 64 x 68
    float* hT    = xb + 64 * 68;      // 64 x 68
    float* red   = hT + 64 * 68;      // 1024

    const int dir = blockIdx.y;
    const int b0  = blockIdx.x * 64;
    const float* W    = dir ? Wb  : Wf;
    const float* bias = dir ? bbv : bfv;
    const int tid = threadIdx.x;
    const int l = tid & 31, w = tid >> 5;

    // ---- stage W into B-fragment layout with gate-unit permutation ----
    for (int q = 0; q < 64; ++q) {
        int s = tid + q * 256;
        int lane = s & 31, kt = (s >> 5) & 15, g = (s >> 9) & 3, ww = s >> 11;
        int k0 = kt * 8 + (lane & 3);
        int n  = g * 64 + 8 * ww + (lane >> 2);
        wFrag[s * 2]     = __uint_as_float(cvt_tf32(W[k0 * 256 + n]));
        wFrag[s * 2 + 1] = __uint_as_float(cvt_tf32(W[(k0 + 4) * 256 + n]));
    }
    // ---- load x(t0); zero hT ----
    {
        int t0 = dir ? 63 : 0;
        const float4* src = (const float4*)(g_x2 + ((size_t)t0 * Bn + b0) * 64);
#pragma unroll
        for (int q = 0; q < 4; ++q) {
            int f = tid + q * 256;
            int sq = f >> 4, c4 = f & 15;
            *(float4*)(xb + sq * 68 + c4 * 4) = src[f];
            *(float4*)(hT + sq * 68 + c4 * 4) = make_float4(0.f, 0.f, 0.f, 0.f);
        }
    }

    const int u0 = 8 * w + 2 * (l & 3);
    float bia[4][2];
#pragma unroll
    for (int g = 0; g < 4; ++g) {
        bia[g][0] = bias[g * 64 + u0];
        bia[g][1] = bias[g * 64 + u0 + 1];
    }
    const float wxu0 = wx[u0], wxu1 = wx[u0 + 1];
    const float wpu0 = wp[u0], wpu1 = wp[u0 + 1];
    const float bxs = bx[0], bps = bp[0];

    float cst[4][4];
#pragma unroll
    for (int mt = 0; mt < 4; ++mt)
#pragma unroll
        for (int s = 0; s < 4; ++s) cst[mt][s] = 0.f;

    const ull* wB = (const ull*)wFrag;
    const int q4 = l & 3, rlq = l >> 2;

    for (int st = 0; st < 64; ++st) {
        const int t = dir ? (63 - st) : st;
        __syncthreads();   // sync1: hT(prev) + xb stores visible

        // early prefetch of next x (latency hidden under mma/epilogue)
        float4 xpf0, xpf1, xpf2, xpf3;
        if (st < 63) {
            int t2 = dir ? (62 - st) : (st + 1);
            const float4* src = (const float4*)(g_x2 + ((size_t)t2 * Bn + b0) * 64);
            xpf0 = src[tid]; xpf1 = src[tid + 256];
            xpf2 = src[tid + 512]; xpf3 = src[tid + 768];
        }

        float acc[4][4][4];
#pragma unroll
        for (int mt = 0; mt < 4; ++mt)
#pragma unroll
            for (int g = 0; g < 4; ++g) {
                acc[mt][g][0] = bia[g][0]; acc[mt][g][1] = bia[g][1];
                acc[mt][g][2] = bia[g][0]; acc[mt][g][3] = bia[g][1];
            }

        // x-part (kt 0..7)
#pragma unroll
        for (int kt = 0; kt < 8; ++kt) {
            uint2 b[4];
#pragma unroll
            for (int g = 0; g < 4; ++g) {
                ull v = wB[(size_t)(((w * 4 + g) * 16 + kt) * 32 + l)];
                b[g].x = (unsigned)(v & 0xffffffffu);
                b[g].y = (unsigned)(v >> 32);
            }
            int c = kt * 8 + q4;
#pragma unroll
            for (int mt = 0; mt < 4; ++mt) {
                int r = mt * 16 + rlq;
                uint4 a;
                a.x = __float_as_uint(xb[r * 68 + c]);
                a.y = __float_as_uint(xb[(r + 8) * 68 + c]);
                a.z = __float_as_uint(xb[r * 68 + c + 4]);
                a.w = __float_as_uint(xb[(r + 8) * 68 + c + 4]);
#pragma unroll
                for (int g = 0; g < 4; ++g) mma_tf32(acc[mt][g], a, b[g]);
            }
        }
        // h-part (kt 8..15)
#pragma unroll
        for (int kt = 8; kt < 16; ++kt) {
            uint2 b[4];
#pragma unroll
            for (int g = 0; g < 4; ++g) {
                ull v = wB[(size_t)(((w * 4 + g) * 16 + kt) * 32 + l)];
                b[g].x = (unsigned)(v & 0xffffffffu);
                b[g].y = (unsigned)(v >> 32);
            }
            int c = (kt - 8) * 8 + q4;
#pragma unroll
            for (int mt = 0; mt < 4; ++mt) {
                int r = mt * 16 + rlq;
                uint4 a;
                a.x = __float_as_uint(hT[r * 68 + c]);
                a.y = __float_as_uint(hT[(r + 8) * 68 + c]);
                a.z = __float_as_uint(hT[r * 68 + c + 4]);
                a.w = __float_as_uint(hT[(r + 8) * 68 + c + 4]);
#pragma unroll
                for (int g = 0; g < 4; ++g) mma_tf32(acc[mt][g], a, b[g]);
            }
        }

        // ---- epilogue: gates (tanh.approx), c/h; h kept in regs ----
        float hreg[4][4];
        float px[4][2], pq[4][2];
#pragma unroll
        for (int mt = 0; mt < 4; ++mt) {
#pragma unroll
            for (int s = 0; s < 4; ++s) {
                float iv = acc[mt][0][s], jv = acc[mt][1][s];
                float fv = acc[mt][2][s], ov = acc[mt][3][s];
                float cn = cst[mt][s] * sigt(fv + 1.f) + sigt(iv) * tanha(jv);
                cst[mt][s] = cn;
                hreg[mt][s] = tanha(cn) * sigt(ov);
            }
            px[mt][0] = hreg[mt][0] * wxu0 + hreg[mt][1] * wxu1;
            px[mt][1] = hreg[mt][2] * wxu0 + hreg[mt][3] * wxu1;
            pq[mt][0] = hreg[mt][0] * wpu0 + hreg[mt][1] * wpu1;
            pq[mt][1] = hreg[mt][2] * wpu0 + hreg[mt][3] * wpu1;
        }
#pragma unroll
        for (int o = 1; o <= 2; o <<= 1) {
#pragma unroll
            for (int mt = 0; mt < 4; ++mt) {
                px[mt][0] += __shfl_xor_sync(0xffffffffu, px[mt][0], o);
                px[mt][1] += __shfl_xor_sync(0xffffffffu, px[mt][1], o);
                pq[mt][0] += __shfl_xor_sync(0xffffffffu, pq[mt][0], o);
                pq[mt][1] += __shfl_xor_sync(0xffffffffu, pq[mt][1], o);
            }
        }
        if ((l & 3) == 0) {
#pragma unroll
            for (int mt = 0; mt < 4; ++mt) {
                int seqlo = mt * 16 + (l >> 2);
                red[w * 64 + seqlo]           = px[mt][0];
                red[w * 64 + seqlo + 8]       = px[mt][1];
                red[512 + w * 64 + seqlo]     = pq[mt][0];
                red[512 + w * 64 + seqlo + 8] = pq[mt][1];
            }
        }
        __syncthreads();   // sync2: all hT/xb reads + red writes done

        // write new h (tf32)
#pragma unroll
        for (int mt = 0; mt < 4; ++mt) {
            int rlo = mt * 16 + rlq, rhi = rlo + 8;
            float2 vlo, vhi;
            vlo.x = __uint_as_float(cvt_tf32(hreg[mt][0]));
            vlo.y = __uint_as_float(cvt_tf32(hreg[mt][1]));
            vhi.x = __uint_as_float(cvt_tf32(hreg[mt][2]));
            vhi.y = __uint_as_float(cvt_tf32(hreg[mt][3]));
            *(float2*)(hT + rlo * 68 + u0) = vlo;
            *(float2*)(hT + rhi * 68 + u0) = vhi;
        }
        // store prefetched x
        if (st < 63) {
            int f0 = tid, f1 = tid + 256, f2 = tid + 512, f3 = tid + 768;
            *(float4*)(xb + (f0 >> 4) * 68 + (f0 & 15) * 4) = xpf0;
            *(float4*)(xb + (f1 >> 4) * 68 + (f1 & 15) * 4) = xpf1;
            *(float4*)(xb + (f2 >> 4) * 68 + (f2 & 15) * 4) = xpf2;
            *(float4*)(xb + (f3 >> 4) * 68 + (f3 & 15) * 4) = xpf3;
        }
        // final xs/ps reduce + STG
        if (tid < 128) {
            int which = tid >> 6, seq = tid & 63;
            const float* rb = red + which * 512 + seq;
            float v = rb[0] + rb[64] + rb[128] + rb[192]
                    + rb[256] + rb[320] + rb[384] + rb[448];
            v += which ? bps : bxs;
            float* gdst = which ? g_ps : g_xs;
            gdst[((size_t)dir * Bn + b0 + seq) * Tn + t] = v;
        }
    }
}

// =====================================================================
// Kernel 3: attention head. warp per sequence; 8 seqs / block.
// =====================================================================
__global__ void __launch_bounds__(256) attn_kernel(
    const float* __restrict__ gp, const float* __restrict__ bep,
    const float* __restrict__ W3, const float* __restrict__ b3,
    float* __restrict__ out)
{
    __shared__ float sW3[4096];
    __shared__ float sb3[64];
    const int tid = threadIdx.x;
    for (int i = tid; i < 1024; i += 256) ((float4*)sW3)[i] = ((const float4*)W3)[i];
    if (tid < 64) sb3[tid] = b3[tid];
    __syncthreads();

    const int lane = tid & 31, w = tid >> 5;
    const int seq = blockIdx.x * 8 + w;

    const float* psr = g_ps + (size_t)seq * Tn;
    float v0 = psr[lane], v1 = psr[lane + 32];
    float s = v0 + v1, q = v0 * v0 + v1 * v1;
#pragma unroll
    for (int o = 16; o; o >>= 1) {
        s += __shfl_xor_sync(0xffffffffu, s, o);
        q += __shfl_xor_sync(0xffffffffu, q, o);
    }
    float m = s * 0.015625f;
    float var = q * 0.015625f - m * m;
    float rs = rsqrtf(var + 1e-12f);
    float p0 = fmaxf((v0 - m) * rs * gp[lane]      + bep[lane],      0.f);
    float p1 = fmaxf((v1 - m) * rs * gp[lane + 32] + bep[lane + 32], 0.f);

    float l0 = sb3[lane], l1 = sb3[lane + 32];
#pragma unroll 8
    for (int tt = 0; tt < 32; ++tt) {
        float pv = __shfl_sync(0xffffffffu, p0, tt);
        l0 += pv * sW3[tt * 64 + lane];
        l1 += pv * sW3[tt * 64 + lane + 32];
    }
#pragma unroll 8
    for (int tt = 0; tt < 32; ++tt) {
        float pv = __shfl_sync(0xffffffffu, p1, tt);
        l0 += pv * sW3[(32 + tt) * 64 + lane];
        l1 += pv * sW3[(32 + tt) * 64 + lane + 32];
    }

    float mx = fmaxf(l0, l1);
#pragma unroll
    for (int o = 16; o; o >>= 1) mx = fmaxf(mx, __shfl_xor_sync(0xffffffffu, mx, o));
    float e0 = __expf(l0 - mx), e1 = __expf(l1 - mx);
    float se = e0 + e1;
    const float* xsr = g_xs + (size_t)seq * Tn;
    float rsum = e0 * xsr[lane] + e1 * xsr[lane + 32];
#pragma unroll
    for (int o = 16; o; o >>= 1) {
        se   += __shfl_xor_sync(0xffffffffu, se, o);
        rsum += __shfl_xor_sync(0xffffffffu, rsum, o);
    }
    if (lane == 0) out[seq] = rsum / se;
}

// =====================================================================
extern "C" void kernel_launch(void* const* d_in, const int* in_sizes, int n_in,
                              void* d_out, int out_size)
{
    const float* obs = (const float*)d_in[0];
    const float* act = (const float*)d_in[1];
    const float* W1  = (const float*)d_in[2];
    const float* b1  = (const float*)d_in[3];
    const float* g1  = (const float*)d_in[4];
    const float* be1 = (const float*)d_in[5];
    const float* W2  = (const float*)d_in[6];
    const float* b2  = (const float*)d_in[7];
    const float* g2  = (const float*)d_in[8];
    const float* be2 = (const float*)d_in[9];
    const float* Wf  = (const float*)d_in[10];
    const float* bf  = (const float*)d_in[11];
    const float* Wb  = (const float*)d_in[12];
    const float* bb  = (const float*)d_in[13];
    const float* wx  = (const float*)d_in[14];
    const float* bx  = (const float*)d_in[15];
    const float* wp  = (const float*)d_in[16];
    const float* bp  = (const float*)d_in[17];
    const float* gp  = (const float*)d_in[18];
    const float* bep = (const float*)d_in[19];
    const float* W3  = (const float*)d_in[20];
    const float* b3  = (const float*)d_in[21];
    float* out = (float*)d_out;

    const int trunk_smem = (8192 + 6144 + 128 * 132 + 128 * 100 + 512 + 384) * 4; // 179712 B
    const int lstm_smem  = (32768 + 2 * 64 * 68 + 1024) * 4;                      // 169984 B
    cudaFuncSetAttribute(trunk_kernel, cudaFuncAttributeMaxDynamicSharedMemorySize, trunk_smem);
    cudaFuncSetAttribute(lstm_kernel,  cudaFuncAttributeMaxDynamicSharedMemorySize, lstm_smem);

    trunk_kernel<<<2048, 512, trunk_smem>>>(obs, act, W1, b1, g1, be1, W2, b2, g2, be2);

    dim3 lg(64, 2);
    lstm_kernel<<<lg, 256, lstm_smem>>>(Wf, bf, Wb, bb, wx, bx, wp, bp);

    attn_kernel<<<1024, 256>>>(gp, bep, W3, b3, out);
}

// round 9
// speedup vs baseline: 3.5896x; 1.0896x over previous
#include <cuda_runtime.h>
#include <math.h>

#define Bn 4096
#define Tn 64

typedef unsigned long long ull;

// ---------------- device scratch (allocation-free rule: __device__ globals) ----
__device__ float g_x2[(size_t)Tn * Bn * 64];   // [t][b][64], tf32-rounded
__device__ float g_xs[(size_t)2 * Bn * Tn];    // [2B][T]
__device__ float g_ps[(size_t)2 * Bn * Tn];    // [2B][T]

__device__ __forceinline__ float tanha(float x) {
    float r; asm("tanh.approx.f32 %0, %1;" : "=f"(r) : "f"(x)); return r;
}
__device__ __forceinline__ float sigt(float x) {
    return fmaf(tanha(0.5f * x), 0.5f, 0.5f);
}
__device__ __forceinline__ unsigned cvt_tf32(float x) {
    unsigned r; asm("cvt.rna.tf32.f32 %0, %1;" : "=r"(r) : "f"(x)); return r;
}
__device__ __forceinline__ void mma_tf32(float* c, uint4 a, uint2 b) {
    asm volatile(
        "mma.sync.aligned.m16n8k8.row.col.f32.tf32.tf32.f32 "
        "{%0,%1,%2,%3}, {%4,%5,%6,%7}, {%8,%9}, {%0,%1,%2,%3};"
        : "+f"(c[0]), "+f"(c[1]), "+f"(c[2]), "+f"(c[3])
        : "r"(a.x), "r"(a.y), "r"(a.z), "r"(a.w), "r"(b.x), "r"(b.y));
}

// =====================================================================
// Kernel 1: MLP trunk via tf32 mma (single-pass, no A-split).
// M=128 rows/CTA (grid 2048), 256 threads, warp w owns rows 16w..16w+15.
// x2 written coalesced to g_x2 in plain [t][b][64] (tf32-rounded).
// =====================================================================
__global__ void __launch_bounds__(256, 1) trunk_kernel(
    const float* __restrict__ obs, const float* __restrict__ act,
    const float* __restrict__ W1, const float* __restrict__ b1,
    const float* __restrict__ g1, const float* __restrict__ be1,
    const float* __restrict__ W2, const float* __restrict__ b2,
    const float* __restrict__ g2, const float* __restrict__ be2)
{
    extern __shared__ float sm[];
    ull*   B1  = (ull*)sm;                    // 4096 ull (32 KB)
    ull*   B2  = (ull*)(sm + 8192);           // 3072 ull (24 KB)
    float* sX  = sm + 8192 + 6144;            // 128 x 132 (obs; later out stage)
    float* sA2 = sX + 128 * 132;              // 128 x 100 (x1 | action)
    float* sP  = sA2 + 128 * 100;             // 384 params

    const int tid = threadIdx.x;
    const int l = tid & 31, w = tid >> 5;
    const int row0 = blockIdx.x * 128;

#pragma unroll
    for (int q = 0; q < 16; ++q) {
        int s = tid + q * 256;
        int lane = s & 31, kt = (s >> 5) & 15, nt = s >> 9;
        int k0 = kt * 8 + (lane & 3), n = nt * 8 + (lane >> 2);
        ull lo = cvt_tf32(W1[k0 * 64 + n]);
        ull hi = cvt_tf32(W1[(k0 + 4) * 64 + n]);
        B1[s] = (hi << 32) | lo;
    }
#pragma unroll
    for (int q = 0; q < 12; ++q) {
        int s = tid + q * 256;
        int lane = s & 31, r = s >> 5;
        int kt = r % 12, nt = r / 12;
        int k0 = kt * 8 + (lane & 3), n = nt * 8 + (lane >> 2);
        ull lo = cvt_tf32(W2[k0 * 64 + n]);
        ull hi = cvt_tf32(W2[(k0 + 4) * 64 + n]);
        B2[s] = (hi << 32) | lo;
    }
    if (tid < 64) {
        sP[tid]       = b1[tid];  sP[64 + tid]  = g1[tid];  sP[128 + tid] = be1[tid];
        sP[192 + tid] = b2[tid];  sP[256 + tid] = g2[tid];  sP[320 + tid] = be2[tid];
    }
#pragma unroll
    for (int q = 0; q < 16; ++q) {
        int f = tid + q * 256;
        int row = f >> 5, c4 = f & 31;
        *(float4*)(sX + row * 132 + c4 * 4) =
            *(const float4*)(obs + (size_t)(row0 + row) * 128 + c4 * 4);
    }
#pragma unroll
    for (int q = 0; q < 4; ++q) {
        int f = tid + q * 256;
        int row = f >> 3, c8 = f & 7;
        *(float4*)(sA2 + row * 100 + 64 + c8 * 4) =
            *(const float4*)(act + (size_t)(row0 + row) * 32 + c8 * 4);
    }
    __syncthreads();

    const int q4 = l & 3, rlq = l >> 2;
    const int ar = w * 16 + rlq;

    // ---- GEMM1 (single tf32 pass) ----
    float acc[8][4];
#pragma unroll
    for (int nt = 0; nt < 8; ++nt) {
        int c0 = nt * 8 + 2 * q4;
        acc[nt][0] = sP[c0]; acc[nt][1] = sP[c0 + 1];
        acc[nt][2] = sP[c0]; acc[nt][3] = sP[c0 + 1];
    }
#pragma unroll
    for (int kt = 0; kt < 16; ++kt) {
        int c = kt * 8 + q4;
        uint4 a;
        a.x = cvt_tf32(sX[ar * 132 + c]);
        a.y = cvt_tf32(sX[(ar + 8) * 132 + c]);
        a.z = cvt_tf32(sX[ar * 132 + c + 4]);
        a.w = cvt_tf32(sX[(ar + 8) * 132 + c + 4]);
#pragma unroll
        for (int nt = 0; nt < 8; ++nt) {
            ull v = B1[(nt * 16 + kt) * 32 + l];
            uint2 b; b.x = (unsigned)v; b.y = (unsigned)(v >> 32);
            mma_tf32(acc[nt], a, b);
        }
    }

    // ---- LN1 + relu -> sA2 ----
    {
        float sl = 0.f, ql = 0.f, sh = 0.f, qh = 0.f;
#pragma unroll
        for (int nt = 0; nt < 8; ++nt) {
            sl += acc[nt][0] + acc[nt][1];
            ql += acc[nt][0] * acc[nt][0] + acc[nt][1] * acc[nt][1];
            sh += acc[nt][2] + acc[nt][3];
            qh += acc[nt][2] * acc[nt][2] + acc[nt][3] * acc[nt][3];
        }
#pragma unroll
        for (int o = 1; o <= 2; o <<= 1) {
            sl += __shfl_xor_sync(0xffffffffu, sl, o);
            ql += __shfl_xor_sync(0xffffffffu, ql, o);
            sh += __shfl_xor_sync(0xffffffffu, sh, o);
            qh += __shfl_xor_sync(0xffffffffu, qh, o);
        }
        float ml = sl * 0.015625f, vl = ql * 0.015625f - ml * ml;
        float mh = sh * 0.015625f, vh = qh * 0.015625f - mh * mh;
        float il = rsqrtf(vl + 1e-12f), ih = rsqrtf(vh + 1e-12f);
#pragma unroll
        for (int nt = 0; nt < 8; ++nt) {
            int c0 = nt * 8 + 2 * q4;
            float g0 = sP[64 + c0], g1v = sP[64 + c0 + 1];
            float e0 = sP[128 + c0], e1v = sP[128 + c0 + 1];
            float2 zl, zh;
            zl.x = fmaxf((acc[nt][0] - ml) * il * g0  + e0,  0.f);
            zl.y = fmaxf((acc[nt][1] - ml) * il * g1v + e1v, 0.f);
            zh.x = fmaxf((acc[nt][2] - mh) * ih * g0  + e0,  0.f);
            zh.y = fmaxf((acc[nt][3] - mh) * ih * g1v + e1v, 0.f);
            *(float2*)(sA2 + ar * 100 + c0)       = zl;
            *(float2*)(sA2 + (ar + 8) * 100 + c0) = zh;
        }
    }
    __syncthreads();

    // ---- GEMM2: K=96 (single tf32 pass) ----
    float a2[8][4];
#pragma unroll
    for (int nt = 0; nt < 8; ++nt) {
        int c0 = nt * 8 + 2 * q4;
        a2[nt][0] = sP[192 + c0]; a2[nt][1] = sP[192 + c0 + 1];
        a2[nt][2] = sP[192 + c0]; a2[nt][3] = sP[192 + c0 + 1];
    }
#pragma unroll
    for (int kt = 0; kt < 12; ++kt) {
        int c = kt * 8 + q4;
        uint4 a;
        a.x = cvt_tf32(sA2[ar * 100 + c]);
        a.y = cvt_tf32(sA2[(ar + 8) * 100 + c]);
        a.z = cvt_tf32(sA2[ar * 100 + c + 4]);
        a.w = cvt_tf32(sA2[(ar + 8) * 100 + c + 4]);
#pragma unroll
        for (int nt = 0; nt < 8; ++nt) {
            ull v = B2[(nt * 12 + kt) * 32 + l];
            uint2 b; b.x = (unsigned)v; b.y = (unsigned)(v >> 32);
            mma_tf32(a2[nt], a, b);
        }
    }

    // ---- LN2 + relu + tf32 -> stage sX -> coalesced STG ----
    {
        float sl = 0.f, ql = 0.f, sh = 0.f, qh = 0.f;
#pragma unroll
        for (int nt = 0; nt < 8; ++nt) {
            sl += a2[nt][0] + a2[nt][1];
            ql += a2[nt][0] * a2[nt][0] + a2[nt][1] * a2[nt][1];
            sh += a2[nt][2] + a2[nt][3];
            qh += a2[nt][2] * a2[nt][2] + a2[nt][3] * a2[nt][3];
        }
#pragma unroll
        for (int o = 1; o <= 2; o <<= 1) {
            sl += __shfl_xor_sync(0xffffffffu, sl, o);
            ql += __shfl_xor_sync(0xffffffffu, ql, o);
            sh += __shfl_xor_sync(0xffffffffu, sh, o);
            qh += __shfl_xor_sync(0xffffffffu, qh, o);
        }
        float ml = sl * 0.015625f, vl = ql * 0.015625f - ml * ml;
        float mh = sh * 0.015625f, vh = qh * 0.015625f - mh * mh;
        float il = rsqrtf(vl + 1e-12f), ih = rsqrtf(vh + 1e-12f);
#pragma unroll
        for (int nt = 0; nt < 8; ++nt) {
            int c0 = nt * 8 + 2 * q4;
            float g0 = sP[256 + c0], g1v = sP[256 + c0 + 1];
            float e0 = sP[320 + c0], e1v = sP[320 + c0 + 1];
            float2 zl, zh;
            zl.x = __uint_as_float(cvt_tf32(fmaxf((a2[nt][0] - ml) * il * g0  + e0,  0.f)));
            zl.y = __uint_as_float(cvt_tf32(fmaxf((a2[nt][1] - ml) * il * g1v + e1v, 0.f)));
            zh.x = __uint_as_float(cvt_tf32(fmaxf((a2[nt][2] - mh) * ih * g0  + e0,  0.f)));
            zh.y = __uint_as_float(cvt_tf32(fmaxf((a2[nt][3] - mh) * ih * g1v + e1v, 0.f)));
            *(float2*)(sX + ar * 132 + c0)       = zl;
            *(float2*)(sX + (ar + 8) * 132 + c0) = zh;
        }
    }
    __syncwarp();
#pragma unroll
    for (int j = 0; j < 8; ++j) {
        int row = w * 16 + 2 * j + (l >> 4);
        int c = (l & 15) * 4;
        float4 v = *(const float4*)(sX + row * 132 + c);
        int t = row & 63;
        int b = (blockIdx.x << 1) + (row >> 6);
        *(float4*)(g_x2 + ((size_t)t * Bn + b) * 64 + c) = v;
    }
}

// =====================================================================
// Kernel 2: bidirectional LSTM via tf32 mma. grid (64, 2), 512 threads.
// 16 warps: wu = w&7 -> unit group (8 units x 4 gates), wm = w>>3 -> seq
// half (mt in {2wm, 2wm+1}). 2 syncs/step; tanh.approx gates.
// =====================================================================
__global__ void __launch_bounds__(512, 1) lstm_kernel(
    const float* __restrict__ Wf, const float* __restrict__ bfv,
    const float* __restrict__ Wb, const float* __restrict__ bbv,
    const float* __restrict__ wx, const float* __restrict__ bx,
    const float* __restrict__ wp, const float* __restrict__ bp)
{
    extern __shared__ float sm[];
    float* wFrag = sm;                // 32768 floats (128KB)
    float* xb    = wFrag + 32768;     // 64 x 68
    float* hT    = xb + 64 * 68;      // 64 x 68
    float* red   = hT + 64 * 68;      // 1024

    const int dir = blockIdx.y;
    const int b0  = blockIdx.x * 64;
    const float* W    = dir ? Wb  : Wf;
    const float* bias = dir ? bbv : bfv;
    const int tid = threadIdx.x;
    const int l = tid & 31, w = tid >> 5;
    const int wu = w & 7, wm = w >> 3;

    // ---- stage W into B-fragment layout with gate-unit permutation ----
    for (int q = 0; q < 32; ++q) {
        int s = tid + q * 512;
        int lane = s & 31, kt = (s >> 5) & 15, g = (s >> 9) & 3, ww = s >> 11;
        int k0 = kt * 8 + (lane & 3);
        int n  = g * 64 + 8 * ww + (lane >> 2);
        wFrag[s * 2]     = __uint_as_float(cvt_tf32(W[k0 * 256 + n]));
        wFrag[s * 2 + 1] = __uint_as_float(cvt_tf32(W[(k0 + 4) * 256 + n]));
    }
    // ---- load x(t0); zero hT ----
    {
        int t0 = dir ? 63 : 0;
        const float4* src = (const float4*)(g_x2 + ((size_t)t0 * Bn + b0) * 64);
#pragma unroll
        for (int q = 0; q < 2; ++q) {
            int f = tid + q * 512;
            int sq = f >> 4, c4 = f & 15;
            *(float4*)(xb + sq * 68 + c4 * 4) = src[f];
            *(float4*)(hT + sq * 68 + c4 * 4) = make_float4(0.f, 0.f, 0.f, 0.f);
        }
    }

    const int u0 = 8 * wu + 2 * (l & 3);
    float bia[4][2];
#pragma unroll
    for (int g = 0; g < 4; ++g) {
        bia[g][0] = bias[g * 64 + u0];
        bia[g][1] = bias[g * 64 + u0 + 1];
    }
    const float wxu0 = wx[u0], wxu1 = wx[u0 + 1];
    const float wpu0 = wp[u0], wpu1 = wp[u0 + 1];
    const float bxs = bx[0], bps = bp[0];

    float cst[2][4];
#pragma unroll
    for (int mt = 0; mt < 2; ++mt)
#pragma unroll
        for (int s = 0; s < 4; ++s) cst[mt][s] = 0.f;

    const ull* wB = (const ull*)wFrag;
    const int q4 = l & 3, rlq = l >> 2;

    for (int st = 0; st < 64; ++st) {
        const int t = dir ? (63 - st) : st;
        __syncthreads();   // sync1: hT(prev) + xb stores visible

        float4 xpf0, xpf1;
        if (st < 63) {
            int t2 = dir ? (62 - st) : (st + 1);
            const float4* src = (const float4*)(g_x2 + ((size_t)t2 * Bn + b0) * 64);
            xpf0 = src[tid]; xpf1 = src[tid + 512];
        }

        float acc[2][4][4];
#pragma unroll
        for (int mt = 0; mt < 2; ++mt)
#pragma unroll
            for (int g = 0; g < 4; ++g) {
                acc[mt][g][0] = bia[g][0]; acc[mt][g][1] = bia[g][1];
                acc[mt][g][2] = bia[g][0]; acc[mt][g][3] = bia[g][1];
            }

        // x-part (kt 0..7)
#pragma unroll
        for (int kt = 0; kt < 8; ++kt) {
            uint2 b[4];
#pragma unroll
            for (int g = 0; g < 4; ++g) {
                ull v = wB[(size_t)(((wu * 4 + g) * 16 + kt) * 32 + l)];
                b[g].x = (unsigned)(v & 0xffffffffu);
                b[g].y = (unsigned)(v >> 32);
            }
            int c = kt * 8 + q4;
#pragma unroll
            for (int mt = 0; mt < 2; ++mt) {
                int r = (wm * 2 + mt) * 16 + rlq;
                uint4 a;
                a.x = __float_as_uint(xb[r * 68 + c]);
                a.y = __float_as_uint(xb[(r + 8) * 68 + c]);
                a.z = __float_as_uint(xb[r * 68 + c + 4]);
                a.w = __float_as_uint(xb[(r + 8) * 68 + c + 4]);
#pragma unroll
                for (int g = 0; g < 4; ++g) mma_tf32(acc[mt][g], a, b[g]);
            }
        }
        // h-part (kt 8..15)
#pragma unroll
        for (int kt = 8; kt < 16; ++kt) {
            uint2 b[4];
#pragma unroll
            for (int g = 0; g < 4; ++g) {
                ull v = wB[(size_t)(((wu * 4 + g) * 16 + kt) * 32 + l)];
                b[g].x = (unsigned)(v & 0xffffffffu);
                b[g].y = (unsigned)(v >> 32);
            }
            int c = (kt - 8) * 8 + q4;
#pragma unroll
            for (int mt = 0; mt < 2; ++mt) {
                int r = (wm * 2 + mt) * 16 + rlq;
                uint4 a;
                a.x = __float_as_uint(hT[r * 68 + c]);
                a.y = __float_as_uint(hT[(r + 8) * 68 + c]);
                a.z = __float_as_uint(hT[r * 68 + c + 4]);
                a.w = __float_as_uint(hT[(r + 8) * 68 + c + 4]);
#pragma unroll
                for (int g = 0; g < 4; ++g) mma_tf32(acc[mt][g], a, b[g]);
            }
        }

        // ---- epilogue: gates, c/h; h kept in regs across sync2 ----
        float hreg[2][4];
        float px[2][2], pq[2][2];
#pragma unroll
        for (int mt = 0; mt < 2; ++mt) {
#pragma unroll
            for (int s = 0; s < 4; ++s) {
                float iv = acc[mt][0][s], jv = acc[mt][1][s];
                float fv = acc[mt][2][s], ov = acc[mt][3][s];
                float cn = cst[mt][s] * sigt(fv + 1.f) + sigt(iv) * tanha(jv);
                cst[mt][s] = cn;
                hreg[mt][s] = tanha(cn) * sigt(ov);
            }
            px[mt][0] = hreg[mt][0] * wxu0 + hreg[mt][1] * wxu1;
            px[mt][1] = hreg[mt][2] * wxu0 + hreg[mt][3] * wxu1;
            pq[mt][0] = hreg[mt][0] * wpu0 + hreg[mt][1] * wpu1;
            pq[mt][1] = hreg[mt][2] * wpu0 + hreg[mt][3] * wpu1;
        }
#pragma unroll
        for (int o = 1; o <= 2; o <<= 1) {
#pragma unroll
            for (int mt = 0; mt < 2; ++mt) {
                px[mt][0] += __shfl_xor_sync(0xffffffffu, px[mt][0], o);
                px[mt][1] += __shfl_xor_sync(0xffffffffu, px[mt][1], o);
                pq[mt][0] += __shfl_xor_sync(0xffffffffu, pq[mt][0], o);
                pq[mt][1] += __shfl_xor_sync(0xffffffffu, pq[mt][1], o);
            }
        }
        if ((l & 3) == 0) {
#pragma unroll
            for (int mt = 0; mt < 2; ++mt) {
                int seqlo = (wm * 2 + mt) * 16 + (l >> 2);
                red[wu * 64 + seqlo]           = px[mt][0];
                red[wu * 64 + seqlo + 8]       = px[mt][1];
                red[512 + wu * 64 + seqlo]     = pq[mt][0];
                red[512 + wu * 64 + seqlo + 8] = pq[mt][1];
            }
        }
        __syncthreads();   // sync2: all hT/xb reads + red writes done

        // write new h (tf32)
#pragma unroll
        for (int mt = 0; mt < 2; ++mt) {
            int rlo = (wm * 2 + mt) * 16 + rlq, rhi = rlo + 8;
            float2 vlo, vhi;
            vlo.x = __uint_as_float(cvt_tf32(hreg[mt][0]));
            vlo.y = __uint_as_float(cvt_tf32(hreg[mt][1]));
            vhi.x = __uint_as_float(cvt_tf32(hreg[mt][2]));
            vhi.y = __uint_as_float(cvt_tf32(hreg[mt][3]));
            *(float2*)(hT + rlo * 68 + u0) = vlo;
            *(float2*)(hT + rhi * 68 + u0) = vhi;
        }
        // store prefetched x
        if (st < 63) {
            int f0 = tid, f1 = tid + 512;
            *(float4*)(xb + (f0 >> 4) * 68 + (f0 & 15) * 4) = xpf0;
            *(float4*)(xb + (f1 >> 4) * 68 + (f1 & 15) * 4) = xpf1;
        }
        // final xs/ps reduce + STG
        if (tid < 128) {
            int which = tid >> 6, seq = tid & 63;
            const float* rb = red + which * 512 + seq;
            float v = rb[0] + rb[64] + rb[128] + rb[192]
                    + rb[256] + rb[320] + rb[384] + rb[448];
            v += which ? bps : bxs;
            float* gdst = which ? g_ps : g_xs;
            gdst[((size_t)dir * Bn + b0 + seq) * Tn + t] = v;
        }
    }
}

// =====================================================================
// Kernel 3: attention head. warp per sequence; 8 seqs / block.
// =====================================================================
__global__ void __launch_bounds__(256) attn_kernel(
    const float* __restrict__ gp, const float* __restrict__ bep,
    const float* __restrict__ W3, const float* __restrict__ b3,
    float* __restrict__ out)
{
    __shared__ float sW3[4096];
    __shared__ float sb3[64];
    const int tid = threadIdx.x;
    for (int i = tid; i < 1024; i += 256) ((float4*)sW3)[i] = ((const float4*)W3)[i];
    if (tid < 64) sb3[tid] = b3[tid];
    __syncthreads();

    const int lane = tid & 31, w = tid >> 5;
    const int seq = blockIdx.x * 8 + w;

    const float* psr = g_ps + (size_t)seq * Tn;
    float v0 = psr[lane], v1 = psr[lane + 32];
    float s = v0 + v1, q = v0 * v0 + v1 * v1;
#pragma unroll
    for (int o = 16; o; o >>= 1) {
        s += __shfl_xor_sync(0xffffffffu, s, o);
        q += __shfl_xor_sync(0xffffffffu, q, o);
    }
    float m = s * 0.015625f;
    float var = q * 0.015625f - m * m;
    float rs = rsqrtf(var + 1e-12f);
    float p0 = fmaxf((v0 - m) * rs * gp[lane]      + bep[lane],      0.f);
    float p1 = fmaxf((v1 - m) * rs * gp[lane + 32] + bep[lane + 32], 0.f);

    float l0 = sb3[lane], l1 = sb3[lane + 32];
#pragma unroll 8
    for (int tt = 0; tt < 32; ++tt) {
        float pv = __shfl_sync(0xffffffffu, p0, tt);
        l0 += pv * sW3[tt * 64 + lane];
        l1 += pv * sW3[tt * 64 + lane + 32];
    }
#pragma unroll 8
    for (int tt = 0; tt < 32; ++tt) {
        float pv = __shfl_sync(0xffffffffu, p1, tt);
        l0 += pv * sW3[(32 + tt) * 64 + lane];
        l1 += pv * sW3[(32 + tt) * 64 + lane + 32];
    }

    float mx = fmaxf(l0, l1);
#pragma unroll
    for (int o = 16; o; o >>= 1) mx = fmaxf(mx, __shfl_xor_sync(0xffffffffu, mx, o));
    float e0 = __expf(l0 - mx), e1 = __expf(l1 - mx);
    float se = e0 + e1;
    const float* xsr = g_xs + (size_t)seq * Tn;
    float rsum = e0 * xsr[lane] + e1 * xsr[lane + 32];
#pragma unroll
    for (int o = 16; o; o >>= 1) {
        se   += __shfl_xor_sync(0xffffffffu, se, o);
        rsum += __shfl_xor_sync(0xffffffffu, rsum, o);
    }
    if (lane == 0) out[seq] = rsum / se;
}

// =====================================================================
extern "C" void kernel_launch(void* const* d_in, const int* in_sizes, int n_in,
                              void* d_out, int out_size)
{
    const float* obs = (const float*)d_in[0];
    const float* act = (const float*)d_in[1];
    const float* W1  = (const float*)d_in[2];
    const float* b1  = (const float*)d_in[3];
    const float* g1  = (const float*)d_in[4];
    const float* be1 = (const float*)d_in[5];
    const float* W2  = (const float*)d_in[6];
    const float* b2  = (const float*)d_in[7];
    const float* g2  = (const float*)d_in[8];
    const float* be2 = (const float*)d_in[9];
    const float* Wf  = (const float*)d_in[10];
    const float* bf  = (const float*)d_in[11];
    const float* Wb  = (const float*)d_in[12];
    const float* bb  = (const float*)d_in[13];
    const float* wx  = (const float*)d_in[14];
    const float* bx  = (const float*)d_in[15];
    const float* wp  = (const float*)d_in[16];
    const float* bp  = (const float*)d_in[17];
    const float* gp  = (const float*)d_in[18];
    const float* bep = (const float*)d_in[19];
    const float* W3  = (const float*)d_in[20];
    const float* b3  = (const float*)d_in[21];
    float* out = (float*)d_out;

    const int trunk_smem = (8192 + 6144 + 128 * 132 + 128 * 100 + 384) * 4;   // 177664 B
    const int lstm_smem  = (32768 + 2 * 64 * 68 + 1024) * 4;                  // 169984 B
    cudaFuncSetAttribute(trunk_kernel, cudaFuncAttributeMaxDynamicSharedMemorySize, trunk_smem);
    cudaFuncSetAttribute(lstm_kernel,  cudaFuncAttributeMaxDynamicSharedMemorySize, lstm_smem);

    trunk_kernel<<<2048, 256, trunk_smem>>>(obs, act, W1, b1, g1, be1, W2, b2, g2, be2);

    dim3 lg(64, 2);
    lstm_kernel<<<lg, 512, lstm_smem>>>(Wf, bf, Wb, bb, wx, bx, wp, bp);

    attn_kernel<<<1024, 256>>>(gp, bep, W3, b3, out);
}

// round 10
// speedup vs baseline: 3.6878x; 1.0274x over previous
#include <cuda_runtime.h>
#include <math.h>

#define Bn 4096
#define Tn 64

typedef unsigned long long ull;

// ---------------- device scratch (allocation-free rule: __device__ globals) ----
__device__ float g_x2[(size_t)Tn * Bn * 64];   // [t][b][64], tf32-rounded
__device__ float g_xs[(size_t)2 * Bn * Tn];    // [2B][T]
__device__ float g_ps[(size_t)2 * Bn * Tn];    // [2B][T]

__device__ __forceinline__ float tanha(float x) {
    float r; asm("tanh.approx.f32 %0, %1;" : "=f"(r) : "f"(x)); return r;
}
__device__ __forceinline__ float sigt(float x) {
    return fmaf(tanha(0.5f * x), 0.5f, 0.5f);
}
__device__ __forceinline__ unsigned cvt_tf32(float x) {
    unsigned r; asm("cvt.rna.tf32.f32 %0, %1;" : "=r"(r) : "f"(x)); return r;
}
__device__ __forceinline__ void mma_tf32(float* c, uint4 a, uint2 b) {
    asm volatile(
        "mma.sync.aligned.m16n8k8.row.col.f32.tf32.tf32.f32 "
        "{%0,%1,%2,%3}, {%4,%5,%6,%7}, {%8,%9}, {%0,%1,%2,%3};"
        : "+f"(c[0]), "+f"(c[1]), "+f"(c[2]), "+f"(c[3])
        : "r"(a.x), "r"(a.y), "r"(a.z), "r"(a.w), "r"(b.x), "r"(b.y));
}

// =====================================================================
// Kernel 1: MLP trunk via tf32 mma (single-pass). Unchanged from round 9.
// =====================================================================
__global__ void __launch_bounds__(256, 1) trunk_kernel(
    const float* __restrict__ obs, const float* __restrict__ act,
    const float* __restrict__ W1, const float* __restrict__ b1,
    const float* __restrict__ g1, const float* __restrict__ be1,
    const float* __restrict__ W2, const float* __restrict__ b2,
    const float* __restrict__ g2, const float* __restrict__ be2)
{
    extern __shared__ float sm[];
    ull*   B1  = (ull*)sm;                    // 4096 ull (32 KB)
    ull*   B2  = (ull*)(sm + 8192);           // 3072 ull (24 KB)
    float* sX  = sm + 8192 + 6144;            // 128 x 132
    float* sA2 = sX + 128 * 132;              // 128 x 100
    float* sP  = sA2 + 128 * 100;             // 384 params

    const int tid = threadIdx.x;
    const int l = tid & 31, w = tid >> 5;
    const int row0 = blockIdx.x * 128;

#pragma unroll
    for (int q = 0; q < 16; ++q) {
        int s = tid + q * 256;
        int lane = s & 31, kt = (s >> 5) & 15, nt = s >> 9;
        int k0 = kt * 8 + (lane & 3), n = nt * 8 + (lane >> 2);
        ull lo = cvt_tf32(W1[k0 * 64 + n]);
        ull hi = cvt_tf32(W1[(k0 + 4) * 64 + n]);
        B1[s] = (hi << 32) | lo;
    }
#pragma unroll
    for (int q = 0; q < 12; ++q) {
        int s = tid + q * 256;
        int lane = s & 31, r = s >> 5;
        int kt = r % 12, nt = r / 12;
        int k0 = kt * 8 + (lane & 3), n = nt * 8 + (lane >> 2);
        ull lo = cvt_tf32(W2[k0 * 64 + n]);
        ull hi = cvt_tf32(W2[(k0 + 4) * 64 + n]);
        B2[s] = (hi << 32) | lo;
    }
    if (tid < 64) {
        sP[tid]       = b1[tid];  sP[64 + tid]  = g1[tid];  sP[128 + tid] = be1[tid];
        sP[192 + tid] = b2[tid];  sP[256 + tid] = g2[tid];  sP[320 + tid] = be2[tid];
    }
#pragma unroll
    for (int q = 0; q < 16; ++q) {
        int f = tid + q * 256;
        int row = f >> 5, c4 = f & 31;
        *(float4*)(sX + row * 132 + c4 * 4) =
            *(const float4*)(obs + (size_t)(row0 + row) * 128 + c4 * 4);
    }
#pragma unroll
    for (int q = 0; q < 4; ++q) {
        int f = tid + q * 256;
        int row = f >> 3, c8 = f & 7;
        *(float4*)(sA2 + row * 100 + 64 + c8 * 4) =
            *(const float4*)(act + (size_t)(row0 + row) * 32 + c8 * 4);
    }
    __syncthreads();

    const int q4 = l & 3, rlq = l >> 2;
    const int ar = w * 16 + rlq;

    float acc[8][4];
#pragma unroll
    for (int nt = 0; nt < 8; ++nt) {
        int c0 = nt * 8 + 2 * q4;
        acc[nt][0] = sP[c0]; acc[nt][1] = sP[c0 + 1];
        acc[nt][2] = sP[c0]; acc[nt][3] = sP[c0 + 1];
    }
#pragma unroll
    for (int kt = 0; kt < 16; ++kt) {
        int c = kt * 8 + q4;
        uint4 a;
        a.x = cvt_tf32(sX[ar * 132 + c]);
        a.y = cvt_tf32(sX[(ar + 8) * 132 + c]);
        a.z = cvt_tf32(sX[ar * 132 + c + 4]);
        a.w = cvt_tf32(sX[(ar + 8) * 132 + c + 4]);
#pragma unroll
        for (int nt = 0; nt < 8; ++nt) {
            ull v = B1[(nt * 16 + kt) * 32 + l];
            uint2 b; b.x = (unsigned)v; b.y = (unsigned)(v >> 32);
            mma_tf32(acc[nt], a, b);
        }
    }

    {
        float sl = 0.f, ql = 0.f, sh = 0.f, qh = 0.f;
#pragma unroll
        for (int nt = 0; nt < 8; ++nt) {
            sl += acc[nt][0] + acc[nt][1];
            ql += acc[nt][0] * acc[nt][0] + acc[nt][1] * acc[nt][1];
            sh += acc[nt][2] + acc[nt][3];
            qh += acc[nt][2] * acc[nt][2] + acc[nt][3] * acc[nt][3];
        }
#pragma unroll
        for (int o = 1; o <= 2; o <<= 1) {
            sl += __shfl_xor_sync(0xffffffffu, sl, o);
            ql += __shfl_xor_sync(0xffffffffu, ql, o);
            sh += __shfl_xor_sync(0xffffffffu, sh, o);
            qh += __shfl_xor_sync(0xffffffffu, qh, o);
        }
        float ml = sl * 0.015625f, vl = ql * 0.015625f - ml * ml;
        float mh = sh * 0.015625f, vh = qh * 0.015625f - mh * mh;
        float il = rsqrtf(vl + 1e-12f), ih = rsqrtf(vh + 1e-12f);
#pragma unroll
        for (int nt = 0; nt < 8; ++nt) {
            int c0 = nt * 8 + 2 * q4;
            float g0 = sP[64 + c0], g1v = sP[64 + c0 + 1];
            float e0 = sP[128 + c0], e1v = sP[128 + c0 + 1];
            float2 zl, zh;
            zl.x = fmaxf((acc[nt][0] - ml) * il * g0  + e0,  0.f);
            zl.y = fmaxf((acc[nt][1] - ml) * il * g1v + e1v, 0.f);
            zh.x = fmaxf((acc[nt][2] - mh) * ih * g0  + e0,  0.f);
            zh.y = fmaxf((acc[nt][3] - mh) * ih * g1v + e1v, 0.f);
            *(float2*)(sA2 + ar * 100 + c0)       = zl;
            *(float2*)(sA2 + (ar + 8) * 100 + c0) = zh;
        }
    }
    __syncthreads();

    float a2[8][4];
#pragma unroll
    for (int nt = 0; nt < 8; ++nt) {
        int c0 = nt * 8 + 2 * q4;
        a2[nt][0] = sP[192 + c0]; a2[nt][1] = sP[192 + c0 + 1];
        a2[nt][2] = sP[192 + c0]; a2[nt][3] = sP[192 + c0 + 1];
    }
#pragma unroll
    for (int kt = 0; kt < 12; ++kt) {
        int c = kt * 8 + q4;
        uint4 a;
        a.x = cvt_tf32(sA2[ar * 100 + c]);
        a.y = cvt_tf32(sA2[(ar + 8) * 100 + c]);
        a.z = cvt_tf32(sA2[ar * 100 + c + 4]);
        a.w = cvt_tf32(sA2[(ar + 8) * 100 + c + 4]);
#pragma unroll
        for (int nt = 0; nt < 8; ++nt) {
            ull v = B2[(nt * 12 + kt) * 32 + l];
            uint2 b; b.x = (unsigned)v; b.y = (unsigned)(v >> 32);
            mma_tf32(a2[nt], a, b);
        }
    }

    {
        float sl = 0.f, ql = 0.f, sh = 0.f, qh = 0.f;
#pragma unroll
        for (int nt = 0; nt < 8; ++nt) {
            sl += a2[nt][0] + a2[nt][1];
            ql += a2[nt][0] * a2[nt][0] + a2[nt][1] * a2[nt][1];
            sh += a2[nt][2] + a2[nt][3];
            qh += a2[nt][2] * a2[nt][2] + a2[nt][3] * a2[nt][3];
        }
#pragma unroll
        for (int o = 1; o <= 2; o <<= 1) {
            sl += __shfl_xor_sync(0xffffffffu, sl, o);
            ql += __shfl_xor_sync(0xffffffffu, ql, o);
            sh += __shfl_xor_sync(0xffffffffu, sh, o);
            qh += __shfl_xor_sync(0xffffffffu, qh, o);
        }
        float ml = sl * 0.015625f, vl = ql * 0.015625f - ml * ml;
        float mh = sh * 0.015625f, vh = qh * 0.015625f - mh * mh;
        float il = rsqrtf(vl + 1e-12f), ih = rsqrtf(vh + 1e-12f);
#pragma unroll
        for (int nt = 0; nt < 8; ++nt) {
            int c0 = nt * 8 + 2 * q4;
            float g0 = sP[256 + c0], g1v = sP[256 + c0 + 1];
            float e0 = sP[320 + c0], e1v = sP[320 + c0 + 1];
            float2 zl, zh;
            zl.x = __uint_as_float(cvt_tf32(fmaxf((a2[nt][0] - ml) * il * g0  + e0,  0.f)));
            zl.y = __uint_as_float(cvt_tf32(fmaxf((a2[nt][1] - ml) * il * g1v + e1v, 0.f)));
            zh.x = __uint_as_float(cvt_tf32(fmaxf((a2[nt][2] - mh) * ih * g0  + e0,  0.f)));
            zh.y = __uint_as_float(cvt_tf32(fmaxf((a2[nt][3] - mh) * ih * g1v + e1v, 0.f)));
            *(float2*)(sX + ar * 132 + c0)       = zl;
            *(float2*)(sX + (ar + 8) * 132 + c0) = zh;
        }
    }
    __syncwarp();
#pragma unroll
    for (int j = 0; j < 8; ++j) {
        int row = w * 16 + 2 * j + (l >> 4);
        int c = (l & 15) * 4;
        float4 v = *(const float4*)(sX + row * 132 + c);
        int t = row & 63;
        int b = (blockIdx.x << 1) + (row >> 6);
        *(float4*)(g_x2 + ((size_t)t * Bn + b) * 64 + c) = v;
    }
}

// =====================================================================
// Kernel 2: bidirectional LSTM via tf32 mma. grid (64, 2), 512 threads.
// ONE __syncthreads per step: double-buffered xb/hF/red.
// h kept in mma A-fragment layout (hF) -> 1 LDS.128 per h-operand.
// =====================================================================
__global__ void __launch_bounds__(512, 1) lstm_kernel(
    const float* __restrict__ Wf, const float* __restrict__ bfv,
    const float* __restrict__ Wb, const float* __restrict__ bbv,
    const float* __restrict__ wx, const float* __restrict__ bx,
    const float* __restrict__ wp, const float* __restrict__ bp)
{
    extern __shared__ float sm[];
    float* wFrag = sm;                 // 32768 floats (128KB)
    float* xb    = wFrag + 32768;      // 2 x (64 x 68) = 8704
    float* hF    = xb + 8704;          // 2 x 4096 (fragment layout)
    float* red   = hF + 8192;          // 2 x 1024

    const int dir = blockIdx.y;
    const int b0  = blockIdx.x * 64;
    const float* W    = dir ? Wb  : Wf;
    const float* bias = dir ? bbv : bfv;
    const int tid = threadIdx.x;
    const int l = tid & 31, w = tid >> 5;
    const int wu = w & 7, wm = w >> 3;

    // ---- stage W into B-fragment layout with gate-unit permutation ----
    for (int q = 0; q < 32; ++q) {
        int s = tid + q * 512;
        int lane = s & 31, kt = (s >> 5) & 15, g = (s >> 9) & 3, ww = s >> 11;
        int k0 = kt * 8 + (lane & 3);
        int n  = g * 64 + 8 * ww + (lane >> 2);
        wFrag[s * 2]     = __uint_as_float(cvt_tf32(W[k0 * 256 + n]));
        wFrag[s * 2 + 1] = __uint_as_float(cvt_tf32(W[(k0 + 4) * 256 + n]));
    }
    // ---- init buffers (parity 0): x(t0) into xb[0], zero hF[0] ----
    {
        int t0 = dir ? 63 : 0;
        const float4* src = (const float4*)(g_x2 + ((size_t)t0 * Bn + b0) * 64);
#pragma unroll
        for (int q = 0; q < 2; ++q) {
            int f = tid + q * 512;
            int sq = f >> 4, c4 = f & 15;
            *(float4*)(xb + sq * 68 + c4 * 4) = src[f];
            ((float4*)hF)[f] = make_float4(0.f, 0.f, 0.f, 0.f);
        }
    }

    const int u0 = 8 * wu + 2 * (l & 3);
    float bia[4][2];
#pragma unroll
    for (int g = 0; g < 4; ++g) {
        bia[g][0] = bias[g * 64 + u0];
        bia[g][1] = bias[g * 64 + u0 + 1];
    }
    const float wxu0 = wx[u0], wxu1 = wx[u0 + 1];
    const float wpu0 = wp[u0], wpu1 = wp[u0 + 1];
    const float bxs = bx[0], bps = bp[0];

    float cst[2][4];
#pragma unroll
    for (int mt = 0; mt < 2; ++mt)
#pragma unroll
        for (int s = 0; s < 4; ++s) cst[mt][s] = 0.f;

    const ull* wB = (const ull*)wFrag;
    const int q4 = l & 3, rlq = l >> 2;
    // h fragment write base offsets (per thread; mt-dependent part added inline)
    const int hoff = (wu * 32 + rlq * 4 + (u0 & 3)) * 4 + 2 * ((u0 >> 2) & 1);

    for (int st = 0; st < 64; ++st) {
        const int t = dir ? (63 - st) : st;
        const int p = st & 1;
        __syncthreads();   // single barrier per step

        // drain xs/ps of the previous step
        if (st > 0 && tid < 128) {
            int which = tid >> 6, seq = tid & 63;
            const float* rb = red + ((st - 1) & 1) * 1024 + which * 512 + seq;
            float v = rb[0] + rb[64] + rb[128] + rb[192]
                    + rb[256] + rb[320] + rb[384] + rb[448];
            v += which ? bps : bxs;
            int tprev = dir ? (64 - st) : (st - 1);
            float* gdst = which ? g_ps : g_xs;
            gdst[((size_t)dir * Bn + b0 + seq) * Tn + tprev] = v;
        }

        // prefetch x(t+1)
        float4 xpf0, xpf1;
        if (st < 63) {
            int t2 = dir ? (62 - st) : (st + 1);
            const float4* src = (const float4*)(g_x2 + ((size_t)t2 * Bn + b0) * 64);
            xpf0 = src[tid]; xpf1 = src[tid + 512];
        }

        const float* xbp = xb + p * 4352;
        const float* hFp = hF + p * 4096;

        float acc[2][4][4];
#pragma unroll
        for (int mt = 0; mt < 2; ++mt)
#pragma unroll
            for (int g = 0; g < 4; ++g) {
                acc[mt][g][0] = bia[g][0]; acc[mt][g][1] = bia[g][1];
                acc[mt][g][2] = bia[g][0]; acc[mt][g][3] = bia[g][1];
            }

        // x-part (kt 0..7): row-major xb, 4x LDS.32
#pragma unroll
        for (int kt = 0; kt < 8; ++kt) {
            uint2 b[4];
#pragma unroll
            for (int g = 0; g < 4; ++g) {
                ull v = wB[(size_t)(((wu * 4 + g) * 16 + kt) * 32 + l)];
                b[g].x = (unsigned)(v & 0xffffffffu);
                b[g].y = (unsigned)(v >> 32);
            }
            int c = kt * 8 + q4;
#pragma unroll
            for (int mt = 0; mt < 2; ++mt) {
                int r = (wm * 2 + mt) * 16 + rlq;
                uint4 a;
                a.x = __float_as_uint(xbp[r * 68 + c]);
                a.y = __float_as_uint(xbp[(r + 8) * 68 + c]);
                a.z = __float_as_uint(xbp[r * 68 + c + 4]);
                a.w = __float_as_uint(xbp[(r + 8) * 68 + c + 4]);
#pragma unroll
                for (int g = 0; g < 4; ++g) mma_tf32(acc[mt][g], a, b[g]);
            }
        }
        // h-part (kt 8..15): fragment layout hF, 1x LDS.128
#pragma unroll
        for (int kt = 8; kt < 16; ++kt) {
            uint2 b[4];
#pragma unroll
            for (int g = 0; g < 4; ++g) {
                ull v = wB[(size_t)(((wu * 4 + g) * 16 + kt) * 32 + l)];
                b[g].x = (unsigned)(v & 0xffffffffu);
                b[g].y = (unsigned)(v >> 32);
            }
#pragma unroll
            for (int mt = 0; mt < 2; ++mt) {
                int mtg = wm * 2 + mt;
                uint4 a = *(const uint4*)(hFp + ((mtg * 8 + (kt - 8)) * 32 + l) * 4);
#pragma unroll
                for (int g = 0; g < 4; ++g) mma_tf32(acc[mt][g], a, b[g]);
            }
        }

        // ---- epilogue: gates, c/h update ----
        float hreg[2][4];
        float px[2][2], pq[2][2];
#pragma unroll
        for (int mt = 0; mt < 2; ++mt) {
#pragma unroll
            for (int s = 0; s < 4; ++s) {
                float iv = acc[mt][0][s], jv = acc[mt][1][s];
                float fv = acc[mt][2][s], ov = acc[mt][3][s];
                float cn = cst[mt][s] * sigt(fv + 1.f) + sigt(iv) * tanha(jv);
                cst[mt][s] = cn;
                hreg[mt][s] = tanha(cn) * sigt(ov);
            }
            px[mt][0] = hreg[mt][0] * wxu0 + hreg[mt][1] * wxu1;
            px[mt][1] = hreg[mt][2] * wxu0 + hreg[mt][3] * wxu1;
            pq[mt][0] = hreg[mt][0] * wpu0 + hreg[mt][1] * wpu1;
            pq[mt][1] = hreg[mt][2] * wpu0 + hreg[mt][3] * wpu1;
        }
#pragma unroll
        for (int o = 1; o <= 2; o <<= 1) {
#pragma unroll
            for (int mt = 0; mt < 2; ++mt) {
                px[mt][0] += __shfl_xor_sync(0xffffffffu, px[mt][0], o);
                px[mt][1] += __shfl_xor_sync(0xffffffffu, px[mt][1], o);
                pq[mt][0] += __shfl_xor_sync(0xffffffffu, pq[mt][0], o);
                pq[mt][1] += __shfl_xor_sync(0xffffffffu, pq[mt][1], o);
            }
        }
        // partial xs/ps -> red[p]
        if ((l & 3) == 0) {
            float* rp = red + p * 1024;
#pragma unroll
            for (int mt = 0; mt < 2; ++mt) {
                int seqlo = (wm * 2 + mt) * 16 + (l >> 2);
                rp[wu * 64 + seqlo]           = px[mt][0];
                rp[wu * 64 + seqlo + 8]       = px[mt][1];
                rp[512 + wu * 64 + seqlo]     = pq[mt][0];
                rp[512 + wu * 64 + seqlo + 8] = pq[mt][1];
            }
        }
        // new h (tf32) -> hF[p^1] in fragment layout (two STS.64)
        {
            float* hDst = hF + (p ^ 1) * 4096;
#pragma unroll
            for (int mt = 0; mt < 2; ++mt) {
                int mtg = wm * 2 + mt;
                float* d = hDst + mtg * 1024 + hoff;
                float2 v0, v1;
                v0.x = __uint_as_float(cvt_tf32(hreg[mt][0]));   // (rlo, u0)
                v0.y = __uint_as_float(cvt_tf32(hreg[mt][2]));   // (rhi, u0)
                v1.x = __uint_as_float(cvt_tf32(hreg[mt][1]));   // (rlo, u0+1)
                v1.y = __uint_as_float(cvt_tf32(hreg[mt][3]));   // (rhi, u0+1)
                *(float2*)(d)     = v0;
                *(float2*)(d + 4) = v1;
            }
        }
        // prefetched x -> xb[p^1]
        if (st < 63) {
            float* xd = xb + (p ^ 1) * 4352;
            int f0 = tid, f1 = tid + 512;
            *(float4*)(xd + (f0 >> 4) * 68 + (f0 & 15) * 4) = xpf0;
            *(float4*)(xd + (f1 >> 4) * 68 + (f1 & 15) * 4) = xpf1;
        }
    }

    // drain final step's xs/ps
    __syncthreads();
    if (tid < 128) {
        int which = tid >> 6, seq = tid & 63;
        const float* rb = red + 1024 + which * 512 + seq;   // parity of st=63 is 1
        float v = rb[0] + rb[64] + rb[128] + rb[192]
                + rb[256] + rb[320] + rb[384] + rb[448];
        v += which ? bps : bxs;
        int tlast = dir ? 0 : 63;
        float* gdst = which ? g_ps : g_xs;
        gdst[((size_t)dir * Bn + b0 + seq) * Tn + tlast] = v;
    }
}

// =====================================================================
// Kernel 3: attention head. warp per sequence; 8 seqs / block.
// =====================================================================
__global__ void __launch_bounds__(256) attn_kernel(
    const float* __restrict__ gp, const float* __restrict__ bep,
    const float* __restrict__ W3, const float* __restrict__ b3,
    float* __restrict__ out)
{
    __shared__ float sW3[4096];
    __shared__ float sb3[64];
    const int tid = threadIdx.x;
    for (int i = tid; i < 1024; i += 256) ((float4*)sW3)[i] = ((const float4*)W3)[i];
    if (tid < 64) sb3[tid] = b3[tid];
    __syncthreads();

    const int lane = tid & 31, w = tid >> 5;
    const int seq = blockIdx.x * 8 + w;

    const float* psr = g_ps + (size_t)seq * Tn;
    float v0 = psr[lane], v1 = psr[lane + 32];
    float s = v0 + v1, q = v0 * v0 + v1 * v1;
#pragma unroll
    for (int o = 16; o; o >>= 1) {
        s += __shfl_xor_sync(0xffffffffu, s, o);
        q += __shfl_xor_sync(0xffffffffu, q, o);
    }
    float m = s * 0.015625f;
    float var = q * 0.015625f - m * m;
    float rs = rsqrtf(var + 1e-12f);
    float p0 = fmaxf((v0 - m) * rs * gp[lane]      + bep[lane],      0.f);
    float p1 = fmaxf((v1 - m) * rs * gp[lane + 32] + bep[lane + 32], 0.f);

    float l0 = sb3[lane], l1 = sb3[lane + 32];
#pragma unroll 8
    for (int tt = 0; tt < 32; ++tt) {
        float pv = __shfl_sync(0xffffffffu, p0, tt);
        l0 += pv * sW3[tt * 64 + lane];
        l1 += pv * sW3[tt * 64 + lane + 32];
    }
#pragma unroll 8
    for (int tt = 0; tt < 32; ++tt) {
        float pv = __shfl_sync(0xffffffffu, p1, tt);
        l0 += pv * sW3[(32 + tt) * 64 + lane];
        l1 += pv * sW3[(32 + tt) * 64 + lane + 32];
    }

    float mx = fmaxf(l0, l1);
#pragma unroll
    for (int o = 16; o; o >>= 1) mx = fmaxf(mx, __shfl_xor_sync(0xffffffffu, mx, o));
    float e0 = __expf(l0 - mx), e1 = __expf(l1 - mx);
    float se = e0 + e1;
    const float* xsr = g_xs + (size_t)seq * Tn;
    float rsum = e0 * xsr[lane] + e1 * xsr[lane + 32];
#pragma unroll
    for (int o = 16; o; o >>= 1) {
        se   += __shfl_xor_sync(0xffffffffu, se, o);
        rsum += __shfl_xor_sync(0xffffffffu, rsum, o);
    }
    if (lane == 0) out[seq] = rsum / se;
}

// =====================================================================
extern "C" void kernel_launch(void* const* d_in, const int* in_sizes, int n_in,
                              void* d_out, int out_size)
{
    const float* obs = (const float*)d_in[0];
    const float* act = (const float*)d_in[1];
    const float* W1  = (const float*)d_in[2];
    const float* b1  = (const float*)d_in[3];
    const float* g1  = (const float*)d_in[4];
    const float* be1 = (const float*)d_in[5];
    const float* W2  = (const float*)d_in[6];
    const float* b2  = (const float*)d_in[7];
    const float* g2  = (const float*)d_in[8];
    const float* be2 = (const float*)d_in[9];
    const float* Wf  = (const float*)d_in[10];
    const float* bf  = (const float*)d_in[11];
    const float* Wb  = (const float*)d_in[12];
    const float* bb  = (const float*)d_in[13];
    const float* wx  = (const float*)d_in[14];
    const float* bx  = (const float*)d_in[15];
    const float* wp  = (const float*)d_in[16];
    const float* bp  = (const float*)d_in[17];
    const float* gp  = (const float*)d_in[18];
    const float* bep = (const float*)d_in[19];
    const float* W3  = (const float*)d_in[20];
    const float* b3  = (const float*)d_in[21];
    float* out = (float*)d_out;

    const int trunk_smem = (8192 + 6144 + 128 * 132 + 128 * 100 + 384) * 4;   // 177664 B
    const int lstm_smem  = (32768 + 8704 + 8192 + 2048) * 4;                  // 206848 B
    cudaFuncSetAttribute(trunk_kernel, cudaFuncAttributeMaxDynamicSharedMemorySize, trunk_smem);
    cudaFuncSetAttribute(lstm_kernel,  cudaFuncAttributeMaxDynamicSharedMemorySize, lstm_smem);

    trunk_kernel<<<2048, 256, trunk_smem>>>(obs, act, W1, b1, g1, be1, W2, b2, g2, be2);

    dim3 lg(64, 2);
    lstm_kernel<<<lg, 512, lstm_smem>>>(Wf, bf, Wb, bb, wx, bx, wp, bp);

    attn_kernel<<<1024, 256>>>(gp, bep, W3, b3, out);
}

// round 11
// speedup vs baseline: 5.7998x; 1.5727x over previous
#include <cuda_runtime.h>
#include <cuda_fp16.h>
#include <math.h>

#define Bn 4096
#define Tn 64

typedef unsigned long long ull;

// ---------------- device scratch ----------------
__device__ __half g_x2h[(size_t)Tn * Bn * 64];  // [t][b][64], fp16
__device__ float g_xs[(size_t)2 * Bn * Tn];     // [2B][T]
__device__ float g_ps[(size_t)2 * Bn * Tn];     // [2B][T]

__device__ __forceinline__ float tanha(float x) {
    float r; asm("tanh.approx.f32 %0, %1;" : "=f"(r) : "f"(x)); return r;
}
__device__ __forceinline__ float sigt(float x) {
    return fmaf(tanha(0.5f * x), 0.5f, 0.5f);
}
__device__ __forceinline__ unsigned h2u(float lo, float hi) {
    __half2 h = __floats2half2_rn(lo, hi);
    return *(unsigned*)&h;
}
__device__ __forceinline__ void mma_f16(float* c, uint4 a, uint2 b) {
    asm volatile(
        "mma.sync.aligned.m16n8k16.row.col.f32.f16.f16.f32 "
        "{%0,%1,%2,%3}, {%4,%5,%6,%7}, {%8,%9}, {%0,%1,%2,%3};"
        : "+f"(c[0]), "+f"(c[1]), "+f"(c[2]), "+f"(c[3])
        : "r"(a.x), "r"(a.y), "r"(a.z), "r"(a.w), "r"(b.x), "r"(b.y));
}

#define XP 136   // trunk sX pad (halves per row)
#define AP 104   // trunk sA2 pad
#define HP 88    // lstm x/h pad

// =====================================================================
// Kernel 1: MLP trunk via fp16 mma (fp32 accum). 256 thr, 2 CTAs/SM.
// =====================================================================
__global__ void __launch_bounds__(256, 2) trunk_kernel(
    const float* __restrict__ obs, const float* __restrict__ act,
    const float* __restrict__ W1, const float* __restrict__ b1,
    const float* __restrict__ g1, const float* __restrict__ be1,
    const float* __restrict__ W2, const float* __restrict__ b2,
    const float* __restrict__ g2, const float* __restrict__ be2)
{
    extern __shared__ char smc[];
    uint2*  B1   = (uint2*)smc;                      // 2048 uint2 (16 KB)
    uint2*  B2   = (uint2*)(smc + 16384);            // 1536 uint2 (12 KB)
    __half* sX   = (__half*)(smc + 28672);           // 128 x XP
    __half* sA2  = (__half*)(smc + 28672 + 128*XP*2);// 128 x AP
    float*  sP   = (float*)(smc + 28672 + 128*XP*2 + 128*AP*2); // 384

    const int tid = threadIdx.x;
    const int l = tid & 31, w = tid >> 5;
    const int row0 = blockIdx.x * 128;

    // ---- W1 -> fp16 B-frags [nt8][kt8][lane32] ----
#pragma unroll
    for (int q = 0; q < 8; ++q) {
        int s = tid + q * 256;
        int l2 = s & 31, kt = (s >> 5) & 7, nt = s >> 8;
        int k0 = kt * 16 + 2 * (l2 & 3), n = nt * 8 + (l2 >> 2);
        uint2 b;
        b.x = h2u(W1[k0 * 64 + n],       W1[(k0 + 1) * 64 + n]);
        b.y = h2u(W1[(k0 + 8) * 64 + n], W1[(k0 + 9) * 64 + n]);
        B1[s] = b;
    }
    // ---- W2 -> fp16 B-frags [nt8][kt6][lane32] ----
#pragma unroll
    for (int q = 0; q < 6; ++q) {
        int s = tid + q * 256;
        int l2 = s & 31, r = s >> 5;
        int kt = r % 6, nt = r / 6;
        int k0 = kt * 16 + 2 * (l2 & 3), n = nt * 8 + (l2 >> 2);
        uint2 b;
        b.x = h2u(W2[k0 * 64 + n],       W2[(k0 + 1) * 64 + n]);
        b.y = h2u(W2[(k0 + 8) * 64 + n], W2[(k0 + 9) * 64 + n]);
        B2[s] = b;
    }
    if (tid < 64) {
        sP[tid]       = b1[tid];  sP[64 + tid]  = g1[tid];  sP[128 + tid] = be1[tid];
        sP[192 + tid] = b2[tid];  sP[256 + tid] = g2[tid];  sP[320 + tid] = be2[tid];
    }
    // ---- obs -> sX (half) ----
#pragma unroll
    for (int q = 0; q < 16; ++q) {
        int f = tid + q * 256;
        int row = f >> 5, c4 = f & 31;
        float4 v = *(const float4*)(obs + (size_t)(row0 + row) * 128 + c4 * 4);
        uint2 hv; hv.x = h2u(v.x, v.y); hv.y = h2u(v.z, v.w);
        *(uint2*)(sX + row * XP + c4 * 4) = hv;
    }
    // ---- action -> sA2 cols 64..95 (half) ----
#pragma unroll
    for (int q = 0; q < 4; ++q) {
        int f = tid + q * 256;
        int row = f >> 3, c8 = f & 7;
        float4 v = *(const float4*)(act + (size_t)(row0 + row) * 32 + c8 * 4);
        uint2 hv; hv.x = h2u(v.x, v.y); hv.y = h2u(v.z, v.w);
        *(uint2*)(sA2 + row * AP + 64 + c8 * 4) = hv;
    }
    __syncthreads();

    const int q4 = l & 3, rlq = l >> 2;
    const int ar = w * 16 + rlq;

    // ---- GEMM1: K=128 -> 8 kt ----
    float acc[8][4];
#pragma unroll
    for (int nt = 0; nt < 8; ++nt) {
        int c0 = nt * 8 + 2 * q4;
        acc[nt][0] = sP[c0]; acc[nt][1] = sP[c0 + 1];
        acc[nt][2] = sP[c0]; acc[nt][3] = sP[c0 + 1];
    }
#pragma unroll
    for (int kt = 0; kt < 8; ++kt) {
        int cb = kt * 16 + 2 * q4;
        uint4 a;
        a.x = *(const unsigned*)(sX + ar * XP + cb);
        a.y = *(const unsigned*)(sX + (ar + 8) * XP + cb);
        a.z = *(const unsigned*)(sX + ar * XP + cb + 8);
        a.w = *(const unsigned*)(sX + (ar + 8) * XP + cb + 8);
#pragma unroll
        for (int nt = 0; nt < 8; ++nt)
            mma_f16(acc[nt], a, B1[(nt * 8 + kt) * 32 + l]);
    }

    // ---- LN1 + relu -> sA2 (half) ----
    {
        float sl = 0.f, ql = 0.f, sh = 0.f, qh = 0.f;
#pragma unroll
        for (int nt = 0; nt < 8; ++nt) {
            sl += acc[nt][0] + acc[nt][1];
            ql += acc[nt][0] * acc[nt][0] + acc[nt][1] * acc[nt][1];
            sh += acc[nt][2] + acc[nt][3];
            qh += acc[nt][2] * acc[nt][2] + acc[nt][3] * acc[nt][3];
        }
#pragma unroll
        for (int o = 1; o <= 2; o <<= 1) {
            sl += __shfl_xor_sync(0xffffffffu, sl, o);
            ql += __shfl_xor_sync(0xffffffffu, ql, o);
            sh += __shfl_xor_sync(0xffffffffu, sh, o);
            qh += __shfl_xor_sync(0xffffffffu, qh, o);
        }
        float ml = sl * 0.015625f, vl = ql * 0.015625f - ml * ml;
        float mh = sh * 0.015625f, vh = qh * 0.015625f - mh * mh;
        float il = rsqrtf(vl + 1e-12f), ih = rsqrtf(vh + 1e-12f);
#pragma unroll
        for (int nt = 0; nt < 8; ++nt) {
            int c0 = nt * 8 + 2 * q4;
            float g0 = sP[64 + c0], g1v = sP[64 + c0 + 1];
            float e0 = sP[128 + c0], e1v = sP[128 + c0 + 1];
            float zl0 = fmaxf((acc[nt][0] - ml) * il * g0  + e0,  0.f);
            float zl1 = fmaxf((acc[nt][1] - ml) * il * g1v + e1v, 0.f);
            float zh0 = fmaxf((acc[nt][2] - mh) * ih * g0  + e0,  0.f);
            float zh1 = fmaxf((acc[nt][3] - mh) * ih * g1v + e1v, 0.f);
            *(unsigned*)(sA2 + ar * AP + c0)       = h2u(zl0, zl1);
            *(unsigned*)(sA2 + (ar + 8) * AP + c0) = h2u(zh0, zh1);
        }
    }
    __syncthreads();

    // ---- GEMM2: K=96 -> 6 kt ----
    float a2[8][4];
#pragma unroll
    for (int nt = 0; nt < 8; ++nt) {
        int c0 = nt * 8 + 2 * q4;
        a2[nt][0] = sP[192 + c0]; a2[nt][1] = sP[192 + c0 + 1];
        a2[nt][2] = sP[192 + c0]; a2[nt][3] = sP[192 + c0 + 1];
    }
#pragma unroll
    for (int kt = 0; kt < 6; ++kt) {
        int cb = kt * 16 + 2 * q4;
        uint4 a;
        a.x = *(const unsigned*)(sA2 + ar * AP + cb);
        a.y = *(const unsigned*)(sA2 + (ar + 8) * AP + cb);
        a.z = *(const unsigned*)(sA2 + ar * AP + cb + 8);
        a.w = *(const unsigned*)(sA2 + (ar + 8) * AP + cb + 8);
#pragma unroll
        for (int nt = 0; nt < 8; ++nt)
            mma_f16(a2[nt], a, B2[(nt * 6 + kt) * 32 + l]);
    }

    // ---- LN2 + relu + fp16 -> stage sX -> coalesced STG ----
    {
        float sl = 0.f, ql = 0.f, sh = 0.f, qh = 0.f;
#pragma unroll
        for (int nt = 0; nt < 8; ++nt) {
            sl += a2[nt][0] + a2[nt][1];
            ql += a2[nt][0] * a2[nt][0] + a2[nt][1] * a2[nt][1];
            sh += a2[nt][2] + a2[nt][3];
            qh += a2[nt][2] * a2[nt][2] + a2[nt][3] * a2[nt][3];
        }
#pragma unroll
        for (int o = 1; o <= 2; o <<= 1) {
            sl += __shfl_xor_sync(0xffffffffu, sl, o);
            ql += __shfl_xor_sync(0xffffffffu, ql, o);
            sh += __shfl_xor_sync(0xffffffffu, sh, o);
            qh += __shfl_xor_sync(0xffffffffu, qh, o);
        }
        float ml = sl * 0.015625f, vl = ql * 0.015625f - ml * ml;
        float mh = sh * 0.015625f, vh = qh * 0.015625f - mh * mh;
        float il = rsqrtf(vl + 1e-12f), ih = rsqrtf(vh + 1e-12f);
#pragma unroll
        for (int nt = 0; nt < 8; ++nt) {
            int c0 = nt * 8 + 2 * q4;
            float g0 = sP[256 + c0], g1v = sP[256 + c0 + 1];
            float e0 = sP[320 + c0], e1v = sP[320 + c0 + 1];
            float zl0 = fmaxf((a2[nt][0] - ml) * il * g0  + e0,  0.f);
            float zl1 = fmaxf((a2[nt][1] - ml) * il * g1v + e1v, 0.f);
            float zh0 = fmaxf((a2[nt][2] - mh) * ih * g0  + e0,  0.f);
            float zh1 = fmaxf((a2[nt][3] - mh) * ih * g1v + e1v, 0.f);
            *(unsigned*)(sX + ar * XP + c0)       = h2u(zl0, zl1);
            *(unsigned*)(sX + (ar + 8) * XP + c0) = h2u(zh0, zh1);
        }
    }
    __syncwarp();
#pragma unroll
    for (int j = 0; j < 4; ++j) {
        int row = w * 16 + 4 * j + (l >> 3);   // warp-local rows
        int c8 = l & 7;
        uint4 v = *(const uint4*)(sX + row * XP + c8 * 8);
        int grow = row0 + row;
        int t = grow & 63;
        int b = (blockIdx.x << 1) + (row >> 6);
        *(uint4*)(g_x2h + ((size_t)t * Bn + b) * 64 + c8 * 8) = v;
    }
}

// =====================================================================
// Kernel 2: bidirectional LSTM via fp16 mma. grid (64,2), 512 threads.
// Single sync/step, double-buffered xb/hT/red. All operands fp16 in smem.
// =====================================================================
__global__ void __launch_bounds__(512, 1) lstm_kernel(
    const float* __restrict__ Wf, const float* __restrict__ bfv,
    const float* __restrict__ Wb, const float* __restrict__ bbv,
    const float* __restrict__ wx, const float* __restrict__ bx,
    const float* __restrict__ wp, const float* __restrict__ bp)
{
    extern __shared__ char smc[];
    uint2*  wF  = (uint2*)smc;                      // 8192 uint2 (64 KB)
    __half* xb  = (__half*)(smc + 65536);           // 2 x (64 x HP)
    __half* hT  = (__half*)(smc + 65536 + 22528);   // 2 x (64 x HP)
    float*  red = (float*)(smc + 65536 + 45056);    // 2 x 1024

    const int dir = blockIdx.y;
    const int b0  = blockIdx.x * 64;
    const float* W    = dir ? Wb  : Wf;
    const float* bias = dir ? bbv : bfv;
    const int tid = threadIdx.x;
    const int l = tid & 31, w = tid >> 5;
    const int wu = w & 7, wm = w >> 3;

    // ---- W -> fp16 B-frags [wu8][g4][kt8][lane32], gate-unit permuted ----
#pragma unroll
    for (int q = 0; q < 16; ++q) {
        int s = tid + q * 512;
        int l2 = s & 31, kt = (s >> 5) & 7, g = (s >> 8) & 3, ww = s >> 10;
        int k0 = kt * 16 + 2 * (l2 & 3);
        int n  = g * 64 + 8 * ww + (l2 >> 2);
        uint2 b;
        b.x = h2u(W[k0 * 256 + n],       W[(k0 + 1) * 256 + n]);
        b.y = h2u(W[(k0 + 8) * 256 + n], W[(k0 + 9) * 256 + n]);
        wF[s] = b;
    }
    // ---- init: x(t0) -> xb[0]; zero hT[0] ----
    {
        int t0 = dir ? 63 : 0;
        const uint4* src = (const uint4*)(g_x2h + ((size_t)t0 * Bn + b0) * 64);
        int row = tid >> 3, c8 = tid & 7;
        *(uint4*)(xb + row * HP + c8 * 8) = src[tid];
        uint4 z = make_uint4(0, 0, 0, 0);
        for (int i = tid; i < 704; i += 512) ((uint4*)hT)[i] = z;
    }

    const int u0 = 8 * wu + 2 * (l & 3);
    float bia[4][2];
#pragma unroll
    for (int g = 0; g < 4; ++g) {
        bia[g][0] = bias[g * 64 + u0];
        bia[g][1] = bias[g * 64 + u0 + 1];
    }
    const float wxu0 = wx[u0], wxu1 = wx[u0 + 1];
    const float wpu0 = wp[u0], wpu1 = wp[u0 + 1];
    const float bxs = bx[0], bps = bp[0];

    float cst[2][4];
#pragma unroll
    for (int mt = 0; mt < 2; ++mt)
#pragma unroll
        for (int s = 0; s < 4; ++s) cst[mt][s] = 0.f;

    const int q4 = l & 3, rlq = l >> 2;

    for (int st = 0; st < 64; ++st) {
        const int p = st & 1;
        __syncthreads();   // single barrier per step

        // drain xs/ps of previous step
        if (st > 0 && tid < 128) {
            int which = tid >> 6, seq = tid & 63;
            const float* rb = red + ((st - 1) & 1) * 1024 + which * 512 + seq;
            float v = rb[0] + rb[64] + rb[128] + rb[192]
                    + rb[256] + rb[320] + rb[384] + rb[448];
            v += which ? bps : bxs;
            int tprev = dir ? (64 - st) : (st - 1);
            float* gdst = which ? g_ps : g_xs;
            gdst[((size_t)dir * Bn + b0 + seq) * Tn + tprev] = v;
        }

        // prefetch x(t+1)
        uint4 xpf;
        if (st < 63) {
            int t2 = dir ? (62 - st) : (st + 1);
            xpf = ((const uint4*)(g_x2h + ((size_t)t2 * Bn + b0) * 64))[tid];
        }

        const __half* xbp = xb + p * 5632;
        const __half* hFp = hT + p * 5632;

        float acc[2][4][4];
#pragma unroll
        for (int mt = 0; mt < 2; ++mt)
#pragma unroll
            for (int g = 0; g < 4; ++g) {
                acc[mt][g][0] = bia[g][0]; acc[mt][g][1] = bia[g][1];
                acc[mt][g][2] = bia[g][0]; acc[mt][g][3] = bia[g][1];
            }

        // x-part: kt 0..3
#pragma unroll
        for (int kt = 0; kt < 4; ++kt) {
            int cb = kt * 16 + 2 * q4;
#pragma unroll
            for (int mt = 0; mt < 2; ++mt) {
                int r = (wm * 2 + mt) * 16 + rlq;
                uint4 a;
                a.x = *(const unsigned*)(xbp + r * HP + cb);
                a.y = *(const unsigned*)(xbp + (r + 8) * HP + cb);
                a.z = *(const unsigned*)(xbp + r * HP + cb + 8);
                a.w = *(const unsigned*)(xbp + (r + 8) * HP + cb + 8);
#pragma unroll
                for (int g = 0; g < 4; ++g)
                    mma_f16(acc[mt][g], a, wF[((wu * 4 + g) * 8 + kt) * 32 + l]);
            }
        }
        // h-part: kt 4..7
#pragma unroll
        for (int kt = 4; kt < 8; ++kt) {
            int cb = (kt - 4) * 16 + 2 * q4;
#pragma unroll
            for (int mt = 0; mt < 2; ++mt) {
                int r = (wm * 2 + mt) * 16 + rlq;
                uint4 a;
                a.x = *(const unsigned*)(hFp + r * HP + cb);
                a.y = *(const unsigned*)(hFp + (r + 8) * HP + cb);
                a.z = *(const unsigned*)(hFp + r * HP + cb + 8);
                a.w = *(const unsigned*)(hFp + (r + 8) * HP + cb + 8);
#pragma unroll
                for (int g = 0; g < 4; ++g)
                    mma_f16(acc[mt][g], a, wF[((wu * 4 + g) * 8 + kt) * 32 + l]);
            }
        }

        // ---- epilogue: gates, c/h update ----
        float hreg[2][4];
        float px[2][2], pq[2][2];
#pragma unroll
        for (int mt = 0; mt < 2; ++mt) {
#pragma unroll
            for (int s = 0; s < 4; ++s) {
                float iv = acc[mt][0][s], jv = acc[mt][1][s];
                float fv = acc[mt][2][s], ov = acc[mt][3][s];
                float cn = cst[mt][s] * sigt(fv + 1.f) + sigt(iv) * tanha(jv);
                cst[mt][s] = cn;
                hreg[mt][s] = tanha(cn) * sigt(ov);
            }
            px[mt][0] = hreg[mt][0] * wxu0 + hreg[mt][1] * wxu1;
            px[mt][1] = hreg[mt][2] * wxu0 + hreg[mt][3] * wxu1;
            pq[mt][0] = hreg[mt][0] * wpu0 + hreg[mt][1] * wpu1;
            pq[mt][1] = hreg[mt][2] * wpu0 + hreg[mt][3] * wpu1;
        }
#pragma unroll
        for (int o = 1; o <= 2; o <<= 1) {
#pragma unroll
            for (int mt = 0; mt < 2; ++mt) {
                px[mt][0] += __shfl_xor_sync(0xffffffffu, px[mt][0], o);
                px[mt][1] += __shfl_xor_sync(0xffffffffu, px[mt][1], o);
                pq[mt][0] += __shfl_xor_sync(0xffffffffu, pq[mt][0], o);
                pq[mt][1] += __shfl_xor_sync(0xffffffffu, pq[mt][1], o);
            }
        }
        if ((l & 3) == 0) {
            float* rp = red + p * 1024;
#pragma unroll
            for (int mt = 0; mt < 2; ++mt) {
                int seqlo = (wm * 2 + mt) * 16 + (l >> 2);
                rp[wu * 64 + seqlo]           = px[mt][0];
                rp[wu * 64 + seqlo + 8]       = px[mt][1];
                rp[512 + wu * 64 + seqlo]     = pq[mt][0];
                rp[512 + wu * 64 + seqlo + 8] = pq[mt][1];
            }
        }
        // new h (fp16) -> hT[p^1]
        {
            __half* hDst = hT + (p ^ 1) * 5632;
#pragma unroll
            for (int mt = 0; mt < 2; ++mt) {
                int rlo = (wm * 2 + mt) * 16 + rlq, rhi = rlo + 8;
                *(unsigned*)(hDst + rlo * HP + u0) = h2u(hreg[mt][0], hreg[mt][1]);
                *(unsigned*)(hDst + rhi * HP + u0) = h2u(hreg[mt][2], hreg[mt][3]);
            }
        }
        // prefetched x -> xb[p^1]
        if (st < 63) {
            __half* xd = xb + (p ^ 1) * 5632;
            int row = tid >> 3, c8 = tid & 7;
            *(uint4*)(xd + row * HP + c8 * 8) = xpf;
        }
    }

    // drain final step
    __syncthreads();
    if (tid < 128) {
        int which = tid >> 6, seq = tid & 63;
        const float* rb = red + 1024 + which * 512 + seq;   // st=63 parity 1
        float v = rb[0] + rb[64] + rb[128] + rb[192]
                + rb[256] + rb[320] + rb[384] + rb[448];
        v += which ? bps : bxs;
        int tlast = dir ? 0 : 63;
        float* gdst = which ? g_ps : g_xs;
        gdst[((size_t)dir * Bn + b0 + seq) * Tn + tlast] = v;
    }
}

// =====================================================================
// Kernel 3: attention head. warp per sequence; 8 seqs / block.
// =====================================================================
__global__ void __launch_bounds__(256) attn_kernel(
    const float* __restrict__ gp, const float* __restrict__ bep,
    const float* __restrict__ W3, const float* __restrict__ b3,
    float* __restrict__ out)
{
    __shared__ float sW3[4096];
    __shared__ float sb3[64];
    const int tid = threadIdx.x;
    for (int i = tid; i < 1024; i += 256) ((float4*)sW3)[i] = ((const float4*)W3)[i];
    if (tid < 64) sb3[tid] = b3[tid];
    __syncthreads();

    const int lane = tid & 31, w = tid >> 5;
    const int seq = blockIdx.x * 8 + w;

    const float* psr = g_ps + (size_t)seq * Tn;
    float v0 = psr[lane], v1 = psr[lane + 32];
    float s = v0 + v1, q = v0 * v0 + v1 * v1;
#pragma unroll
    for (int o = 16; o; o >>= 1) {
        s += __shfl_xor_sync(0xffffffffu, s, o);
        q += __shfl_xor_sync(0xffffffffu, q, o);
    }
    float m = s * 0.015625f;
    float var = q * 0.015625f - m * m;
    float rs = rsqrtf(var + 1e-12f);
    float p0 = fmaxf((v0 - m) * rs * gp[lane]      + bep[lane],      0.f);
    float p1 = fmaxf((v1 - m) * rs * gp[lane + 32] + bep[lane + 32], 0.f);

    float l0 = sb3[lane], l1 = sb3[lane + 32];
#pragma unroll 8
    for (int tt = 0; tt < 32; ++tt) {
        float pv = __shfl_sync(0xffffffffu, p0, tt);
        l0 += pv * sW3[tt * 64 + lane];
        l1 += pv * sW3[tt * 64 + lane + 32];
    }
#pragma unroll 8
    for (int tt = 0; tt < 32; ++tt) {
        float pv = __shfl_sync(0xffffffffu, p1, tt);
        l0 += pv * sW3[(32 + tt) * 64 + lane];
        l1 += pv * sW3[(32 + tt) * 64 + lane + 32];
    }

    float mx = fmaxf(l0, l1);
#pragma unroll
    for (int o = 16; o; o >>= 1) mx = fmaxf(mx, __shfl_xor_sync(0xffffffffu, mx, o));
    float e0 = __expf(l0 - mx), e1 = __expf(l1 - mx);
    float se = e0 + e1;
    const float* xsr = g_xs + (size_t)seq * Tn;
    float rsum = e0 * xsr[lane] + e1 * xsr[lane + 32];
#pragma unroll
    for (int o = 16; o; o >>= 1) {
        se   += __shfl_xor_sync(0xffffffffu, se, o);
        rsum += __shfl_xor_sync(0xffffffffu, rsum, o);
    }
    if (lane == 0) out[seq] = rsum / se;
}

// =====================================================================
extern "C" void kernel_launch(void* const* d_in, const int* in_sizes, int n_in,
                              void* d_out, int out_size)
{
    const float* obs = (const float*)d_in[0];
    const float* act = (const float*)d_in[1];
    const float* W1  = (const float*)d_in[2];
    const float* b1  = (const float*)d_in[3];
    const float* g1  = (const float*)d_in[4];
    const float* be1 = (const float*)d_in[5];
    const float* W2  = (const float*)d_in[6];
    const float* b2  = (const float*)d_in[7];
    const float* g2  = (const float*)d_in[8];
    const float* be2 = (const float*)d_in[9];
    const float* Wf  = (const float*)d_in[10];
    const float* bf  = (const float*)d_in[11];
    const float* Wb  = (const float*)d_in[12];
    const float* bb  = (const float*)d_in[13];
    const float* wx  = (const float*)d_in[14];
    const float* bx  = (const float*)d_in[15];
    const float* wp  = (const float*)d_in[16];
    const float* bp  = (const float*)d_in[17];
    const float* gp  = (const float*)d_in[18];
    const float* bep = (const float*)d_in[19];
    const float* W3  = (const float*)d_in[20];
    const float* b3  = (const float*)d_in[21];
    float* out = (float*)d_out;

    const int trunk_smem = 28672 + 128 * XP * 2 + 128 * AP * 2 + 384 * 4;  // 91648 B
    const int lstm_smem  = 65536 + 2 * 22528 + 8192;                       // 118784 B
    cudaFuncSetAttribute(trunk_kernel, cudaFuncAttributeMaxDynamicSharedMemorySize, trunk_smem);
    cudaFuncSetAttribute(lstm_kernel,  cudaFuncAttributeMaxDynamicSharedMemorySize, lstm_smem);

    trunk_kernel<<<2048, 256, trunk_smem>>>(obs, act, W1, b1, g1, be1, W2, b2, g2, be2);

    dim3 lg(64, 2);
    lstm_kernel<<<lg, 512, lstm_smem>>>(Wf, bf, Wb, bb, wx, bx, wp, bp);

    attn_kernel<<<1024, 256>>>(gp, bep, W3, b3, out);
}

// round 12
// speedup vs baseline: 6.0139x; 1.0369x over previous
#include <cuda_runtime.h>
#include <cuda_fp16.h>
#include <math.h>

#define Bn 4096
#define Tn 64

typedef unsigned long long ull;

// ---------------- device scratch ----------------
// g_x2h: [t][chunk(64 seqs)][4096 halves in m16n8k16 A-fragment order]
__device__ __half g_x2h[(size_t)Tn * Bn * 64];

__device__ __forceinline__ float tanha(float x) {
    float r; asm("tanh.approx.f32 %0, %1;" : "=f"(r) : "f"(x)); return r;
}
__device__ __forceinline__ float sigt(float x) {
    return fmaf(tanha(0.5f * x), 0.5f, 0.5f);
}
__device__ __forceinline__ unsigned h2u(float lo, float hi) {
    __half2 h = __floats2half2_rn(lo, hi);
    return *(unsigned*)&h;
}
__device__ __forceinline__ void mma_f16(float* c, uint4 a, uint2 b) {
    asm volatile(
        "mma.sync.aligned.m16n8k16.row.col.f32.f16.f16.f32 "
        "{%0,%1,%2,%3}, {%4,%5,%6,%7}, {%8,%9}, {%0,%1,%2,%3};"
        : "+f"(c[0]), "+f"(c[1]), "+f"(c[2]), "+f"(c[3])
        : "r"(a.x), "r"(a.y), "r"(a.z), "r"(a.w), "r"(b.x), "r"(b.y));
}

#define XP 136   // trunk sX pad (halves per row)
#define AP 104   // trunk sA2 pad

// =====================================================================
// Kernel 1: MLP trunk via fp16 mma. CTA = (chunk, tpair): 64 seqs x 2 t.
// Local row r = tj*64 + s. Output written in fragment order, coalesced.
// =====================================================================
__global__ void __launch_bounds__(256, 2) trunk_kernel(
    const float* __restrict__ obs, const float* __restrict__ act,
    const float* __restrict__ W1, const float* __restrict__ b1,
    const float* __restrict__ g1, const float* __restrict__ be1,
    const float* __restrict__ W2, const float* __restrict__ b2,
    const float* __restrict__ g2, const float* __restrict__ be2)
{
    extern __shared__ char smc[];
    uint2*  B1   = (uint2*)smc;                      // 2048 uint2 (16 KB)
    uint2*  B2   = (uint2*)(smc + 16384);            // 1536 uint2 (12 KB)
    __half* sX   = (__half*)(smc + 28672);           // 128 x XP
    __half* sA2  = (__half*)(smc + 28672 + 128*XP*2);// 128 x AP
    float*  sP   = (float*)(smc + 28672 + 128*XP*2 + 128*AP*2); // 384

    const int tid = threadIdx.x;
    const int l = tid & 31, w = tid >> 5;
    const int chunk = blockIdx.x >> 5, tpair = blockIdx.x & 31;

#pragma unroll
    for (int q = 0; q < 8; ++q) {
        int s = tid + q * 256;
        int l2 = s & 31, kt = (s >> 5) & 7, nt = s >> 8;
        int k0 = kt * 16 + 2 * (l2 & 3), n = nt * 8 + (l2 >> 2);
        uint2 b;
        b.x = h2u(W1[k0 * 64 + n],       W1[(k0 + 1) * 64 + n]);
        b.y = h2u(W1[(k0 + 8) * 64 + n], W1[(k0 + 9) * 64 + n]);
        B1[s] = b;
    }
#pragma unroll
    for (int q = 0; q < 6; ++q) {
        int s = tid + q * 256;
        int l2 = s & 31, r = s >> 5;
        int kt = r % 6, nt = r / 6;
        int k0 = kt * 16 + 2 * (l2 & 3), n = nt * 8 + (l2 >> 2);
        uint2 b;
        b.x = h2u(W2[k0 * 64 + n],       W2[(k0 + 1) * 64 + n]);
        b.y = h2u(W2[(k0 + 8) * 64 + n], W2[(k0 + 9) * 64 + n]);
        B2[s] = b;
    }
    if (tid < 64) {
        sP[tid]       = b1[tid];  sP[64 + tid]  = g1[tid];  sP[128 + tid] = be1[tid];
        sP[192 + tid] = b2[tid];  sP[256 + tid] = g2[tid];  sP[320 + tid] = be2[tid];
    }
#pragma unroll
    for (int q = 0; q < 16; ++q) {
        int f = tid + q * 256;
        int row = f >> 5, c4 = f & 31;
        int s = row & 63, tj = row >> 6;
        size_t grow = ((size_t)(chunk * 64 + s)) * 64 + tpair * 2 + tj;
        float4 v = *(const float4*)(obs + grow * 128 + c4 * 4);
        uint2 hv; hv.x = h2u(v.x, v.y); hv.y = h2u(v.z, v.w);
        *(uint2*)(sX + row * XP + c4 * 4) = hv;
    }
#pragma unroll
    for (int q = 0; q < 4; ++q) {
        int f = tid + q * 256;
        int row = f >> 3, c8 = f & 7;
        int s = row & 63, tj = row >> 6;
        size_t grow = ((size_t)(chunk * 64 + s)) * 64 + tpair * 2 + tj;
        float4 v = *(const float4*)(act + grow * 32 + c8 * 4);
        uint2 hv; hv.x = h2u(v.x, v.y); hv.y = h2u(v.z, v.w);
        *(uint2*)(sA2 + row * AP + 64 + c8 * 4) = hv;
    }
    __syncthreads();

    const int q4 = l & 3, rlq = l >> 2;
    const int ar = w * 16 + rlq;

    float acc[8][4];
#pragma unroll
    for (int nt = 0; nt < 8; ++nt) {
        int c0 = nt * 8 + 2 * q4;
        acc[nt][0] = sP[c0]; acc[nt][1] = sP[c0 + 1];
        acc[nt][2] = sP[c0]; acc[nt][3] = sP[c0 + 1];
    }
#pragma unroll
    for (int kt = 0; kt < 8; ++kt) {
        int cb = kt * 16 + 2 * q4;
        uint4 a;
        a.x = *(const unsigned*)(sX + ar * XP + cb);
        a.y = *(const unsigned*)(sX + (ar + 8) * XP + cb);
        a.z = *(const unsigned*)(sX + ar * XP + cb + 8);
        a.w = *(const unsigned*)(sX + (ar + 8) * XP + cb + 8);
#pragma unroll
        for (int nt = 0; nt < 8; ++nt)
            mma_f16(acc[nt], a, B1[(nt * 8 + kt) * 32 + l]);
    }

    {
        float sl = 0.f, ql = 0.f, sh = 0.f, qh = 0.f;
#pragma unroll
        for (int nt = 0; nt < 8; ++nt) {
            sl += acc[nt][0] + acc[nt][1];
            ql += acc[nt][0] * acc[nt][0] + acc[nt][1] * acc[nt][1];
            sh += acc[nt][2] + acc[nt][3];
            qh += acc[nt][2] * acc[nt][2] + acc[nt][3] * acc[nt][3];
        }
#pragma unroll
        for (int o = 1; o <= 2; o <<= 1) {
            sl += __shfl_xor_sync(0xffffffffu, sl, o);
            ql += __shfl_xor_sync(0xffffffffu, ql, o);
            sh += __shfl_xor_sync(0xffffffffu, sh, o);
            qh += __shfl_xor_sync(0xffffffffu, qh, o);
        }
        float ml = sl * 0.015625f, vl = ql * 0.015625f - ml * ml;
        float mh = sh * 0.015625f, vh = qh * 0.015625f - mh * mh;
        float il = rsqrtf(vl + 1e-12f), ih = rsqrtf(vh + 1e-12f);
#pragma unroll
        for (int nt = 0; nt < 8; ++nt) {
            int c0 = nt * 8 + 2 * q4;
            float g0 = sP[64 + c0], g1v = sP[64 + c0 + 1];
            float e0 = sP[128 + c0], e1v = sP[128 + c0 + 1];
            float zl0 = fmaxf((acc[nt][0] - ml) * il * g0  + e0,  0.f);
            float zl1 = fmaxf((acc[nt][1] - ml) * il * g1v + e1v, 0.f);
            float zh0 = fmaxf((acc[nt][2] - mh) * ih * g0  + e0,  0.f);
            float zh1 = fmaxf((acc[nt][3] - mh) * ih * g1v + e1v, 0.f);
            *(unsigned*)(sA2 + ar * AP + c0)       = h2u(zl0, zl1);
            *(unsigned*)(sA2 + (ar + 8) * AP + c0) = h2u(zh0, zh1);
        }
    }
    __syncthreads();

    float a2[8][4];
#pragma unroll
    for (int nt = 0; nt < 8; ++nt) {
        int c0 = nt * 8 + 2 * q4;
        a2[nt][0] = sP[192 + c0]; a2[nt][1] = sP[192 + c0 + 1];
        a2[nt][2] = sP[192 + c0]; a2[nt][3] = sP[192 + c0 + 1];
    }
#pragma unroll
    for (int kt = 0; kt < 6; ++kt) {
        int cb = kt * 16 + 2 * q4;
        uint4 a;
        a.x = *(const unsigned*)(sA2 + ar * AP + cb);
        a.y = *(const unsigned*)(sA2 + (ar + 8) * AP + cb);
        a.z = *(const unsigned*)(sA2 + ar * AP + cb + 8);
        a.w = *(const unsigned*)(sA2 + (ar + 8) * AP + cb + 8);
#pragma unroll
        for (int nt = 0; nt < 8; ++nt)
            mma_f16(a2[nt], a, B2[(nt * 6 + kt) * 32 + l]);
    }

    {
        float sl = 0.f, ql = 0.f, sh = 0.f, qh = 0.f;
#pragma unroll
        for (int nt = 0; nt < 8; ++nt) {
            sl += a2[nt][0] + a2[nt][1];
            ql += a2[nt][0] * a2[nt][0] + a2[nt][1] * a2[nt][1];
            sh += a2[nt][2] + a2[nt][3];
            qh += a2[nt][2] * a2[nt][2] + a2[nt][3] * a2[nt][3];
        }
#pragma unroll
        for (int o = 1; o <= 2; o <<= 1) {
            sl += __shfl_xor_sync(0xffffffffu, sl, o);
            ql += __shfl_xor_sync(0xffffffffu, ql, o);
            sh += __shfl_xor_sync(0xffffffffu, sh, o);
            qh += __shfl_xor_sync(0xffffffffu, qh, o);
        }
        float ml = sl * 0.015625f, vl = ql * 0.015625f - ml * ml;
        float mh = sh * 0.015625f, vh = qh * 0.015625f - mh * mh;
        float il = rsqrtf(vl + 1e-12f), ih = rsqrtf(vh + 1e-12f);
#pragma unroll
        for (int nt = 0; nt < 8; ++nt) {
            int c0 = nt * 8 + 2 * q4;
            float g0 = sP[256 + c0], g1v = sP[256 + c0 + 1];
            float e0 = sP[320 + c0], e1v = sP[320 + c0 + 1];
            float zl0 = fmaxf((a2[nt][0] - ml) * il * g0  + e0,  0.f);
            float zl1 = fmaxf((a2[nt][1] - ml) * il * g1v + e1v, 0.f);
            float zh0 = fmaxf((a2[nt][2] - mh) * ih * g0  + e0,  0.f);
            float zh1 = fmaxf((a2[nt][3] - mh) * ih * g1v + e1v, 0.f);
            *(unsigned*)(sX + ar * XP + c0)       = h2u(zl0, zl1);
            *(unsigned*)(sX + (ar + 8) * XP + c0) = h2u(zh0, zh1);
        }
    }
    __syncthreads();   // out-stage reads rows across warps

#pragma unroll
    for (int q = 0; q < 4; ++q) {
        int idx = tid + q * 256;
        int f = idx & 511, tj = idx >> 9;
        int l2 = f & 31, kt = (f >> 5) & 3, mtg = f >> 7;
        int sA = mtg * 16 + (l2 >> 2);
        int c0 = kt * 16 + 2 * (l2 & 3);
        const __half* bsx = sX + (tj * 64) * XP;
        uint4 v;
        v.x = *(const unsigned*)(bsx + sA * XP + c0);
        v.y = *(const unsigned*)(bsx + (sA + 8) * XP + c0);
        v.z = *(const unsigned*)(bsx + sA * XP + c0 + 8);
        v.w = *(const unsigned*)(bsx + (sA + 8) * XP + c0 + 8);
        int t = tpair * 2 + tj;
        *(uint4*)(g_x2h + ((size_t)t * 64 + chunk) * 4096 + (size_t)f * 8) = v;
    }
}

// =====================================================================
// Kernel 2: bidirectional LSTM + fused attention. grid (64,2), 512 thr.
// =====================================================================
__global__ void __launch_bounds__(512, 1) lstm_kernel(
    const float* __restrict__ Wf, const float* __restrict__ bfv,
    const float* __restrict__ Wb, const float* __restrict__ bbv,
    const float* __restrict__ wx, const float* __restrict__ bxv,
    const float* __restrict__ wp, const float* __restrict__ bp,
    const float* __restrict__ gp, const float* __restrict__ bep,
    const float* __restrict__ W3, const float* __restrict__ b3,
    float* __restrict__ out)
{
    extern __shared__ char smc[];
    uint2*  wF  = (uint2*)smc;                      // 8192 uint2 (64 KB)
    __half* xb  = (__half*)(smc + 65536);           // 2 x 4096 halves
    __half* hT  = (__half*)(smc + 65536 + 16384);   // 2 x 4096 halves
    float*  red = (float*)(smc + 65536 + 32768);    // 2 x 1024
    float*  sXS = (float*)(smc + 65536 + 40960);    // 64 x 65
    float*  sPS = sXS + 64 * 65;                    // 64 x 65

    const int dir = blockIdx.y;
    const int chk = blockIdx.x;
    const int b0  = chk * 64;
    const float* W    = dir ? Wb  : Wf;
    const float* bias = dir ? bbv : bfv;
    const int tid = threadIdx.x;
    const int l = tid & 31, w = tid >> 5;
    const int wu = w & 7, wm = w >> 3;

#pragma unroll
    for (int q = 0; q < 16; ++q) {
        int s = tid + q * 512;
        int l2 = s & 31, kt = (s >> 5) & 7, g = (s >> 8) & 3, ww = s >> 10;
        int k0 = kt * 16 + 2 * (l2 & 3);
        int n  = g * 64 + 8 * ww + (l2 >> 2);
        uint2 b;
        b.x = h2u(W[k0 * 256 + n],       W[(k0 + 1) * 256 + n]);
        b.y = h2u(W[(k0 + 8) * 256 + n], W[(k0 + 9) * 256 + n]);
        wF[s] = b;
    }
    {
        int t0 = dir ? 63 : 0;
        const uint4* src = (const uint4*)(g_x2h + ((size_t)t0 * 64 + chk) * 4096);
        ((uint4*)xb)[tid] = src[tid];
        ((uint4*)hT)[tid] = make_uint4(0, 0, 0, 0);
    }
    __syncthreads();   // wF visible for register hoist

    uint2 bxr[4][4];
#pragma unroll
    for (int kt = 0; kt < 4; ++kt)
#pragma unroll
        for (int g = 0; g < 4; ++g)
            bxr[kt][g] = wF[((wu * 4 + g) * 8 + kt) * 32 + l];

    const int q4 = l & 3, rlq = l >> 2;
    const int u0 = 8 * wu + 2 * q4;
    float bia[4][2];
#pragma unroll
    for (int g = 0; g < 4; ++g) {
        bia[g][0] = bias[g * 64 + u0];
        bia[g][1] = bias[g * 64 + u0 + 1];
    }
    const float wxu0 = wx[u0], wxu1 = wx[u0 + 1];
    const float wpu0 = wp[u0], wpu1 = wp[u0 + 1];
    const float bxs = bxv[0], bps = bp[0];

    float cst[2][4];
#pragma unroll
    for (int mt = 0; mt < 2; ++mt)
#pragma unroll
        for (int s = 0; s < 4; ++s) cst[mt][s] = 0.f;

    const int kth = wu >> 1;
    const int hsl = (wu & 1) * 4;

    for (int st = 0; st < 64; ++st) {
        const int p = st & 1;
        __syncthreads();

        if (st > 0 && tid < 128) {
            int which = tid >> 6, seq = tid & 63;
            const float* rb = red + ((st - 1) & 1) * 1024 + which * 512 + seq;
            float v = rb[0] + rb[64] + rb[128] + rb[192]
                    + rb[256] + rb[320] + rb[384] + rb[448];
            int tprev = dir ? (64 - st) : (st - 1);
            if (which) sPS[seq * 65 + tprev] = v + bps;
            else       sXS[seq * 65 + tprev] = v + bxs;
        }

        uint4 xpf;
        if (st < 63) {
            int t2 = dir ? (62 - st) : (st + 1);
            xpf = ((const uint4*)(g_x2h + ((size_t)t2 * 64 + chk) * 4096))[tid];
        }

        const __half* xbp = xb + p * 4096;
        const __half* hFp = hT + p * 4096;

        float acc[2][4][4];
#pragma unroll
        for (int mt = 0; mt < 2; ++mt)
#pragma unroll
            for (int g = 0; g < 4; ++g) {
                acc[mt][g][0] = bia[g][0]; acc[mt][g][1] = bia[g][1];
                acc[mt][g][2] = bia[g][0]; acc[mt][g][3] = bia[g][1];
            }

#pragma unroll
        for (int kt = 0; kt < 4; ++kt) {
#pragma unroll
            for (int mt = 0; mt < 2; ++mt) {
                int mtg = wm * 2 + mt;
                uint4 a = *(const uint4*)(xbp + (((mtg * 4 + kt) * 32 + l) << 3));
#pragma unroll
                for (int g = 0; g < 4; ++g)
                    mma_f16(acc[mt][g], a, bxr[kt][g]);
            }
        }
#pragma unroll
        for (int kt = 0; kt < 4; ++kt) {
#pragma unroll
            for (int mt = 0; mt < 2; ++mt) {
                int mtg = wm * 2 + mt;
                uint4 a = *(const uint4*)(hFp + (((mtg * 4 + kt) * 32 + l) << 3));
#pragma unroll
                for (int g = 0; g < 4; ++g)
                    mma_f16(acc[mt][g], a, wF[((wu * 4 + g) * 8 + 4 + kt) * 32 + l]);
            }
        }

        float hreg[2][4];
        float px[2][2], pq[2][2];
#pragma unroll
        for (int mt = 0; mt < 2; ++mt) {
#pragma unroll
            for (int s = 0; s < 4; ++s) {
                float iv = acc[mt][0][s], jv = acc[mt][1][s];
                float fv = acc[mt][2][s], ov = acc[mt][3][s];
                float cn = cst[mt][s] * sigt(fv + 1.f) + sigt(iv) * tanha(jv);
                cst[mt][s] = cn;
                hreg[mt][s] = tanha(cn) * sigt(ov);
            }
            px[mt][0] = hreg[mt][0] * wxu0 + hreg[mt][1] * wxu1;
            px[mt][1] = hreg[mt][2] * wxu0 + hreg[mt][3] * wxu1;
            pq[mt][0] = hreg[mt][0] * wpu0 + hreg[mt][1] * wpu1;
            pq[mt][1] = hreg[mt][2] * wpu0 + hreg[mt][3] * wpu1;
        }
#pragma unroll
        for (int o = 1; o <= 2; o <<= 1) {
#pragma unroll
            for (int mt = 0; mt < 2; ++mt) {
                px[mt][0] += __shfl_xor_sync(0xffffffffu, px[mt][0], o);
                px[mt][1] += __shfl_xor_sync(0xffffffffu, px[mt][1], o);
                pq[mt][0] += __shfl_xor_sync(0xffffffffu, pq[mt][0], o);
                pq[mt][1] += __shfl_xor_sync(0xffffffffu, pq[mt][1], o);
            }
        }
        if ((l & 3) == 0) {
            float* rp = red + p * 1024;
#pragma unroll
            for (int mt = 0; mt < 2; ++mt) {
                int seqlo = (wm * 2 + mt) * 16 + (l >> 2);
                rp[wu * 64 + seqlo]           = px[mt][0];
                rp[wu * 64 + seqlo + 8]       = px[mt][1];
                rp[512 + wu * 64 + seqlo]     = pq[mt][0];
                rp[512 + wu * 64 + seqlo + 8] = pq[mt][1];
            }
        }
        {
            __half* hDst = hT + (p ^ 1) * 4096;
#pragma unroll
            for (int mt = 0; mt < 2; ++mt) {
                int mtg = wm * 2 + mt;
                uint2 hv;
                hv.x = h2u(hreg[mt][0], hreg[mt][1]);
                hv.y = h2u(hreg[mt][2], hreg[mt][3]);
                *(uint2*)(hDst + (((mtg * 4 + kth) * 32 + l) << 3) + hsl) = hv;
            }
        }
        if (st < 63) {
            ((uint4*)(xb + (p ^ 1) * 4096))[tid] = xpf;
        }
    }

    __syncthreads();
    if (tid < 128) {
        int which = tid >> 6, seq = tid & 63;
        const float* rb = red + 1024 + which * 512 + seq;
        float v = rb[0] + rb[64] + rb[128] + rb[192]
                + rb[256] + rb[320] + rb[384] + rb[448];
        int tlast = dir ? 0 : 63;
        if (which) sPS[seq * 65 + tlast] = v + bps;
        else       sXS[seq * 65 + tlast] = v + bxs;
    }
    float* sW3a = (float*)smc;
    float* sprm = sW3a + 4096;
    for (int i = tid; i < 1024; i += 512) ((float4*)sW3a)[i] = ((const float4*)W3)[i];
    if (tid < 64) {
        sprm[tid]       = b3[tid];
        sprm[64 + tid]  = gp[tid];
        sprm[128 + tid] = bep[tid];
    }
    __syncthreads();

#pragma unroll
    for (int si = 0; si < 4; ++si) {
        int seq = w * 4 + si;
        float v0 = sPS[seq * 65 + l], v1 = sPS[seq * 65 + 32 + l];
        float s = v0 + v1, q = v0 * v0 + v1 * v1;
#pragma unroll
        for (int o = 16; o; o >>= 1) {
            s += __shfl_xor_sync(0xffffffffu, s, o);
            q += __shfl_xor_sync(0xffffffffu, q, o);
        }
        float m = s * 0.015625f;
        float var = q * 0.015625f - m * m;
        float rs = rsqrtf(var + 1e-12f);
        float p0 = fmaxf((v0 - m) * rs * sprm[64 + l] + sprm[128 + l], 0.f);
        float p1 = fmaxf((v1 - m) * rs * sprm[96 + l] + sprm[160 + l], 0.f);

        float l0 = sprm[l], l1 = sprm[32 + l];
#pragma unroll 8
        for (int tt = 0; tt < 32; ++tt) {
            float pv = __shfl_sync(0xffffffffu, p0, tt);
            l0 += pv * sW3a[tt * 64 + l];
            l1 += pv * sW3a[tt * 64 + 32 + l];
        }
#pragma unroll 8
        for (int tt = 0; tt < 32; ++tt) {
            float pv = __shfl_sync(0xffffffffu, p1, tt);
            l0 += pv * sW3a[(32 + tt) * 64 + l];
            l1 += pv * sW3a[(32 + tt) * 64 + 32 + l];
        }

        float mx = fmaxf(l0, l1);
#pragma unroll
        for (int o = 16; o; o >>= 1) mx = fmaxf(mx, __shfl_xor_sync(0xffffffffu, mx, o));
        float e0 = __expf(l0 - mx), e1 = __expf(l1 - mx);
        float se = e0 + e1;
        float rsum = e0 * sXS[seq * 65 + l] + e1 * sXS[seq * 65 + 32 + l];
#pragma unroll
        for (int o = 16; o; o >>= 1) {
            se   += __shfl_xor_sync(0xffffffffu, se, o);
            rsum += __shfl_xor_sync(0xffffffffu, rsum, o);
        }
        if (l == 0) out[(size_t)dir * Bn + b0 + seq] = rsum / se;
    }
}

// =====================================================================
extern "C" void kernel_launch(void* const* d_in, const int* in_sizes, int n_in,
                              void* d_out, int out_size)
{
    const float* obs = (const float*)d_in[0];
    const float* act = (const float*)d_in[1];
    const float* W1  = (const float*)d_in[2];
    const float* b1  = (const float*)d_in[3];
    const float* g1  = (const float*)d_in[4];
    const float* be1 = (const float*)d_in[5];
    const float* W2  = (const float*)d_in[6];
    const float* b2  = (const float*)d_in[7];
    const float* g2  = (const float*)d_in[8];
    const float* be2 = (const float*)d_in[9];
    const float* Wf  = (const float*)d_in[10];
    const float* bf  = (const float*)d_in[11];
    const float* Wb  = (const float*)d_in[12];
    const float* bb  = (const float*)d_in[13];
    const float* wx  = (const float*)d_in[14];
    const float* bxv = (const float*)d_in[15];
    const float* wp  = (const float*)d_in[16];
    const float* bp  = (const float*)d_in[17];
    const float* gp  = (const float*)d_in[18];
    const float* bep = (const float*)d_in[19];
    const float* W3  = (const float*)d_in[20];
    const float* b3  = (const float*)d_in[21];
    float* out = (float*)d_out;

    const int trunk_smem = 28672 + 128 * XP * 2 + 128 * AP * 2 + 384 * 4;  // 91648 B
    const int lstm_smem  = 65536 + 16384 + 16384 + 8192 + 2 * 64 * 65 * 4; // 139776 B
    cudaFuncSetAttribute(trunk_kernel, cudaFuncAttributeMaxDynamicSharedMemorySize, trunk_smem);
    cudaFuncSetAttribute(lstm_kernel,  cudaFuncAttributeMaxDynamicSharedMemorySize, lstm_smem);

    trunk_kernel<<<2048, 256, trunk_smem>>>(obs, act, W1, b1, g1, be1, W2, b2, g2, be2);

    dim3 lg(64, 2);
    lstm_kernel<<<lg, 512, lstm_smem>>>(Wf, bf, Wb, bb, wx, bxv, wp, bp,
                                        gp, bep, W3, b3, out);
}

// round 13
// speedup vs baseline: 6.7915x; 1.1293x over previous
#include <cuda_runtime.h>
#include <cuda_fp16.h>
#include <math.h>

#define Bn 4096
#define Tn 64

typedef unsigned long long ull;

// ---------------- device scratch ----------------
// g_x2h: [t][chunk64][4096 halves in m16n8k16 A-fragment order, mtg-major]
// (a 32-seq sub-chunk is the contiguous 2048-half half of a 64-chunk block)
__device__ __half g_x2h[(size_t)Tn * Bn * 64];

__device__ __forceinline__ float tanha(float x) {
    float r; asm("tanh.approx.f32 %0, %1;" : "=f"(r) : "f"(x)); return r;
}
__device__ __forceinline__ float sigt(float x) {
    return fmaf(tanha(0.5f * x), 0.5f, 0.5f);
}
__device__ __forceinline__ unsigned h2u(float lo, float hi) {
    __half2 h = __floats2half2_rn(lo, hi);
    return *(unsigned*)&h;
}
__device__ __forceinline__ void mma_f16(float* c, uint4 a, uint2 b) {
    asm volatile(
        "mma.sync.aligned.m16n8k16.row.col.f32.f16.f16.f32 "
        "{%0,%1,%2,%3}, {%4,%5,%6,%7}, {%8,%9}, {%0,%1,%2,%3};"
        : "+f"(c[0]), "+f"(c[1]), "+f"(c[2]), "+f"(c[3])
        : "r"(a.x), "r"(a.y), "r"(a.z), "r"(a.w), "r"(b.x), "r"(b.y));
}

#define XP 136   // trunk sX pad (halves per row)
#define AP 104   // trunk sA2 pad

// =====================================================================
// Kernel 1: MLP trunk via fp16 mma. CTA = (chunk64, tpair): 64 seqs x 2 t.
// Output written in fragment order, coalesced. (Unchanged from round 12.)
// =====================================================================
__global__ void __launch_bounds__(256, 2) trunk_kernel(
    const float* __restrict__ obs, const float* __restrict__ act,
    const float* __restrict__ W1, const float* __restrict__ b1,
    const float* __restrict__ g1, const float* __restrict__ be1,
    const float* __restrict__ W2, const float* __restrict__ b2,
    const float* __restrict__ g2, const float* __restrict__ be2)
{
    extern __shared__ char smc[];
    uint2*  B1   = (uint2*)smc;                      // 2048 uint2 (16 KB)
    uint2*  B2   = (uint2*)(smc + 16384);            // 1536 uint2 (12 KB)
    __half* sX   = (__half*)(smc + 28672);           // 128 x XP
    __half* sA2  = (__half*)(smc + 28672 + 128*XP*2);// 128 x AP
    float*  sP   = (float*)(smc + 28672 + 128*XP*2 + 128*AP*2); // 384

    const int tid = threadIdx.x;
    const int l = tid & 31, w = tid >> 5;
    const int chunk = blockIdx.x >> 5, tpair = blockIdx.x & 31;

#pragma unroll
    for (int q = 0; q < 8; ++q) {
        int s = tid + q * 256;
        int l2 = s & 31, kt = (s >> 5) & 7, nt = s >> 8;
        int k0 = kt * 16 + 2 * (l2 & 3), n = nt * 8 + (l2 >> 2);
        uint2 b;
        b.x = h2u(W1[k0 * 64 + n],       W1[(k0 + 1) * 64 + n]);
        b.y = h2u(W1[(k0 + 8) * 64 + n], W1[(k0 + 9) * 64 + n]);
        B1[s] = b;
    }
#pragma unroll
    for (int q = 0; q < 6; ++q) {
        int s = tid + q * 256;
        int l2 = s & 31, r = s >> 5;
        int kt = r % 6, nt = r / 6;
        int k0 = kt * 16 + 2 * (l2 & 3), n = nt * 8 + (l2 >> 2);
        uint2 b;
        b.x = h2u(W2[k0 * 64 + n],       W2[(k0 + 1) * 64 + n]);
        b.y = h2u(W2[(k0 + 8) * 64 + n], W2[(k0 + 9) * 64 + n]);
        B2[s] = b;
    }
    if (tid < 64) {
        sP[tid]       = b1[tid];  sP[64 + tid]  = g1[tid];  sP[128 + tid] = be1[tid];
        sP[192 + tid] = b2[tid];  sP[256 + tid] = g2[tid];  sP[320 + tid] = be2[tid];
    }
#pragma unroll
    for (int q = 0; q < 16; ++q) {
        int f = tid + q * 256;
        int row = f >> 5, c4 = f & 31;
        int s = row & 63, tj = row >> 6;
        size_t grow = ((size_t)(chunk * 64 + s)) * 64 + tpair * 2 + tj;
        float4 v = *(const float4*)(obs + grow * 128 + c4 * 4);
        uint2 hv; hv.x = h2u(v.x, v.y); hv.y = h2u(v.z, v.w);
        *(uint2*)(sX + row * XP + c4 * 4) = hv;
    }
#pragma unroll
    for (int q = 0; q < 4; ++q) {
        int f = tid + q * 256;
        int row = f >> 3, c8 = f & 7;
        int s = row & 63, tj = row >> 6;
        size_t grow = ((size_t)(chunk * 64 + s)) * 64 + tpair * 2 + tj;
        float4 v = *(const float4*)(act + grow * 32 + c8 * 4);
        uint2 hv; hv.x = h2u(v.x, v.y); hv.y = h2u(v.z, v.w);
        *(uint2*)(sA2 + row * AP + 64 + c8 * 4) = hv;
    }
    __syncthreads();

    const int q4 = l & 3, rlq = l >> 2;
    const int ar = w * 16 + rlq;

    float acc[8][4];
#pragma unroll
    for (int nt = 0; nt < 8; ++nt) {
        int c0 = nt * 8 + 2 * q4;
        acc[nt][0] = sP[c0]; acc[nt][1] = sP[c0 + 1];
        acc[nt][2] = sP[c0]; acc[nt][3] = sP[c0 + 1];
    }
#pragma unroll
    for (int kt = 0; kt < 8; ++kt) {
        int cb = kt * 16 + 2 * q4;
        uint4 a;
        a.x = *(const unsigned*)(sX + ar * XP + cb);
        a.y = *(const unsigned*)(sX + (ar + 8) * XP + cb);
        a.z = *(const unsigned*)(sX + ar * XP + cb + 8);
        a.w = *(const unsigned*)(sX + (ar + 8) * XP + cb + 8);
#pragma unroll
        for (int nt = 0; nt < 8; ++nt)
            mma_f16(acc[nt], a, B1[(nt * 8 + kt) * 32 + l]);
    }

    {
        float sl = 0.f, ql = 0.f, sh = 0.f, qh = 0.f;
#pragma unroll
        for (int nt = 0; nt < 8; ++nt) {
            sl += acc[nt][0] + acc[nt][1];
            ql += acc[nt][0] * acc[nt][0] + acc[nt][1] * acc[nt][1];
            sh += acc[nt][2] + acc[nt][3];
            qh += acc[nt][2] * acc[nt][2] + acc[nt][3] * acc[nt][3];
        }
#pragma unroll
        for (int o = 1; o <= 2; o <<= 1) {
            sl += __shfl_xor_sync(0xffffffffu, sl, o);
            ql += __shfl_xor_sync(0xffffffffu, ql, o);
            sh += __shfl_xor_sync(0xffffffffu, sh, o);
            qh += __shfl_xor_sync(0xffffffffu, qh, o);
        }
        float ml = sl * 0.015625f, vl = ql * 0.015625f - ml * ml;
        float mh = sh * 0.015625f, vh = qh * 0.015625f - mh * mh;
        float il = rsqrtf(vl + 1e-12f), ih = rsqrtf(vh + 1e-12f);
#pragma unroll
        for (int nt = 0; nt < 8; ++nt) {
            int c0 = nt * 8 + 2 * q4;
            float g0 = sP[64 + c0], g1v = sP[64 + c0 + 1];
            float e0 = sP[128 + c0], e1v = sP[128 + c0 + 1];
            float zl0 = fmaxf((acc[nt][0] - ml) * il * g0  + e0,  0.f);
            float zl1 = fmaxf((acc[nt][1] - ml) * il * g1v + e1v, 0.f);
            float zh0 = fmaxf((acc[nt][2] - mh) * ih * g0  + e0,  0.f);
            float zh1 = fmaxf((acc[nt][3] - mh) * ih * g1v + e1v, 0.f);
            *(unsigned*)(sA2 + ar * AP + c0)       = h2u(zl0, zl1);
            *(unsigned*)(sA2 + (ar + 8) * AP + c0) = h2u(zh0, zh1);
        }
    }
    __syncthreads();

    float a2[8][4];
#pragma unroll
    for (int nt = 0; nt < 8; ++nt) {
        int c0 = nt * 8 + 2 * q4;
        a2[nt][0] = sP[192 + c0]; a2[nt][1] = sP[192 + c0 + 1];
        a2[nt][2] = sP[192 + c0]; a2[nt][3] = sP[192 + c0 + 1];
    }
#pragma unroll
    for (int kt = 0; kt < 6; ++kt) {
        int cb = kt * 16 + 2 * q4;
        uint4 a;
        a.x = *(const unsigned*)(sA2 + ar * AP + cb);
        a.y = *(const unsigned*)(sA2 + (ar + 8) * AP + cb);
        a.z = *(const unsigned*)(sA2 + ar * AP + cb + 8);
        a.w = *(const unsigned*)(sA2 + (ar + 8) * AP + cb + 8);
#pragma unroll
        for (int nt = 0; nt < 8; ++nt)
            mma_f16(a2[nt], a, B2[(nt * 6 + kt) * 32 + l]);
    }

    {
        float sl = 0.f, ql = 0.f, sh = 0.f, qh = 0.f;
#pragma unroll
        for (int nt = 0; nt < 8; ++nt) {
            sl += a2[nt][0] + a2[nt][1];
            ql += a2[nt][0] * a2[nt][0] + a2[nt][1] * a2[nt][1];
            sh += a2[nt][2] + a2[nt][3];
            qh += a2[nt][2] * a2[nt][2] + a2[nt][3] * a2[nt][3];
        }
#pragma unroll
        for (int o = 1; o <= 2; o <<= 1) {
            sl += __shfl_xor_sync(0xffffffffu, sl, o);
            ql += __shfl_xor_sync(0xffffffffu, ql, o);
            sh += __shfl_xor_sync(0xffffffffu, sh, o);
            qh += __shfl_xor_sync(0xffffffffu, qh, o);
        }
        float ml = sl * 0.015625f, vl = ql * 0.015625f - ml * ml;
        float mh = sh * 0.015625f, vh = qh * 0.015625f - mh * mh;
        float il = rsqrtf(vl + 1e-12f), ih = rsqrtf(vh + 1e-12f);
#pragma unroll
        for (int nt = 0; nt < 8; ++nt) {
            int c0 = nt * 8 + 2 * q4;
            float g0 = sP[256 + c0], g1v = sP[256 + c0 + 1];
            float e0 = sP[320 + c0], e1v = sP[320 + c0 + 1];
            float zl0 = fmaxf((a2[nt][0] - ml) * il * g0  + e0,  0.f);
            float zl1 = fmaxf((a2[nt][1] - ml) * il * g1v + e1v, 0.f);
            float zh0 = fmaxf((a2[nt][2] - mh) * ih * g0  + e0,  0.f);
            float zh1 = fmaxf((a2[nt][3] - mh) * ih * g1v + e1v, 0.f);
            *(unsigned*)(sX + ar * XP + c0)       = h2u(zl0, zl1);
            *(unsigned*)(sX + (ar + 8) * XP + c0) = h2u(zh0, zh1);
        }
    }
    __syncthreads();

#pragma unroll
    for (int q = 0; q < 4; ++q) {
        int idx = tid + q * 256;
        int f = idx & 511, tj = idx >> 9;
        int l2 = f & 31, kt = (f >> 5) & 3, mtg = f >> 7;
        int sA = mtg * 16 + (l2 >> 2);
        int c0 = kt * 16 + 2 * (l2 & 3);
        const __half* bsx = sX + (tj * 64) * XP;
        uint4 v;
        v.x = *(const unsigned*)(bsx + sA * XP + c0);
        v.y = *(const unsigned*)(bsx + (sA + 8) * XP + c0);
        v.z = *(const unsigned*)(bsx + sA * XP + c0 + 8);
        v.w = *(const unsigned*)(bsx + (sA + 8) * XP + c0 + 8);
        int t = tpair * 2 + tj;
        *(uint4*)(g_x2h + ((size_t)t * 64 + chunk) * 4096 + (size_t)f * 8) = v;
    }
}

// =====================================================================
// Kernel 2: bidirectional LSTM + fused attention. 32 seqs/CTA,
// grid (128, 2) = 256 CTAs, 256 threads -> 2 CTAs/SM co-residency.
// =====================================================================
__global__ void __launch_bounds__(256, 2) lstm_kernel(
    const float* __restrict__ Wf, const float* __restrict__ bfv,
    const float* __restrict__ Wb, const float* __restrict__ bbv,
    const float* __restrict__ wx, const float* __restrict__ bxv,
    const float* __restrict__ wp, const float* __restrict__ bp,
    const float* __restrict__ gp, const float* __restrict__ bep,
    const float* __restrict__ W3, const float* __restrict__ b3,
    float* __restrict__ out)
{
    extern __shared__ char smc[];
    uint2*  wF  = (uint2*)smc;                      // 8192 uint2 (64 KB)
    __half* xb  = (__half*)(smc + 65536);           // 2 x 2048 halves (8 KB)
    __half* hT  = (__half*)(smc + 65536 + 8192);    // 2 x 2048 halves (8 KB)
    float*  red = (float*)(smc + 65536 + 16384);    // 2 x 512 (4 KB)
    float*  sXS = (float*)(smc + 65536 + 20480);    // 32 x 65
    float*  sPS = sXS + 32 * 65;                    // 32 x 65

    const int dir = blockIdx.y;
    const int chk = blockIdx.x;                     // 0..127 (32-seq chunks)
    const float* W    = dir ? Wb  : Wf;
    const float* bias = dir ? bbv : bfv;
    const int tid = threadIdx.x;
    const int l = tid & 31, w = tid >> 5;           // 8 warps; wu = w
    const int wu = w;
    const size_t xbase = ((size_t)(chk >> 1)) * 4096 + (size_t)(chk & 1) * 2048;

    // ---- W -> fp16 B-frags [wu8][g4][kt8][lane32], gate-unit permuted ----
#pragma unroll
    for (int q = 0; q < 32; ++q) {
        int s = tid + q * 256;
        int l2 = s & 31, kt = (s >> 5) & 7, g = (s >> 8) & 3, ww = s >> 10;
        int k0 = kt * 16 + 2 * (l2 & 3);
        int n  = g * 64 + 8 * ww + (l2 >> 2);
        uint2 b;
        b.x = h2u(W[k0 * 256 + n],       W[(k0 + 1) * 256 + n]);
        b.y = h2u(W[(k0 + 8) * 256 + n], W[(k0 + 9) * 256 + n]);
        wF[s] = b;
    }
    // ---- init: x(t0) -> xb[0]; zero hT[0] ----
    {
        int t0 = dir ? 63 : 0;
        const uint4* src = (const uint4*)(g_x2h + (size_t)t0 * 64 * 4096 + xbase);
        ((uint4*)xb)[tid] = src[tid];
        ((uint4*)hT)[tid] = make_uint4(0, 0, 0, 0);
    }
    __syncthreads();   // wF visible for register hoist

    // hoist x-part B frags (kt 0..3) into registers
    uint2 bxr[4][4];
#pragma unroll
    for (int kt = 0; kt < 4; ++kt)
#pragma unroll
        for (int g = 0; g < 4; ++g)
            bxr[kt][g] = wF[((wu * 4 + g) * 8 + kt) * 32 + l];

    const int q4 = l & 3, rlq = l >> 2;
    const int u0 = 8 * wu + 2 * q4;
    float bia[4][2];
#pragma unroll
    for (int g = 0; g < 4; ++g) {
        bia[g][0] = bias[g * 64 + u0];
        bia[g][1] = bias[g * 64 + u0 + 1];
    }
    const float wxu0 = wx[u0], wxu1 = wx[u0 + 1];
    const float wpu0 = wp[u0], wpu1 = wp[u0 + 1];
    const float bxs = bxv[0], bps = bp[0];

    float cst[2][4];
#pragma unroll
    for (int mt = 0; mt < 2; ++mt)
#pragma unroll
        for (int s = 0; s < 4; ++s) cst[mt][s] = 0.f;

    const int kth = wu >> 1;
    const int hsl = (wu & 1) * 4;

    for (int st = 0; st < 64; ++st) {
        const int p = st & 1;
        __syncthreads();   // single barrier per step

        // drain xs/ps of previous step into smem
        if (st > 0 && tid < 64) {
            int which = tid >> 5, seq = tid & 31;
            const float* rb = red + ((st - 1) & 1) * 512 + which * 256 + seq;
            float v = rb[0] + rb[32] + rb[64] + rb[96]
                    + rb[128] + rb[160] + rb[192] + rb[224];
            int tprev = dir ? (64 - st) : (st - 1);
            if (which) sPS[seq * 65 + tprev] = v + bps;
            else       sXS[seq * 65 + tprev] = v + bxs;
        }

        // prefetch x(t+1)
        uint4 xpf;
        if (st < 63) {
            int t2 = dir ? (62 - st) : (st + 1);
            xpf = ((const uint4*)(g_x2h + (size_t)t2 * 64 * 4096 + xbase))[tid];
        }

        const __half* xbp = xb + p * 2048;
        const __half* hFp = hT + p * 2048;

        float acc[2][4][4];
#pragma unroll
        for (int mt = 0; mt < 2; ++mt)
#pragma unroll
            for (int g = 0; g < 4; ++g) {
                acc[mt][g][0] = bia[g][0]; acc[mt][g][1] = bia[g][1];
                acc[mt][g][2] = bia[g][0]; acc[mt][g][3] = bia[g][1];
            }

        // x-part: kt 0..3, B in regs
#pragma unroll
        for (int kt = 0; kt < 4; ++kt) {
#pragma unroll
            for (int mt = 0; mt < 2; ++mt) {
                uint4 a = *(const uint4*)(xbp + (((mt * 4 + kt) * 32 + l) << 3));
#pragma unroll
                for (int g = 0; g < 4; ++g)
                    mma_f16(acc[mt][g], a, bxr[kt][g]);
            }
        }
        // h-part: kt 0..3 of hT (wF kts 4..7)
#pragma unroll
        for (int kt = 0; kt < 4; ++kt) {
#pragma unroll
            for (int mt = 0; mt < 2; ++mt) {
                uint4 a = *(const uint4*)(hFp + (((mt * 4 + kt) * 32 + l) << 3));
#pragma unroll
                for (int g = 0; g < 4; ++g)
                    mma_f16(acc[mt][g], a, wF[((wu * 4 + g) * 8 + 4 + kt) * 32 + l]);
            }
        }

        // ---- epilogue ----
        float hreg[2][4];
        float px[2][2], pq[2][2];
#pragma unroll
        for (int mt = 0; mt < 2; ++mt) {
#pragma unroll
            for (int s = 0; s < 4; ++s) {
                float iv = acc[mt][0][s], jv = acc[mt][1][s];
                float fv = acc[mt][2][s], ov = acc[mt][3][s];
                float cn = cst[mt][s] * sigt(fv + 1.f) + sigt(iv) * tanha(jv);
                cst[mt][s] = cn;
                hreg[mt][s] = tanha(cn) * sigt(ov);
            }
            px[mt][0] = hreg[mt][0] * wxu0 + hreg[mt][1] * wxu1;
            px[mt][1] = hreg[mt][2] * wxu0 + hreg[mt][3] * wxu1;
            pq[mt][0] = hreg[mt][0] * wpu0 + hreg[mt][1] * wpu1;
            pq[mt][1] = hreg[mt][2] * wpu0 + hreg[mt][3] * wpu1;
        }
#pragma unroll
        for (int o = 1; o <= 2; o <<= 1) {
#pragma unroll
            for (int mt = 0; mt < 2; ++mt) {
                px[mt][0] += __shfl_xor_sync(0xffffffffu, px[mt][0], o);
                px[mt][1] += __shfl_xor_sync(0xffffffffu, px[mt][1], o);
                pq[mt][0] += __shfl_xor_sync(0xffffffffu, pq[mt][0], o);
                pq[mt][1] += __shfl_xor_sync(0xffffffffu, pq[mt][1], o);
            }
        }
        if ((l & 3) == 0) {
            float* rp = red + p * 512;
#pragma unroll
            for (int mt = 0; mt < 2; ++mt) {
                int seqlo = mt * 16 + (l >> 2);
                rp[wu * 32 + seqlo]           = px[mt][0];
                rp[wu * 32 + seqlo + 8]       = px[mt][1];
                rp[256 + wu * 32 + seqlo]     = pq[mt][0];
                rp[256 + wu * 32 + seqlo + 8] = pq[mt][1];
            }
        }
        // new h (fp16) -> hT[p^1] in fragment order
        {
            __half* hDst = hT + (p ^ 1) * 2048;
#pragma unroll
            for (int mt = 0; mt < 2; ++mt) {
                uint2 hv;
                hv.x = h2u(hreg[mt][0], hreg[mt][1]);
                hv.y = h2u(hreg[mt][2], hreg[mt][3]);
                *(uint2*)(hDst + (((mt * 4 + kth) * 32 + l) << 3) + hsl) = hv;
            }
        }
        if (st < 63) {
            ((uint4*)(xb + (p ^ 1) * 2048))[tid] = xpf;
        }
    }

    // ---- final drain + attn params (reuse wF region) ----
    __syncthreads();
    if (tid < 64) {
        int which = tid >> 5, seq = tid & 31;
        const float* rb = red + 512 + which * 256 + seq;   // st=63 parity 1
        float v = rb[0] + rb[32] + rb[64] + rb[96]
                + rb[128] + rb[160] + rb[192] + rb[224];
        int tlast = dir ? 0 : 63;
        if (which) sPS[seq * 65 + tlast] = v + bps;
        else       sXS[seq * 65 + tlast] = v + bxs;
    }
    float* sW3a = (float*)smc;
    float* sprm = sW3a + 4096;
    for (int i = tid; i < 1024; i += 256) ((float4*)sW3a)[i] = ((const float4*)W3)[i];
    if (tid < 64) {
        sprm[tid]       = b3[tid];
        sprm[64 + tid]  = gp[tid];
        sprm[128 + tid] = bep[tid];
    }
    __syncthreads();

    // ---- fused attention: 8 warps x 4 seqs = 32 ----
#pragma unroll
    for (int si = 0; si < 4; ++si) {
        int seq = w * 4 + si;
        float v0 = sPS[seq * 65 + l], v1 = sPS[seq * 65 + 32 + l];
        float s = v0 + v1, q = v0 * v0 + v1 * v1;
#pragma unroll
        for (int o = 16; o; o >>= 1) {
            s += __shfl_xor_sync(0xffffffffu, s, o);
            q += __shfl_xor_sync(0xffffffffu, q, o);
        }
        float m = s * 0.015625f;
        float var = q * 0.015625f - m * m;
        float rs = rsqrtf(var + 1e-12f);
        float p0 = fmaxf((v0 - m) * rs * sprm[64 + l] + sprm[128 + l], 0.f);
        float p1 = fmaxf((v1 - m) * rs * sprm[96 + l] + sprm[160 + l], 0.f);

        float l0 = sprm[l], l1 = sprm[32 + l];
#pragma unroll 8
        for (int tt = 0; tt < 32; ++tt) {
            float pv = __shfl_sync(0xffffffffu, p0, tt);
            l0 += pv * sW3a[tt * 64 + l];
            l1 += pv * sW3a[tt * 64 + 32 + l];
        }
#pragma unroll 8
        for (int tt = 0; tt < 32; ++tt) {
            float pv = __shfl_sync(0xffffffffu, p1, tt);
            l0 += pv * sW3a[(32 + tt) * 64 + l];
            l1 += pv * sW3a[(32 + tt) * 64 + 32 + l];
        }

        float mx = fmaxf(l0, l1);
#pragma unroll
        for (int o = 16; o; o >>= 1) mx = fmaxf(mx, __shfl_xor_sync(0xffffffffu, mx, o));
        float e0 = __expf(l0 - mx), e1 = __expf(l1 - mx);
        float se = e0 + e1;
        float rsum = e0 * sXS[seq * 65 + l] + e1 * sXS[seq * 65 + 32 + l];
#pragma unroll
        for (int o = 16; o; o >>= 1) {
            se   += __shfl_xor_sync(0xffffffffu, se, o);
            rsum += __shfl_xor_sync(0xffffffffu, rsum, o);
        }
        if (l == 0) out[(size_t)dir * Bn + chk * 32 + seq] = rsum / se;
    }
}

// =====================================================================
extern "C" void kernel_launch(void* const* d_in, const int* in_sizes, int n_in,
                              void* d_out, int out_size)
{
    const float* obs = (const float*)d_in[0];
    const float* act = (const float*)d_in[1];
    const float* W1  = (const float*)d_in[2];
    const float* b1  = (const float*)d_in[3];
    const float* g1  = (const float*)d_in[4];
    const float* be1 = (const float*)d_in[5];
    const float* W2  = (const float*)d_in[6];
    const float* b2  = (const float*)d_in[7];
    const float* g2  = (const float*)d_in[8];
    const float* be2 = (const float*)d_in[9];
    const float* Wf  = (const float*)d_in[10];
    const float* bf  = (const float*)d_in[11];
    const float* Wb  = (const float*)d_in[12];
    const float* bb  = (const float*)d_in[13];
    const float* wx  = (const float*)d_in[14];
    const float* bxv = (const float*)d_in[15];
    const float* wp  = (const float*)d_in[16];
    const float* bp  = (const float*)d_in[17];
    const float* gp  = (const float*)d_in[18];
    const float* bep = (const float*)d_in[19];
    const float* W3  = (const float*)d_in[20];
    const float* b3  = (const float*)d_in[21];
    float* out = (float*)d_out;

    const int trunk_smem = 28672 + 128 * XP * 2 + 128 * AP * 2 + 384 * 4;    // 91648 B
    const int lstm_smem  = 65536 + 8192 + 8192 + 4096 + 2 * 32 * 65 * 4;     // 102656 B
    cudaFuncSetAttribute(trunk_kernel, cudaFuncAttributeMaxDynamicSharedMemorySize, trunk_smem);
    cudaFuncSetAttribute(lstm_kernel,  cudaFuncAttributeMaxDynamicSharedMemorySize, lstm_smem);

    trunk_kernel<<<2048, 256, trunk_smem>>>(obs, act, W1, b1, g1, be1, W2, b2, g2, be2);

    dim3 lg(128, 2);
    lstm_kernel<<<lg, 256, lstm_smem>>>(Wf, bf, Wb, bb, wx, bxv, wp, bp,
                                        gp, bep, W3, b3, out);
}